// round 1
// baseline (speedup 1.0000x reference)
#include <cuda_runtime.h>
#include <math.h>

// ---------------- problem constants ----------------
#define BB 4
#define SS 4096
#define EE 512
#define HH 8
#define LL 4
#define AA 3
#define WIN 64
#define CC 64           // S / WIN clusters
#define DD 64           // E / H
#define MM (BB*SS)      // 16384 rows
#define FF (4*EE)       // 2048 ffn dim
#define NVOC 17

// ---------------- scratch (device globals; no allocation allowed) ----------------
__device__ float g_x[MM*EE];
__device__ float g_h[MM*EE];
__device__ float g_q[MM*EE];
__device__ float g_k[MM*EE];
__device__ float g_v[MM*EE];
__device__ float g_t[MM*FF];
__device__ float g_dists[BB*HH*CC*SS];
__device__ float g_qinv[BB*HH*SS];
__device__ int   g_idx[BB*HH*CC*WIN];
__device__ float g_attout[MM*EE];
__device__ float g_cnt[MM*HH];

// ---------------- embedding + shift-right ----------------
__global__ void embed_kernel(const int* __restrict__ value, const int* __restrict__ depth,
                             const int* __restrict__ pos, const float* __restrict__ sos,
                             const float* __restrict__ tok, const float* __restrict__ dep,
                             const float* __restrict__ pemb, float* __restrict__ x) {
    int row = blockIdx.x;              // b*S + t
    int t = row & (SS - 1);
    if (t == 0) {
        for (int e = threadIdx.x; e < EE; e += blockDim.x) x[(size_t)row*EE + e] = sos[e];
        return;
    }
    int pr = row - 1;                  // same b since t>0
    int v  = value[pr], dp = depth[pr];
    int p0 = pos[pr*AA+0], p1 = pos[pr*AA+1], p2 = pos[pr*AA+2];
    for (int e = threadIdx.x; e < EE; e += blockDim.x) {
        float s = tok[v*EE+e] + dep[dp*EE+e]
                + pemb[(0*65 + p0)*EE + e]
                + pemb[(1*65 + p1)*EE + e]
                + pemb[(2*65 + p2)*EE + e];
        x[(size_t)row*EE + e] = s;
    }
}

// ---------------- layernorm (one block of 256 per row, E=512) ----------------
__global__ void ln_kernel(const float* __restrict__ x, const float* __restrict__ sc,
                          const float* __restrict__ bi, float* __restrict__ out) {
    int row = blockIdx.x;
    int tid = threadIdx.x;
    const float* xr = x + (size_t)row*EE;
    float v0 = xr[tid], v1 = xr[tid + 256];
    __shared__ float rs[256], rq[256];
    rs[tid] = v0 + v1;
    rq[tid] = v0*v0 + v1*v1;
    __syncthreads();
    for (int off = 128; off > 0; off >>= 1) {
        if (tid < off) { rs[tid] += rs[tid+off]; rq[tid] += rq[tid+off]; }
        __syncthreads();
    }
    __shared__ float s_m, s_r;
    if (tid == 0) {
        float m = rs[0] * (1.0f/EE);
        float var = rq[0] * (1.0f/EE) - m*m;
        s_m = m; s_r = rsqrtf(var + 1e-5f);
    }
    __syncthreads();
    float m = s_m, r = s_r;
    float* orow = out + (size_t)row*EE;
    orow[tid]       = (v0 - m)*r*sc[tid]       + bi[tid];
    orow[tid + 256] = (v1 - m)*r*sc[tid + 256] + bi[tid + 256];
}

// ---------------- gelu (tanh approximation, matches jax default) ----------------
__device__ __forceinline__ float gelu_f(float x) {
    float x3 = x*x*x;
    return 0.5f*x*(1.0f + tanhf(0.7978845608028654f*(x + 0.044715f*x3)));
}

// ---------------- tiled SGEMM: C[M,N] = A[M,K] @ B[K,N] (+bias)(+gelu)(+accum) ----------------
// BM=BN=128, BK=8, 256 threads, 8x8 per thread. M,N multiples of 128; K multiple of 8.
template<int ACT, bool ACCUM, bool HASB>
__global__ void __launch_bounds__(256) sgemm_kernel(const float* __restrict__ A,
                                                    const float* __restrict__ Bm,
                                                    const float* __restrict__ bias,
                                                    float* __restrict__ C,
                                                    int M, int N, int K) {
    __shared__ float As[8][128];
    __shared__ float Bs[8][128];
    int tid = threadIdx.x;
    int bm = blockIdx.y * 128, bn = blockIdx.x * 128;
    int ty = tid >> 4, tx = tid & 15;
    float acc[8][8];
#pragma unroll
    for (int i = 0; i < 8; i++)
#pragma unroll
        for (int j = 0; j < 8; j++) acc[i][j] = 0.0f;

    int arow = tid >> 1, acol = (tid & 1) * 4;
    int brow = tid >> 5, bcol = (tid & 31) * 4;
    const float* Aptr = A + (size_t)(bm + arow)*K + acol;
    const float* Bptr = Bm + (size_t)brow*N + bn + bcol;

    for (int k0 = 0; k0 < K; k0 += 8) {
        float4 av = *(const float4*)Aptr; Aptr += 8;
        float4 bv = *(const float4*)Bptr; Bptr += (size_t)8*N;
        As[acol+0][arow] = av.x; As[acol+1][arow] = av.y;
        As[acol+2][arow] = av.z; As[acol+3][arow] = av.w;
        *(float4*)&Bs[brow][bcol] = bv;
        __syncthreads();
#pragma unroll
        for (int kc = 0; kc < 8; kc++) {
            float a[8], b[8];
            *(float4*)(a)   = *(float4*)&As[kc][ty*8];
            *(float4*)(a+4) = *(float4*)&As[kc][ty*8+4];
            *(float4*)(b)   = *(float4*)&Bs[kc][tx*8];
            *(float4*)(b+4) = *(float4*)&Bs[kc][tx*8+4];
#pragma unroll
            for (int i = 0; i < 8; i++)
#pragma unroll
                for (int j = 0; j < 8; j++) acc[i][j] += a[i]*b[j];
        }
        __syncthreads();
    }
#pragma unroll
    for (int i = 0; i < 8; i++) {
        int r = bm + ty*8 + i;
#pragma unroll
        for (int j = 0; j < 8; j++) {
            int c = bn + tx*8 + j;
            float vv = acc[i][j];
            if (HASB) vv += bias[c];
            if (ACT == 1) vv = gelu_f(vv);
            size_t o = (size_t)r*N + c;
            if (ACCUM) C[o] += vv; else C[o] = vv;
        }
    }
}

// ---------------- per-(b,h,n) inverse q norm ----------------
__global__ void qinv_kernel(const float* __restrict__ q, float* __restrict__ qinv) {
    int gw = (blockIdx.x*blockDim.x + threadIdx.x) >> 5;
    int lane = threadIdx.x & 31;
    if (gw >= MM*HH) return;
    int h = gw % HH;
    int row = gw / HH;                 // b*S + n
    const float* qp = q + (size_t)row*EE + h*DD;
    float v0 = qp[lane], v1 = qp[lane + 32];
    float ss = v0*v0 + v1*v1;
#pragma unroll
    for (int o = 16; o; o >>= 1) ss += __shfl_xor_sync(0xffffffffu, ss, o);
    if (lane == 0) {
        int b = row / SS, n = row % SS;
        qinv[((size_t)b*HH + h)*SS + n] = 1.0f/(sqrtf(ss) + 1e-8f);
    }
}

// ---------------- cluster distances: dists[b,h,c,n] = qn . mn ----------------
__global__ void dist_kernel(const float* __restrict__ q, const float* __restrict__ qinv,
                            const float* __restrict__ means_l, float* __restrict__ dists) {
    int blk = blockIdx.x;              // (b*H + h)*C + c
    int c = blk % CC; int bh = blk / CC; int h = bh % HH; int b = bh / HH;
    __shared__ float mm[64];
    __shared__ float red[256];
    int tid = threadIdx.x;
    float msq = 0.0f;
    if (tid < 64) { float mv = means_l[(h*CC + c)*DD + tid]; mm[tid] = mv; msq = mv*mv; }
    red[tid] = msq;
    __syncthreads();
    for (int off = 128; off > 0; off >>= 1) {
        if (tid < off) red[tid] += red[tid+off];
        __syncthreads();
    }
    float minv = 1.0f/(sqrtf(red[0]) + 1e-8f);
    float* drow = dists + (size_t)blk*SS;
    const float* qbase = q + (size_t)b*SS*EE + h*DD;
    const float* qi = qinv + (size_t)bh*SS;
    for (int n = tid; n < SS; n += 256) {
        const float4* qp = (const float4*)(qbase + (size_t)n*EE);
        float dot = 0.0f;
#pragma unroll
        for (int k4 = 0; k4 < 16; k4++) {
            float4 vv = qp[k4];
            dot += vv.x*mm[k4*4] + vv.y*mm[k4*4+1] + vv.z*mm[k4*4+2] + vv.w*mm[k4*4+3];
        }
        drow[n] = dot * minv * qi[n];
    }
}

// ---------------- exact top-64 of 4096 (tie-break: smallest index, matches jax) ----------------
__global__ void topk_kernel(const float* __restrict__ dists, int* __restrict__ idxout) {
    int blk = blockIdx.x;
    __shared__ float vals[SS];
    __shared__ float rv[256];
    __shared__ int   ri[256];
    int tid = threadIdx.x;
    const float* drow = dists + (size_t)blk*SS;
    for (int n = tid; n < SS; n += 256) vals[n] = drow[n];
    __syncthreads();
    int* orow = idxout + blk*WIN;
    for (int it = 0; it < WIN; it++) {
        float bv = -INFINITY; int bi = -1;
        for (int n = tid; n < SS; n += 256) {
            float v = vals[n];
            if (v > bv || (v == bv && n < bi)) { bv = v; bi = n; }
        }
        rv[tid] = bv; ri[tid] = bi;
        __syncthreads();
        for (int off = 128; off > 0; off >>= 1) {
            if (tid < off) {
                float ov = rv[tid+off]; int oi = ri[tid+off];
                if (ov > rv[tid] || (ov == rv[tid] && oi != -1 && (ri[tid] == -1 || oi < ri[tid]))) {
                    rv[tid] = ov; ri[tid] = oi;
                }
            }
            __syncthreads();
        }
        if (tid == 0) { orow[it] = ri[0]; vals[ri[0]] = -INFINITY; }
        __syncthreads();
    }
}

// ---------------- bucket attention: gather, scores, mask, softmax, AV, scatter-add ----------------
// dynamic smem: qb/kb/vb/sc each 64*65 floats (padded rows for conflict-free LDS)
__global__ void bucket_attn_kernel(const float* __restrict__ q, const float* __restrict__ k,
                                   const float* __restrict__ v, const int* __restrict__ value,
                                   const int* __restrict__ idxin, float* __restrict__ attout,
                                   float* __restrict__ cnt) {
    extern __shared__ float sm[];
    float* qb = sm;
    float* kb = qb + 64*65;
    float* vb = kb + 64*65;
    float* sc = vb + 64*65;
    __shared__ int idxs[64];
    __shared__ int kms[64];
    int blk = blockIdx.x;              // (b*H + h)*C + c
    int bh = blk / CC; int h = bh % HH; int b = bh / HH;
    int tid = threadIdx.x;
    if (tid < 64) {
        int t = idxin[blk*WIN + tid];
        idxs[tid] = t;
        kms[tid] = (value[b*SS + t] != 0);
    }
    __syncthreads();
    // gather q/k/v rows for the bucket
    for (int i = tid; i < 64*64; i += 256) {
        int w = i >> 6, d = i & 63;
        size_t base = ((size_t)(b*SS + idxs[w]))*EE + h*DD + d;
        qb[w*65 + d] = q[base];
        kb[w*65 + d] = k[base];
        vb[w*65 + d] = v[base];
    }
    __syncthreads();
    // scores with value-based causal mask + key mask
    float sres[16];
#pragma unroll
    for (int j = 0; j < 16; j++) {
        int i = tid + j*256; int w = i >> 6, xx = i & 63;
        float dot = 0.0f;
#pragma unroll
        for (int kk = 0; kk < 64; kk++) dot += qb[w*65+kk]*kb[xx*65+kk];
        bool allowed = (idxs[w] >= idxs[xx]) && kms[xx];
        sres[j] = allowed ? dot*0.125f : -1e9f;
    }
#pragma unroll
    for (int j = 0; j < 16; j++) {
        int i = tid + j*256;
        sc[(i >> 6)*65 + (i & 63)] = sres[j];
    }
    __syncthreads();
    // softmax per row (threads 0..63)
    if (tid < 64) {
        float mx = -INFINITY;
        for (int xx = 0; xx < 64; xx++) mx = fmaxf(mx, sc[tid*65+xx]);
        float sum = 0.0f;
        for (int xx = 0; xx < 64; xx++) { float e = expf(sc[tid*65+xx]-mx); sc[tid*65+xx] = e; sum += e; }
        float inv = 1.0f/sum;
        for (int xx = 0; xx < 64; xx++) sc[tid*65+xx] *= inv;
    }
    __syncthreads();
    // O = attn @ V, scatter-add to (b, tok, h, d)
#pragma unroll
    for (int j = 0; j < 16; j++) {
        int i = tid + j*256; int w = i >> 6, d = i & 63;
        float o = 0.0f;
#pragma unroll
        for (int xx = 0; xx < 64; xx++) o += sc[w*65+xx]*vb[xx*65+d];
        atomicAdd(&attout[((size_t)(b*SS + idxs[w]))*EE + h*DD + d], o);
    }
    if (tid < 64) atomicAdd(&cnt[(size_t)(b*SS + idxs[tid])*HH + h], 1.0f);
}

// ---------------- scatter-mean normalization ----------------
__global__ void norm_attout_kernel(float* __restrict__ attout, const float* __restrict__ cnt) {
    int i = blockIdx.x*256 + threadIdx.x;   // over MM*EE
    int row = i >> 9;
    int h = (i & 511) >> 6;
    float c = cnt[(size_t)row*HH + h];
    attout[i] = attout[i] / fmaxf(c, 1.0f);
}

// ---------------- head: logits = x @ head_w.T  (N=17), warp per row ----------------
__global__ void head_kernel(const float* __restrict__ x, const float* __restrict__ hw,
                            float* __restrict__ out) {
    int gw = (blockIdx.x*256 + threadIdx.x) >> 5;
    int lane = threadIdx.x & 31;
    if (gw >= MM) return;
    const float* xp = x + (size_t)gw*EE;
    float xr[16];
#pragma unroll
    for (int i = 0; i < 16; i++) xr[i] = xp[lane + i*32];
    for (int o = 0; o < NVOC; o++) {
        const float* w = hw + o*EE;
        float s = 0.0f;
#pragma unroll
        for (int i = 0; i < 16; i++) s += xr[i]*w[lane + i*32];
#pragma unroll
        for (int off = 16; off; off >>= 1) s += __shfl_xor_sync(0xffffffffu, s, off);
        if (lane == 0) out[(size_t)gw*NVOC + o] = s;
    }
}

// ---------------- host orchestration ----------------
extern "C" void kernel_launch(void* const* d_in, const int* in_sizes, int n_in,
                              void* d_out, int out_size) {
    const int*   value     = (const int*)d_in[0];
    const int*   depth     = (const int*)d_in[1];
    const int*   pos       = (const int*)d_in[2];
    const float* sos       = (const float*)d_in[3];
    const float* tok_emb   = (const float*)d_in[4];
    const float* depth_emb = (const float*)d_in[5];
    const float* pos_emb   = (const float*)d_in[6];
    const float* ln1_s     = (const float*)d_in[7];
    const float* ln1_b     = (const float*)d_in[8];
    const float* Wq        = (const float*)d_in[9];
    const float* Wk        = (const float*)d_in[10];
    const float* Wv        = (const float*)d_in[11];
    const float* Wo        = (const float*)d_in[12];
    const float* means     = (const float*)d_in[13];
    const float* ln2_s     = (const float*)d_in[14];
    const float* ln2_b     = (const float*)d_in[15];
    const float* W1        = (const float*)d_in[16];
    const float* b1        = (const float*)d_in[17];
    const float* W2        = (const float*)d_in[18];
    const float* b2        = (const float*)d_in[19];
    const float* head_w    = (const float*)d_in[20];
    float* out = (float*)d_out;

    float *x, *h, *q, *k, *v, *t, *dists, *qinv, *attout, *cnt;
    int* idxb;
    cudaGetSymbolAddress((void**)&x, g_x);
    cudaGetSymbolAddress((void**)&h, g_h);
    cudaGetSymbolAddress((void**)&q, g_q);
    cudaGetSymbolAddress((void**)&k, g_k);
    cudaGetSymbolAddress((void**)&v, g_v);
    cudaGetSymbolAddress((void**)&t, g_t);
    cudaGetSymbolAddress((void**)&dists, g_dists);
    cudaGetSymbolAddress((void**)&qinv, g_qinv);
    cudaGetSymbolAddress((void**)&idxb, g_idx);
    cudaGetSymbolAddress((void**)&attout, g_attout);
    cudaGetSymbolAddress((void**)&cnt, g_cnt);

    const int ATTN_SMEM = 4 * 64 * 65 * (int)sizeof(float);   // ~66.5 KB
    cudaFuncSetAttribute(bucket_attn_kernel, cudaFuncAttributeMaxDynamicSharedMemorySize, ATTN_SMEM);

    embed_kernel<<<MM, 128>>>(value, depth, pos, sos, tok_emb, depth_emb, pos_emb, x);

    dim3 gE(EE/128, MM/128);     // 4 x 128
    dim3 gF(FF/128, MM/128);     // 16 x 128

    for (int l = 0; l < LL; l++) {
        const float* wq = Wq + (size_t)l*EE*EE;
        const float* wk = Wk + (size_t)l*EE*EE;
        const float* wv = Wv + (size_t)l*EE*EE;
        const float* wo = Wo + (size_t)l*EE*EE;
        const float* w1 = W1 + (size_t)l*EE*FF;
        const float* w2 = W2 + (size_t)l*FF*EE;
        const float* ml = means + (size_t)l*HH*CC*DD;

        ln_kernel<<<MM, 256>>>(x, ln1_s + l*EE, ln1_b + l*EE, h);
        sgemm_kernel<0,false,false><<<gE, 256>>>(h, wq, nullptr, q, MM, EE, EE);
        sgemm_kernel<0,false,false><<<gE, 256>>>(h, wk, nullptr, k, MM, EE, EE);
        sgemm_kernel<0,false,false><<<gE, 256>>>(h, wv, nullptr, v, MM, EE, EE);

        qinv_kernel<<<(MM*HH*32)/256, 256>>>(q, qinv);
        dist_kernel<<<BB*HH*CC, 256>>>(q, qinv, ml, dists);
        topk_kernel<<<BB*HH*CC, 256>>>(dists, idxb);

        cudaMemsetAsync(attout, 0, (size_t)MM*EE*sizeof(float));
        cudaMemsetAsync(cnt, 0, (size_t)MM*HH*sizeof(float));
        bucket_attn_kernel<<<BB*HH*CC, 256, ATTN_SMEM>>>(q, k, v, value, idxb, attout, cnt);
        norm_attout_kernel<<<(MM*EE)/256, 256>>>(attout, cnt);

        sgemm_kernel<0,true,false><<<gE, 256>>>(attout, wo, nullptr, x, MM, EE, EE);   // x += attn @ Wo

        ln_kernel<<<MM, 256>>>(x, ln2_s + l*EE, ln2_b + l*EE, h);
        sgemm_kernel<1,false,true><<<gF, 256>>>(h, w1, b1 + l*FF, t, MM, FF, EE);      // gelu(h@W1+b1)
        sgemm_kernel<0,true,true><<<gE, 256>>>(t, w2, b2 + l*EE, x, MM, EE, FF);       // x += t@W2+b2
    }

    head_kernel<<<MM/8, 256>>>(x, head_w, out);
}

// round 3
// speedup vs baseline: 1.6587x; 1.6587x over previous
#include <cuda_runtime.h>
#include <cuda_bf16.h>
#include <math.h>
#include <stdint.h>

// ---------------- problem constants ----------------
#define BB 4
#define SS 4096
#define EE 512
#define HH 8
#define LL 4
#define AA 3
#define WIN 64
#define CC 64           // S / WIN clusters
#define DD 64           // E / H
#define MM (BB*SS)      // 16384 rows
#define FF (4*EE)       // 2048 ffn dim
#define NVOC 17

// ---------------- scratch (device globals; no allocation allowed) ----------------
__device__ float g_x[MM*EE];
__device__ float g_h[MM*EE];
__device__ float g_q[MM*EE];
__device__ float g_k[MM*EE];
__device__ float g_v[MM*EE];
__device__ float g_t[MM*FF];
__device__ float g_dists[BB*HH*CC*SS];
__device__ float g_qinv[BB*HH*SS];
__device__ int   g_idx[BB*HH*CC*WIN];
__device__ float g_attout[MM*EE];
__device__ float g_cnt[MM*HH];

// ---------------- embedding + shift-right ----------------
__global__ void embed_kernel(const int* __restrict__ value, const int* __restrict__ depth,
                             const int* __restrict__ pos, const float* __restrict__ sos,
                             const float* __restrict__ tok, const float* __restrict__ dep,
                             const float* __restrict__ pemb, float* __restrict__ x) {
    int row = blockIdx.x;              // b*S + t
    int t = row & (SS - 1);
    if (t == 0) {
        for (int e = threadIdx.x; e < EE; e += blockDim.x) x[(size_t)row*EE + e] = sos[e];
        return;
    }
    int pr = row - 1;                  // same b since t>0
    int v  = value[pr], dp = depth[pr];
    int p0 = pos[pr*AA+0], p1 = pos[pr*AA+1], p2 = pos[pr*AA+2];
    for (int e = threadIdx.x; e < EE; e += blockDim.x) {
        float s = tok[v*EE+e] + dep[dp*EE+e]
                + pemb[(0*65 + p0)*EE + e]
                + pemb[(1*65 + p1)*EE + e]
                + pemb[(2*65 + p2)*EE + e];
        x[(size_t)row*EE + e] = s;
    }
}

// ---------------- layernorm (one block of 256 per row, E=512) ----------------
__global__ void ln_kernel(const float* __restrict__ x, const float* __restrict__ sc,
                          const float* __restrict__ bi, float* __restrict__ out) {
    int row = blockIdx.x;
    int tid = threadIdx.x;
    const float* xr = x + (size_t)row*EE;
    float v0 = xr[tid], v1 = xr[tid + 256];
    __shared__ float rs[256], rq[256];
    rs[tid] = v0 + v1;
    rq[tid] = v0*v0 + v1*v1;
    __syncthreads();
    for (int off = 128; off > 0; off >>= 1) {
        if (tid < off) { rs[tid] += rs[tid+off]; rq[tid] += rq[tid+off]; }
        __syncthreads();
    }
    __shared__ float s_m, s_r;
    if (tid == 0) {
        float m = rs[0] * (1.0f/EE);
        float var = rq[0] * (1.0f/EE) - m*m;
        s_m = m; s_r = rsqrtf(var + 1e-5f);
    }
    __syncthreads();
    float m = s_m, r = s_r;
    float* orow = out + (size_t)row*EE;
    orow[tid]       = (v0 - m)*r*sc[tid]       + bi[tid];
    orow[tid + 256] = (v1 - m)*r*sc[tid + 256] + bi[tid + 256];
}

// ---------------- gelu (tanh approximation, matches jax default) ----------------
__device__ __forceinline__ float gelu_f(float x) {
    float x3 = x*x*x;
    return 0.5f*x*(1.0f + tanhf(0.7978845608028654f*(x + 0.044715f*x3)));
}

// ---------------- bf16 split helpers ----------------
__device__ __forceinline__ uint32_t packbf(float x, float y) {
    __nv_bfloat162 t = __floats2bfloat162_rn(x, y);
    return *reinterpret_cast<uint32_t*>(&t);
}
// hi = bf16_rn(x), lo = bf16_rn(x - hi); packed as (x in low half, y in high half)
__device__ __forceinline__ void split2(float x, float y, uint32_t& hi, uint32_t& lo) {
    float xh = __bfloat162float(__float2bfloat16(x));
    float yh = __bfloat162float(__float2bfloat16(y));
    hi = packbf(x, y);
    lo = packbf(x - xh, y - yh);
}

__device__ __forceinline__ void mma_bf16(float d[4], const uint32_t a[4], const uint32_t b[2]) {
    asm volatile(
        "mma.sync.aligned.m16n8k16.row.col.f32.bf16.bf16.f32 "
        "{%0,%1,%2,%3}, {%4,%5,%6,%7}, {%8,%9}, {%0,%1,%2,%3};\n"
        : "+f"(d[0]), "+f"(d[1]), "+f"(d[2]), "+f"(d[3])
        : "r"(a[0]), "r"(a[1]), "r"(a[2]), "r"(a[3]), "r"(b[0]), "r"(b[1]));
}

// ---------------- split-bf16 (3-term) tensor GEMM: C[M,N] = A[M,K] @ B[K,N] ----------------
// BM=BN=128, BK=16, 256 threads = 8 warps (2x4), warp tile 64x32, m16n8k16 frags.
// A stored as packed k-pairs (8 per row), uint32 stride 12 -> conflict-free frag LDS.
// B stored as packed k-pairs (8 pair-rows x 128 cols), uint32 stride 136.
#define AST 12
#define BST 136
template<int ACT, bool ACCUM, bool HASB>
__global__ void __launch_bounds__(256) bf3_gemm(const float* __restrict__ A,
                                                const float* __restrict__ Bm,
                                                const float* __restrict__ bias,
                                                float* __restrict__ C,
                                                int M, int N, int K) {
    __shared__ uint32_t AsH[2][128*AST];
    __shared__ uint32_t AsL[2][128*AST];
    __shared__ uint32_t BsH[2][8*BST];
    __shared__ uint32_t BsL[2][8*BST];
    int tid = threadIdx.x;
    int lane = tid & 31;
    int warp = tid >> 5;
    int wm = (warp >> 2) * 64;
    int wn = (warp & 3) * 32;
    int bm = blockIdx.y * 128, bn = blockIdx.x * 128;

    float acc[4][4][4];
#pragma unroll
    for (int mi = 0; mi < 4; mi++)
#pragma unroll
        for (int ni = 0; ni < 4; ni++)
#pragma unroll
            for (int r = 0; r < 4; r++) acc[mi][ni][r] = 0.0f;

    const float* Ab = A + (size_t)bm * K;
    const float* Bb = Bm + bn;

    // prefetch registers
    uint32_t rAh[2][2], rAl[2][2], rBh[4], rBl[4];
    int nk = K / 16;

    // A: 128 rows x 16 k. 512 float4 tasks, 2 per thread. idx: row=idx>>2, kcol=(idx&3)*4.
    // B: 16 k x 128 n. 256 tasks: p=tid>>5 (pair-row), cg=(tid&31)*4 (col group); loads rows 2p,2p+1.
    int a_r0 = tid >> 2, a_c4 = (tid & 3) * 4;
    int b_p = tid >> 5, b_cg = (tid & 31) * 4;

#define LOAD_AB(K0)                                                              \
    {                                                                            \
        _Pragma("unroll")                                                        \
        for (int i = 0; i < 2; i++) {                                            \
            int r = a_r0 + i*64;                                                 \
            float4 v = *(const float4*)(Ab + (size_t)r*K + (K0) + a_c4);         \
            split2(v.x, v.y, rAh[i][0], rAl[i][0]);                              \
            split2(v.z, v.w, rAh[i][1], rAl[i][1]);                              \
        }                                                                        \
        const float* bp0 = Bb + (size_t)((K0) + 2*b_p)*N + b_cg;                 \
        float4 v0 = *(const float4*)bp0;                                         \
        float4 v1 = *(const float4*)(bp0 + N);                                   \
        split2(v0.x, v1.x, rBh[0], rBl[0]);                                      \
        split2(v0.y, v1.y, rBh[1], rBl[1]);                                      \
        split2(v0.z, v1.z, rBh[2], rBl[2]);                                      \
        split2(v0.w, v1.w, rBh[3], rBl[3]);                                      \
    }

#define STORE_AB(BUF)                                                            \
    {                                                                            \
        _Pragma("unroll")                                                        \
        for (int i = 0; i < 2; i++) {                                            \
            int r = a_r0 + i*64; int cp = a_c4 >> 1;                             \
            *(uint2*)&AsH[BUF][r*AST + cp] = make_uint2(rAh[i][0], rAh[i][1]);   \
            *(uint2*)&AsL[BUF][r*AST + cp] = make_uint2(rAl[i][0], rAl[i][1]);   \
        }                                                                        \
        *(uint4*)&BsH[BUF][b_p*BST + b_cg] = make_uint4(rBh[0], rBh[1], rBh[2], rBh[3]); \
        *(uint4*)&BsL[BUF][b_p*BST + b_cg] = make_uint4(rBl[0], rBl[1], rBl[2], rBl[3]); \
    }

    LOAD_AB(0)
    STORE_AB(0)
    __syncthreads();

    int ar0 = wm + (lane >> 2);
    int ac0 = lane & 3;
    int bc0 = wn + (lane >> 2);
    int bp0 = lane & 3;

    for (int it = 0; it < nk; it++) {
        int buf = it & 1;
        if (it + 1 < nk) { LOAD_AB((it + 1) * 16) }

        uint32_t afh[4][4], afl[4][4], bfh[4][2], bfl[4][2];
#pragma unroll
        for (int mi = 0; mi < 4; mi++) {
            int base = (ar0 + mi*16)*AST + ac0;
            afh[mi][0] = AsH[buf][base];
            afh[mi][1] = AsH[buf][base + 8*AST];
            afh[mi][2] = AsH[buf][base + 4];
            afh[mi][3] = AsH[buf][base + 8*AST + 4];
            afl[mi][0] = AsL[buf][base];
            afl[mi][1] = AsL[buf][base + 8*AST];
            afl[mi][2] = AsL[buf][base + 4];
            afl[mi][3] = AsL[buf][base + 8*AST + 4];
        }
#pragma unroll
        for (int ni = 0; ni < 4; ni++) {
            int base = bp0*BST + bc0 + ni*8;
            bfh[ni][0] = BsH[buf][base];
            bfh[ni][1] = BsH[buf][base + 4*BST];
            bfl[ni][0] = BsL[buf][base];
            bfl[ni][1] = BsL[buf][base + 4*BST];
        }
#pragma unroll
        for (int mi = 0; mi < 4; mi++)
#pragma unroll
            for (int ni = 0; ni < 4; ni++) {
                mma_bf16(acc[mi][ni], afl[mi], bfh[ni]);
                mma_bf16(acc[mi][ni], afh[mi], bfl[ni]);
                mma_bf16(acc[mi][ni], afh[mi], bfh[ni]);
            }

        if (it + 1 < nk) {
            __syncthreads();
            STORE_AB(buf ^ 1)
            __syncthreads();
        }
    }

    // epilogue (m16n8 C frag layout: c0,c1 @ (row, 2c..2c+1), c2,c3 @ (row+8))
#pragma unroll
    for (int mi = 0; mi < 4; mi++) {
        int r0 = bm + wm + mi*16 + (lane >> 2);
#pragma unroll
        for (int ni = 0; ni < 4; ni++) {
            int c0 = bn + wn + ni*8 + (lane & 3)*2;
            float* a = acc[mi][ni];
#pragma unroll
            for (int hr = 0; hr < 2; hr++) {
                int r = r0 + hr*8;
                float v0 = a[hr*2 + 0], v1 = a[hr*2 + 1];
                if (HASB) { v0 += bias[c0]; v1 += bias[c0+1]; }
                if (ACT == 1) { v0 = gelu_f(v0); v1 = gelu_f(v1); }
                size_t o = (size_t)r*N + c0;
                if (ACCUM) {
                    float2 old = *(float2*)&C[o];
                    old.x += v0; old.y += v1;
                    *(float2*)&C[o] = old;
                } else {
                    float2 t2; t2.x = v0; t2.y = v1;
                    *(float2*)&C[o] = t2;
                }
            }
        }
    }
}

// ---------------- per-(b,h,n) inverse q norm ----------------
__global__ void qinv_kernel(const float* __restrict__ q, float* __restrict__ qinv) {
    int gw = (blockIdx.x*blockDim.x + threadIdx.x) >> 5;
    int lane = threadIdx.x & 31;
    if (gw >= MM*HH) return;
    int h = gw % HH;
    int row = gw / HH;                 // b*S + n
    const float* qp = q + (size_t)row*EE + h*DD;
    float v0 = qp[lane], v1 = qp[lane + 32];
    float ss = v0*v0 + v1*v1;
#pragma unroll
    for (int o = 16; o; o >>= 1) ss += __shfl_xor_sync(0xffffffffu, ss, o);
    if (lane == 0) {
        int b = row / SS, n = row % SS;
        qinv[((size_t)b*HH + h)*SS + n] = 1.0f/(sqrtf(ss) + 1e-8f);
    }
}

// ---------------- cluster distances: dists[b,h,c,n] = qn . mn ----------------
__global__ void dist_kernel(const float* __restrict__ q, const float* __restrict__ qinv,
                            const float* __restrict__ means_l, float* __restrict__ dists) {
    int blk = blockIdx.x;              // (b*H + h)*C + c
    int c = blk % CC; int bh = blk / CC; int h = bh % HH; int b = bh / HH;
    __shared__ float mm[64];
    __shared__ float red[256];
    int tid = threadIdx.x;
    float msq = 0.0f;
    if (tid < 64) { float mv = means_l[(h*CC + c)*DD + tid]; mm[tid] = mv; msq = mv*mv; }
    red[tid] = msq;
    __syncthreads();
    for (int off = 128; off > 0; off >>= 1) {
        if (tid < off) red[tid] += red[tid+off];
        __syncthreads();
    }
    float minv = 1.0f/(sqrtf(red[0]) + 1e-8f);
    float* drow = dists + (size_t)blk*SS;
    const float* qbase = q + (size_t)b*SS*EE + h*DD;
    const float* qi = qinv + (size_t)bh*SS;
    for (int n = tid; n < SS; n += 256) {
        const float4* qp = (const float4*)(qbase + (size_t)n*EE);
        float dot = 0.0f;
#pragma unroll
        for (int k4 = 0; k4 < 16; k4++) {
            float4 vv = qp[k4];
            dot += vv.x*mm[k4*4] + vv.y*mm[k4*4+1] + vv.z*mm[k4*4+2] + vv.w*mm[k4*4+3];
        }
        drow[n] = dot * minv * qi[n];
    }
}

// ---------------- exact top-64 of 4096 (tie-break: smallest index, matches jax) ----------------
__global__ void topk_kernel(const float* __restrict__ dists, int* __restrict__ idxout) {
    int blk = blockIdx.x;
    __shared__ float vals[SS];
    __shared__ float rv[256];
    __shared__ int   ri[256];
    int tid = threadIdx.x;
    const float* drow = dists + (size_t)blk*SS;
    for (int n = tid; n < SS; n += 256) vals[n] = drow[n];
    __syncthreads();
    int* orow = idxout + blk*WIN;
    for (int it = 0; it < WIN; it++) {
        float bv = -INFINITY; int bi = -1;
        for (int n = tid; n < SS; n += 256) {
            float v = vals[n];
            if (v > bv || (v == bv && n < bi)) { bv = v; bi = n; }
        }
        rv[tid] = bv; ri[tid] = bi;
        __syncthreads();
        for (int off = 128; off > 0; off >>= 1) {
            if (tid < off) {
                float ov = rv[tid+off]; int oi = ri[tid+off];
                if (ov > rv[tid] || (ov == rv[tid] && oi != -1 && (ri[tid] == -1 || oi < ri[tid]))) {
                    rv[tid] = ov; ri[tid] = oi;
                }
            }
            __syncthreads();
        }
        if (tid == 0) { orow[it] = ri[0]; vals[ri[0]] = -INFINITY; }
        __syncthreads();
    }
}

// ---------------- bucket attention: gather, scores, mask, softmax, AV, scatter-add ----------------
__global__ void bucket_attn_kernel(const float* __restrict__ q, const float* __restrict__ k,
                                   const float* __restrict__ v, const int* __restrict__ value,
                                   const int* __restrict__ idxin, float* __restrict__ attout,
                                   float* __restrict__ cnt) {
    extern __shared__ float sm[];
    float* qb = sm;
    float* kb = qb + 64*65;
    float* vb = kb + 64*65;
    float* sc = vb + 64*65;
    __shared__ int idxs[64];
    __shared__ int kms[64];
    int blk = blockIdx.x;              // (b*H + h)*C + c
    int bh = blk / CC; int h = bh % HH; int b = bh / HH;
    int tid = threadIdx.x;
    if (tid < 64) {
        int t = idxin[blk*WIN + tid];
        idxs[tid] = t;
        kms[tid] = (value[b*SS + t] != 0);
    }
    __syncthreads();
    for (int i = tid; i < 64*64; i += 256) {
        int w = i >> 6, d = i & 63;
        size_t base = ((size_t)(b*SS + idxs[w]))*EE + h*DD + d;
        qb[w*65 + d] = q[base];
        kb[w*65 + d] = k[base];
        vb[w*65 + d] = v[base];
    }
    __syncthreads();
    float sres[16];
#pragma unroll
    for (int j = 0; j < 16; j++) {
        int i = tid + j*256; int w = i >> 6, xx = i & 63;
        float dot = 0.0f;
#pragma unroll
        for (int kk = 0; kk < 64; kk++) dot += qb[w*65+kk]*kb[xx*65+kk];
        bool allowed = (idxs[w] >= idxs[xx]) && kms[xx];
        sres[j] = allowed ? dot*0.125f : -1e9f;
    }
#pragma unroll
    for (int j = 0; j < 16; j++) {
        int i = tid + j*256;
        sc[(i >> 6)*65 + (i & 63)] = sres[j];
    }
    __syncthreads();
    if (tid < 64) {
        float mx = -INFINITY;
        for (int xx = 0; xx < 64; xx++) mx = fmaxf(mx, sc[tid*65+xx]);
        float sum = 0.0f;
        for (int xx = 0; xx < 64; xx++) { float e = expf(sc[tid*65+xx]-mx); sc[tid*65+xx] = e; sum += e; }
        float inv = 1.0f/sum;
        for (int xx = 0; xx < 64; xx++) sc[tid*65+xx] *= inv;
    }
    __syncthreads();
#pragma unroll
    for (int j = 0; j < 16; j++) {
        int i = tid + j*256; int w = i >> 6, d = i & 63;
        float o = 0.0f;
#pragma unroll
        for (int xx = 0; xx < 64; xx++) o += sc[w*65+xx]*vb[xx*65+d];
        atomicAdd(&attout[((size_t)(b*SS + idxs[w]))*EE + h*DD + d], o);
    }
    if (tid < 64) atomicAdd(&cnt[(size_t)(b*SS + idxs[tid])*HH + h], 1.0f);
}

// ---------------- scatter-mean normalization ----------------
__global__ void norm_attout_kernel(float* __restrict__ attout, const float* __restrict__ cnt) {
    int i = blockIdx.x*256 + threadIdx.x;   // over MM*EE
    int row = i >> 9;
    int h = (i & 511) >> 6;
    float c = cnt[(size_t)row*HH + h];
    attout[i] = attout[i] / fmaxf(c, 1.0f);
}

// ---------------- head: logits = x @ head_w.T  (N=17), warp per row ----------------
__global__ void head_kernel(const float* __restrict__ x, const float* __restrict__ hw,
                            float* __restrict__ out) {
    int gw = (blockIdx.x*256 + threadIdx.x) >> 5;
    int lane = threadIdx.x & 31;
    if (gw >= MM) return;
    const float* xp = x + (size_t)gw*EE;
    float xr[16];
#pragma unroll
    for (int i = 0; i < 16; i++) xr[i] = xp[lane + i*32];
    for (int o = 0; o < NVOC; o++) {
        const float* w = hw + o*EE;
        float s = 0.0f;
#pragma unroll
        for (int i = 0; i < 16; i++) s += xr[i]*w[lane + i*32];
#pragma unroll
        for (int off = 16; off; off >>= 1) s += __shfl_xor_sync(0xffffffffu, s, off);
        if (lane == 0) out[(size_t)gw*NVOC + o] = s;
    }
}

// ---------------- host orchestration ----------------
extern "C" void kernel_launch(void* const* d_in, const int* in_sizes, int n_in,
                              void* d_out, int out_size) {
    const int*   value     = (const int*)d_in[0];
    const int*   depth     = (const int*)d_in[1];
    const int*   pos       = (const int*)d_in[2];
    const float* sos       = (const float*)d_in[3];
    const float* tok_emb   = (const float*)d_in[4];
    const float* depth_emb = (const float*)d_in[5];
    const float* pos_emb   = (const float*)d_in[6];
    const float* ln1_s     = (const float*)d_in[7];
    const float* ln1_b     = (const float*)d_in[8];
    const float* Wq        = (const float*)d_in[9];
    const float* Wk        = (const float*)d_in[10];
    const float* Wv        = (const float*)d_in[11];
    const float* Wo        = (const float*)d_in[12];
    const float* means     = (const float*)d_in[13];
    const float* ln2_s     = (const float*)d_in[14];
    const float* ln2_b     = (const float*)d_in[15];
    const float* W1        = (const float*)d_in[16];
    const float* b1        = (const float*)d_in[17];
    const float* W2        = (const float*)d_in[18];
    const float* b2        = (const float*)d_in[19];
    const float* head_w    = (const float*)d_in[20];
    float* out = (float*)d_out;

    float *x, *h, *q, *k, *v, *t, *dists, *qinv, *attout, *cnt;
    int* idxb;
    cudaGetSymbolAddress((void**)&x, g_x);
    cudaGetSymbolAddress((void**)&h, g_h);
    cudaGetSymbolAddress((void**)&q, g_q);
    cudaGetSymbolAddress((void**)&k, g_k);
    cudaGetSymbolAddress((void**)&v, g_v);
    cudaGetSymbolAddress((void**)&t, g_t);
    cudaGetSymbolAddress((void**)&dists, g_dists);
    cudaGetSymbolAddress((void**)&qinv, g_qinv);
    cudaGetSymbolAddress((void**)&idxb, g_idx);
    cudaGetSymbolAddress((void**)&attout, g_attout);
    cudaGetSymbolAddress((void**)&cnt, g_cnt);

    const int ATTN_SMEM = 4 * 64 * 65 * (int)sizeof(float);
    cudaFuncSetAttribute(bucket_attn_kernel, cudaFuncAttributeMaxDynamicSharedMemorySize, ATTN_SMEM);

    embed_kernel<<<MM, 128>>>(value, depth, pos, sos, tok_emb, depth_emb, pos_emb, x);

    dim3 gE(EE/128, MM/128);     // 4 x 128
    dim3 gF(FF/128, MM/128);     // 16 x 128

    for (int l = 0; l < LL; l++) {
        const float* wq = Wq + (size_t)l*EE*EE;
        const float* wk = Wk + (size_t)l*EE*EE;
        const float* wv = Wv + (size_t)l*EE*EE;
        const float* wo = Wo + (size_t)l*EE*EE;
        const float* w1 = W1 + (size_t)l*EE*FF;
        const float* w2 = W2 + (size_t)l*FF*EE;
        const float* ml = means + (size_t)l*HH*CC*DD;

        ln_kernel<<<MM, 256>>>(x, ln1_s + l*EE, ln1_b + l*EE, h);
        bf3_gemm<0,false,false><<<gE, 256>>>(h, wq, nullptr, q, MM, EE, EE);
        bf3_gemm<0,false,false><<<gE, 256>>>(h, wk, nullptr, k, MM, EE, EE);
        bf3_gemm<0,false,false><<<gE, 256>>>(h, wv, nullptr, v, MM, EE, EE);

        qinv_kernel<<<(MM*HH*32)/256, 256>>>(q, qinv);
        dist_kernel<<<BB*HH*CC, 256>>>(q, qinv, ml, dists);
        topk_kernel<<<BB*HH*CC, 256>>>(dists, idxb);

        cudaMemsetAsync(attout, 0, (size_t)MM*EE*sizeof(float));
        cudaMemsetAsync(cnt, 0, (size_t)MM*HH*sizeof(float));
        bucket_attn_kernel<<<BB*HH*CC, 256, ATTN_SMEM>>>(q, k, v, value, idxb, attout, cnt);
        norm_attout_kernel<<<(MM*EE)/256, 256>>>(attout, cnt);

        bf3_gemm<0,true,false><<<gE, 256>>>(attout, wo, nullptr, x, MM, EE, EE);   // x += attn @ Wo

        ln_kernel<<<MM, 256>>>(x, ln2_s + l*EE, ln2_b + l*EE, h);
        bf3_gemm<1,false,true><<<gF, 256>>>(h, w1, b1 + l*FF, t, MM, FF, EE);      // gelu(h@W1+b1)
        bf3_gemm<0,true,true><<<gE, 256>>>(t, w2, b2 + l*EE, x, MM, EE, FF);       // x += t@W2+b2
    }

    head_kernel<<<MM/8, 256>>>(x, head_w, out);
}

// round 4
// speedup vs baseline: 2.2718x; 1.3696x over previous
#include <cuda_runtime.h>
#include <cuda_bf16.h>
#include <math.h>
#include <stdint.h>

// ---------------- problem constants ----------------
#define BB 4
#define SS 4096
#define EE 512
#define HH 8
#define LL 4
#define AA 3
#define WIN 64
#define CC 64           // S / WIN clusters
#define DD 64           // E / H
#define MM (BB*SS)      // 16384 rows
#define FF (4*EE)       // 2048 ffn dim
#define NVOC 17

// ---------------- scratch (device globals; no allocation allowed) ----------------
__device__ float g_x[MM*EE];
__device__ float g_q[MM*EE];
__device__ float g_k[MM*EE];
__device__ float g_v[MM*EE];
__device__ float g_dists[BB*HH*CC*SS];
__device__ int   g_idx[BB*HH*CC*WIN];
__device__ float g_attout[MM*EE];
__device__ float g_cnt[MM*HH];
// split activations
__device__ __nv_bfloat16 g_hh[MM*EE],  g_hl[MM*EE];
__device__ __nv_bfloat16 g_th[MM*FF],  g_tl[MM*FF];
__device__ __nv_bfloat16 g_aoh[MM*EE], g_aol[MM*EE];
// split weights
__device__ __nv_bfloat16 g_Wqh[LL*EE*EE], g_Wql[LL*EE*EE];
__device__ __nv_bfloat16 g_Wkh[LL*EE*EE], g_Wkl[LL*EE*EE];
__device__ __nv_bfloat16 g_Wvh[LL*EE*EE], g_Wvl[LL*EE*EE];
__device__ __nv_bfloat16 g_Woh[LL*EE*EE], g_Wol[LL*EE*EE];
__device__ __nv_bfloat16 g_W1h[LL*EE*FF], g_W1l[LL*EE*FF];
__device__ __nv_bfloat16 g_W2h[LL*FF*EE], g_W2l[LL*FF*EE];

// ---------------- bf16 split helpers ----------------
__device__ __forceinline__ uint32_t packbf(float x, float y) {
    __nv_bfloat162 t = __floats2bfloat162_rn(x, y);
    return *reinterpret_cast<uint32_t*>(&t);
}
__device__ __forceinline__ void split2(float x, float y, uint32_t& hi, uint32_t& lo) {
    float xh = __bfloat162float(__float2bfloat16(x));
    float yh = __bfloat162float(__float2bfloat16(y));
    hi = packbf(x, y);
    lo = packbf(x - xh, y - yh);
}
__device__ __forceinline__ void split1(float x, __nv_bfloat16& h, __nv_bfloat16& l) {
    h = __float2bfloat16(x);
    l = __float2bfloat16(x - __bfloat162float(h));
}

// ---------------- weight split prep ----------------
__global__ void split_kernel(const float* __restrict__ s, __nv_bfloat16* __restrict__ dh,
                             __nv_bfloat16* __restrict__ dl, int n) {
    int i = (blockIdx.x*256 + threadIdx.x)*4;
    if (i >= n) return;
    float4 v = *(const float4*)(s + i);
    uint32_t hA, lA, hB, lB;
    split2(v.x, v.y, hA, lA);
    split2(v.z, v.w, hB, lB);
    *(uint2*)(dh + i) = make_uint2(hA, hB);
    *(uint2*)(dl + i) = make_uint2(lA, lB);
}

// ---------------- embedding + shift-right ----------------
__global__ void embed_kernel(const int* __restrict__ value, const int* __restrict__ depth,
                             const int* __restrict__ pos, const float* __restrict__ sos,
                             const float* __restrict__ tok, const float* __restrict__ dep,
                             const float* __restrict__ pemb, float* __restrict__ x) {
    int row = blockIdx.x;
    int t = row & (SS - 1);
    if (t == 0) {
        for (int e = threadIdx.x; e < EE; e += blockDim.x) x[(size_t)row*EE + e] = sos[e];
        return;
    }
    int pr = row - 1;
    int v  = value[pr], dp = depth[pr];
    int p0 = pos[pr*AA+0], p1 = pos[pr*AA+1], p2 = pos[pr*AA+2];
    for (int e = threadIdx.x; e < EE; e += blockDim.x) {
        float s = tok[v*EE+e] + dep[dp*EE+e]
                + pemb[(0*65 + p0)*EE + e]
                + pemb[(1*65 + p1)*EE + e]
                + pemb[(2*65 + p2)*EE + e];
        x[(size_t)row*EE + e] = s;
    }
}

// ---------------- layernorm -> split bf16 output ----------------
__global__ void ln_kernel(const float* __restrict__ x, const float* __restrict__ sc,
                          const float* __restrict__ bi,
                          __nv_bfloat16* __restrict__ oh, __nv_bfloat16* __restrict__ ol) {
    int row = blockIdx.x;
    int tid = threadIdx.x;
    const float* xr = x + (size_t)row*EE;
    float v0 = xr[tid], v1 = xr[tid + 256];
    __shared__ float rs[256], rq[256];
    rs[tid] = v0 + v1;
    rq[tid] = v0*v0 + v1*v1;
    __syncthreads();
    for (int off = 128; off > 0; off >>= 1) {
        if (tid < off) { rs[tid] += rs[tid+off]; rq[tid] += rq[tid+off]; }
        __syncthreads();
    }
    __shared__ float s_m, s_r;
    if (tid == 0) {
        float m = rs[0] * (1.0f/EE);
        float var = rq[0] * (1.0f/EE) - m*m;
        s_m = m; s_r = rsqrtf(var + 1e-5f);
    }
    __syncthreads();
    float m = s_m, r = s_r;
    float y0 = (v0 - m)*r*sc[tid]       + bi[tid];
    float y1 = (v1 - m)*r*sc[tid + 256] + bi[tid + 256];
    __nv_bfloat16 h, l;
    split1(y0, h, l); oh[(size_t)row*EE + tid] = h;       ol[(size_t)row*EE + tid] = l;
    split1(y1, h, l); oh[(size_t)row*EE + tid + 256] = h; ol[(size_t)row*EE + tid + 256] = l;
}

// ---------------- gelu ----------------
__device__ __forceinline__ float gelu_f(float x) {
    float x3 = x*x*x;
    return 0.5f*x*(1.0f + tanhf(0.7978845608028654f*(x + 0.044715f*x3)));
}

__device__ __forceinline__ void mma_bf16(float d[4], const uint32_t a[4], const uint32_t b[2]) {
    asm volatile(
        "mma.sync.aligned.m16n8k16.row.col.f32.bf16.bf16.f32 "
        "{%0,%1,%2,%3}, {%4,%5,%6,%7}, {%8,%9}, {%0,%1,%2,%3};\n"
        : "+f"(d[0]), "+f"(d[1]), "+f"(d[2]), "+f"(d[3])
        : "r"(a[0]), "r"(a[1]), "r"(a[2]), "r"(a[3]), "r"(b[0]), "r"(b[1]));
}

// ---------------- split-bf16 tensor GEMM, pre-split operands ----------------
// BM=BN=128, BK=16, 256 threads = 8 warps (2x4), warp tile 64x32, m16n8k16.
// OUTMODE: 0=store f32, 1=accum f32, 2=split bf16 store
#define AST 12
#define BST 136
template<int ACT, int OUTMODE, bool HASB>
__global__ void __launch_bounds__(256,2) bf3_gemm(
    const __nv_bfloat16* __restrict__ Ah, const __nv_bfloat16* __restrict__ Al,
    const __nv_bfloat16* __restrict__ Bh, const __nv_bfloat16* __restrict__ Bl,
    const float* __restrict__ bias,
    float* __restrict__ C,
    __nv_bfloat16* __restrict__ Ch, __nv_bfloat16* __restrict__ Cl,
    int M, int N, int K)
{
    __shared__ uint32_t AsH[2][128*AST];
    __shared__ uint32_t AsL[2][128*AST];
    __shared__ uint32_t BsH[2][8*BST];
    __shared__ uint32_t BsL[2][8*BST];
    int tid = threadIdx.x;
    int lane = tid & 31;
    int warp = tid >> 5;
    int wm = (warp >> 2) * 64;
    int wn = (warp & 3) * 32;
    int bm = blockIdx.y * 128, bn = blockIdx.x * 128;

    float acc[4][4][4];
#pragma unroll
    for (int mi = 0; mi < 4; mi++)
#pragma unroll
        for (int ni = 0; ni < 4; ni++)
#pragma unroll
            for (int r = 0; r < 4; r++) acc[mi][ni][r] = 0.0f;

    // A: thread loads 8 consecutive bf16 (one uint4) : row=tid>>1, half=(tid&1)*8
    // B: thread loads cols cg..cg+3 of rows 2p,2p+1 : p=tid>>5, cg=(tid&31)*4
    int a_r = tid >> 1, a_h = (tid & 1) * 8;
    int b_p = tid >> 5, b_cg = (tid & 31) * 4;
    const __nv_bfloat16* Abh = Ah + (size_t)bm * K;
    const __nv_bfloat16* Abl = Al + (size_t)bm * K;
    const __nv_bfloat16* Bbh = Bh + bn;
    const __nv_bfloat16* Bbl = Bl + bn;

    uint4 pAh, pAl;
    uint2 r0h, r1h, r0l, r1l;
    int nk = K / 16;

#define LOAD_AB(K0)                                                       \
    {                                                                     \
        pAh = *(const uint4*)(Abh + (size_t)a_r*K + (K0) + a_h);          \
        pAl = *(const uint4*)(Abl + (size_t)a_r*K + (K0) + a_h);          \
        const __nv_bfloat16* bp = Bbh + (size_t)((K0) + 2*b_p)*N + b_cg;  \
        r0h = *(const uint2*)bp;  r1h = *(const uint2*)(bp + N);          \
        const __nv_bfloat16* bq = Bbl + (size_t)((K0) + 2*b_p)*N + b_cg;  \
        r0l = *(const uint2*)bq;  r1l = *(const uint2*)(bq + N);          \
    }

#define STORE_AB(BUF)                                                     \
    {                                                                     \
        *(uint4*)&AsH[BUF][a_r*AST + (a_h>>1)] = pAh;                     \
        *(uint4*)&AsL[BUF][a_r*AST + (a_h>>1)] = pAl;                     \
        uint32_t q0 = __byte_perm(r0h.x, r1h.x, 0x5410);                  \
        uint32_t q1 = __byte_perm(r0h.x, r1h.x, 0x7632);                  \
        uint32_t q2 = __byte_perm(r0h.y, r1h.y, 0x5410);                  \
        uint32_t q3 = __byte_perm(r0h.y, r1h.y, 0x7632);                  \
        *(uint4*)&BsH[BUF][b_p*BST + b_cg] = make_uint4(q0,q1,q2,q3);     \
        q0 = __byte_perm(r0l.x, r1l.x, 0x5410);                           \
        q1 = __byte_perm(r0l.x, r1l.x, 0x7632);                           \
        q2 = __byte_perm(r0l.y, r1l.y, 0x5410);                           \
        q3 = __byte_perm(r0l.y, r1l.y, 0x7632);                           \
        *(uint4*)&BsL[BUF][b_p*BST + b_cg] = make_uint4(q0,q1,q2,q3);     \
    }

    LOAD_AB(0)
    STORE_AB(0)
    __syncthreads();

    int ar0 = wm + (lane >> 2);
    int ac0 = lane & 3;
    int bc0 = wn + (lane >> 2);
    int bp0 = lane & 3;

    for (int it = 0; it < nk; it++) {
        int buf = it & 1;
        uint32_t afh[4][4], afl[4][4], bfh[4][2], bfl[4][2];
#pragma unroll
        for (int mi = 0; mi < 4; mi++) {
            int base = (ar0 + mi*16)*AST + ac0;
            afh[mi][0] = AsH[buf][base];
            afh[mi][1] = AsH[buf][base + 8*AST];
            afh[mi][2] = AsH[buf][base + 4];
            afh[mi][3] = AsH[buf][base + 8*AST + 4];
            afl[mi][0] = AsL[buf][base];
            afl[mi][1] = AsL[buf][base + 8*AST];
            afl[mi][2] = AsL[buf][base + 4];
            afl[mi][3] = AsL[buf][base + 8*AST + 4];
        }
#pragma unroll
        for (int ni = 0; ni < 4; ni++) {
            int base = bp0*BST + bc0 + ni*8;
            bfh[ni][0] = BsH[buf][base];
            bfh[ni][1] = BsH[buf][base + 4*BST];
            bfl[ni][0] = BsL[buf][base];
            bfl[ni][1] = BsL[buf][base + 4*BST];
        }
        if (it + 1 < nk) {
            LOAD_AB((it + 1) * 16)
            STORE_AB(buf ^ 1)
        }
        __syncthreads();
#pragma unroll
        for (int mi = 0; mi < 4; mi++)
#pragma unroll
            for (int ni = 0; ni < 4; ni++) {
                mma_bf16(acc[mi][ni], afl[mi], bfh[ni]);
                mma_bf16(acc[mi][ni], afh[mi], bfl[ni]);
                mma_bf16(acc[mi][ni], afh[mi], bfh[ni]);
            }
    }

#pragma unroll
    for (int mi = 0; mi < 4; mi++) {
        int r0 = bm + wm + mi*16 + (lane >> 2);
#pragma unroll
        for (int ni = 0; ni < 4; ni++) {
            int c0 = bn + wn + ni*8 + (lane & 3)*2;
            float* a = acc[mi][ni];
#pragma unroll
            for (int hr = 0; hr < 2; hr++) {
                int r = r0 + hr*8;
                float v0 = a[hr*2 + 0], v1 = a[hr*2 + 1];
                if (HASB) { v0 += bias[c0]; v1 += bias[c0+1]; }
                if (ACT == 1) { v0 = gelu_f(v0); v1 = gelu_f(v1); }
                size_t o = (size_t)r*N + c0;
                if (OUTMODE == 0) {
                    float2 t2; t2.x = v0; t2.y = v1;
                    *(float2*)&C[o] = t2;
                } else if (OUTMODE == 1) {
                    float2 old = *(float2*)&C[o];
                    old.x += v0; old.y += v1;
                    *(float2*)&C[o] = old;
                } else {
                    uint32_t hh2, ll2;
                    split2(v0, v1, hh2, ll2);
                    *(uint32_t*)&Ch[o] = hh2;
                    *(uint32_t*)&Cl[o] = ll2;
                }
            }
        }
    }
}

// ---------------- fused qnorm + cluster distances (tiled) ----------------
// grid: (SS/128, BB*HH). block 256. dynamic smem: qs[128*65] + ms[64*64] + mn[64] + qn[128]
__global__ void dist_kernel(const float* __restrict__ q, const float* __restrict__ means_l,
                            float* __restrict__ dists) {
    extern __shared__ float dsm[];
    float* qs = dsm;             // 128*65
    float* ms = qs + 128*65;     // 64*64
    float* mn = ms + 64*64;      // 64
    float* qn = mn + 64;         // 128
    int tile = blockIdx.x;
    int bh = blockIdx.y;
    int h = bh & 7, b = bh >> 3;
    int n0 = tile * 128;
    int tid = threadIdx.x;
    for (int i = tid; i < 64*64; i += 256) ms[i] = means_l[h*64*64 + i];
    for (int i = tid; i < 128*16; i += 256) {
        int r = i >> 4, c4 = (i & 15) * 4;
        float4 v = *(const float4*)(q + ((size_t)(b*SS + n0 + r))*EE + h*DD + c4);
        float* dst = qs + r*65 + c4;
        dst[0]=v.x; dst[1]=v.y; dst[2]=v.z; dst[3]=v.w;
    }
    __syncthreads();
    if (tid < 64) {
        float s = 0; const float* mr = ms + tid*64;
#pragma unroll 16
        for (int d = 0; d < 64; d++) s += mr[d]*mr[d];
        mn[tid] = 1.0f/(sqrtf(s) + 1e-8f);
    } else if (tid >= 128) {
        int r = tid - 128;
        float s = 0; const float* qr = qs + r*65;
#pragma unroll 16
        for (int d = 0; d < 64; d++) s += qr[d]*qr[d];
        qn[r] = 1.0f/(sqrtf(s) + 1e-8f);
    }
    __syncthreads();
    int nl = tid & 127;
    int c0 = (tid >> 7) * 32;
    float acc[32];
#pragma unroll
    for (int c = 0; c < 32; c++) acc[c] = 0.0f;
    for (int dc = 0; dc < 64; dc += 16) {
        float qreg[16];
#pragma unroll
        for (int d = 0; d < 16; d++) qreg[d] = qs[nl*65 + dc + d];
#pragma unroll
        for (int c = 0; c < 32; c++) {
            const float* mr = ms + (c0 + c)*64 + dc;
            float s = acc[c];
#pragma unroll
            for (int d = 0; d < 16; d++) s += qreg[d]*mr[d];
            acc[c] = s;
        }
    }
    float qi = qn[nl];
#pragma unroll
    for (int c = 0; c < 32; c++) {
        int cc = c0 + c;
        dists[((size_t)bh*CC + cc)*SS + n0 + nl] = acc[c]*mn[cc]*qi;
    }
}

// ---------------- radix-select top-64 (exact, ties -> smallest index) ----------------
__global__ void topk_kernel(const float* __restrict__ dists, int* __restrict__ idxout) {
    __shared__ uint32_t keys[SS];
    __shared__ int hist[256];
    __shared__ int ties[SS];
    __shared__ int rmin[256];
    __shared__ int s_chosen, s_rem, s_cntgt, s_ntie, s_pick;
    int blk = blockIdx.x, tid = threadIdx.x;
    const float* drow = dists + (size_t)blk*SS;
    for (int n = tid; n < SS; n += 256) {
        uint32_t u = __float_as_uint(drow[n]);
        keys[n] = (u & 0x80000000u) ? ~u : (u | 0x80000000u);
    }
    uint32_t prefix = 0, maskhi = 0;
    int rem = WIN;
    for (int p = 0; p < 4; p++) {
        int shift = 24 - 8*p;
        hist[tid] = 0;
        __syncthreads();
        for (int n = tid; n < SS; n += 256) {
            uint32_t kk = keys[n];
            if ((kk & maskhi) == prefix) atomicAdd(&hist[(kk >> shift) & 255], 1);
        }
        __syncthreads();
        if (tid == 0) {
            int cum = 0, bsel = 255;
            for (; bsel >= 0; bsel--) { cum += hist[bsel]; if (cum >= rem) break; }
            s_chosen = bsel; s_rem = rem - (cum - hist[bsel]);
        }
        __syncthreads();
        prefix |= ((uint32_t)s_chosen) << shift;
        maskhi |= 0xFFu << shift;
        rem = s_rem;
        __syncthreads();
    }
    uint32_t T = prefix;
    if (tid == 0) { s_cntgt = 0; s_ntie = 0; }
    __syncthreads();
    int* orow = idxout + blk*WIN;
    for (int n = tid; n < SS; n += 256) {
        uint32_t kk = keys[n];
        if (kk > T) { int pp = atomicAdd(&s_cntgt, 1); orow[pp] = n; }
        else if (kk == T) { int pp = atomicAdd(&s_ntie, 1); ties[pp] = n; }
    }
    __syncthreads();
    int cntgt = s_cntgt;
    int need = WIN - cntgt;
    int ntie = s_ntie;
    if (need > 0) {
        if (need == ntie) {
            for (int j = tid; j < need; j += 256) orow[cntgt + j] = ties[j];
        } else {
            int last = -1;
            for (int j = 0; j < need; j++) {
                int mymin = 0x7FFFFFFF;
                for (int t2 = tid; t2 < ntie; t2 += 256) {
                    int vv = ties[t2];
                    if (vv > last && vv < mymin) mymin = vv;
                }
                rmin[tid] = mymin;
                __syncthreads();
                for (int off = 128; off; off >>= 1) {
                    if (tid < off) rmin[tid] = min(rmin[tid], rmin[tid+off]);
                    __syncthreads();
                }
                if (tid == 0) { orow[cntgt + j] = rmin[0]; s_pick = rmin[0]; }
                __syncthreads();
                last = s_pick;
            }
        }
    }
}

// ---------------- bucket attention ----------------
__global__ void bucket_attn_kernel(const float* __restrict__ q, const float* __restrict__ k,
                                   const float* __restrict__ v, const int* __restrict__ value,
                                   const int* __restrict__ idxin, float* __restrict__ attout,
                                   float* __restrict__ cnt) {
    extern __shared__ float sm[];
    float* qb = sm;
    float* kb = qb + 64*65;
    float* vb = kb + 64*65;
    float* sc = vb + 64*65;
    __shared__ int idxs[64];
    __shared__ int kms[64];
    int blk = blockIdx.x;
    int bh = blk / CC; int h = bh % HH; int b = bh / HH;
    int tid = threadIdx.x;
    if (tid < 64) {
        int t = idxin[blk*WIN + tid];
        idxs[tid] = t;
        kms[tid] = (value[b*SS + t] != 0);
    }
    __syncthreads();
    for (int i = tid; i < 64*64; i += 256) {
        int w = i >> 6, d = i & 63;
        size_t base = ((size_t)(b*SS + idxs[w]))*EE + h*DD + d;
        qb[w*65 + d] = q[base];
        kb[w*65 + d] = k[base];
        vb[w*65 + d] = v[base];
    }
    __syncthreads();
    float sres[16];
#pragma unroll
    for (int j = 0; j < 16; j++) {
        int i = tid + j*256; int w = i >> 6, xx = i & 63;
        float dot = 0.0f;
#pragma unroll
        for (int kk = 0; kk < 64; kk++) dot += qb[w*65+kk]*kb[xx*65+kk];
        bool allowed = (idxs[w] >= idxs[xx]) && kms[xx];
        sres[j] = allowed ? dot*0.125f : -1e9f;
    }
#pragma unroll
    for (int j = 0; j < 16; j++) {
        int i = tid + j*256;
        sc[(i >> 6)*65 + (i & 63)] = sres[j];
    }
    __syncthreads();
    if (tid < 64) {
        float mx = -INFINITY;
        for (int xx = 0; xx < 64; xx++) mx = fmaxf(mx, sc[tid*65+xx]);
        float sum = 0.0f;
        for (int xx = 0; xx < 64; xx++) { float e = expf(sc[tid*65+xx]-mx); sc[tid*65+xx] = e; sum += e; }
        float inv = 1.0f/sum;
        for (int xx = 0; xx < 64; xx++) sc[tid*65+xx] *= inv;
    }
    __syncthreads();
#pragma unroll
    for (int j = 0; j < 16; j++) {
        int i = tid + j*256; int w = i >> 6, d = i & 63;
        float o = 0.0f;
#pragma unroll
        for (int xx = 0; xx < 64; xx++) o += sc[w*65+xx]*vb[xx*65+d];
        atomicAdd(&attout[((size_t)(b*SS + idxs[w]))*EE + h*DD + d], o);
    }
    if (tid < 64) atomicAdd(&cnt[(size_t)(b*SS + idxs[tid])*HH + h], 1.0f);
}

// ---------------- scatter-mean normalization -> split bf16 ----------------
__global__ void norm_attout_kernel(const float* __restrict__ attout, const float* __restrict__ cnt,
                                   __nv_bfloat16* __restrict__ oh, __nv_bfloat16* __restrict__ ol) {
    int i = blockIdx.x*256 + threadIdx.x;
    int row = i >> 9;
    int h = (i & 511) >> 6;
    float c = cnt[(size_t)row*HH + h];
    float val = attout[i] / fmaxf(c, 1.0f);
    __nv_bfloat16 hh2, ll2;
    split1(val, hh2, ll2);
    oh[i] = hh2; ol[i] = ll2;
}

// ---------------- head: logits = x @ head_w.T  (N=17), warp per row ----------------
__global__ void head_kernel(const float* __restrict__ x, const float* __restrict__ hw,
                            float* __restrict__ out) {
    int gw = (blockIdx.x*256 + threadIdx.x) >> 5;
    int lane = threadIdx.x & 31;
    if (gw >= MM) return;
    const float* xp = x + (size_t)gw*EE;
    float xr[16];
#pragma unroll
    for (int i = 0; i < 16; i++) xr[i] = xp[lane + i*32];
    for (int o = 0; o < NVOC; o++) {
        const float* w = hw + o*EE;
        float s = 0.0f;
#pragma unroll
        for (int i = 0; i < 16; i++) s += xr[i]*w[lane + i*32];
#pragma unroll
        for (int off = 16; off; off >>= 1) s += __shfl_xor_sync(0xffffffffu, s, off);
        if (lane == 0) out[(size_t)gw*NVOC + o] = s;
    }
}

// ---------------- host orchestration ----------------
extern "C" void kernel_launch(void* const* d_in, const int* in_sizes, int n_in,
                              void* d_out, int out_size) {
    const int*   value     = (const int*)d_in[0];
    const int*   depth     = (const int*)d_in[1];
    const int*   pos       = (const int*)d_in[2];
    const float* sos       = (const float*)d_in[3];
    const float* tok_emb   = (const float*)d_in[4];
    const float* depth_emb = (const float*)d_in[5];
    const float* pos_emb   = (const float*)d_in[6];
    const float* ln1_s     = (const float*)d_in[7];
    const float* ln1_b     = (const float*)d_in[8];
    const float* Wq        = (const float*)d_in[9];
    const float* Wk        = (const float*)d_in[10];
    const float* Wv        = (const float*)d_in[11];
    const float* Wo        = (const float*)d_in[12];
    const float* means     = (const float*)d_in[13];
    const float* ln2_s     = (const float*)d_in[14];
    const float* ln2_b     = (const float*)d_in[15];
    const float* W1        = (const float*)d_in[16];
    const float* b1        = (const float*)d_in[17];
    const float* W2        = (const float*)d_in[18];
    const float* b2        = (const float*)d_in[19];
    const float* head_w    = (const float*)d_in[20];
    float* out = (float*)d_out;

    float *x, *q, *k, *v, *dists, *attout, *cnt;
    int* idxb;
    __nv_bfloat16 *hh, *hl, *th, *tl, *aoh, *aol;
    __nv_bfloat16 *Wqh, *Wql, *Wkh, *Wkl, *Wvh, *Wvl, *Woh, *Wol, *W1h, *W1l, *W2h, *W2l;
    cudaGetSymbolAddress((void**)&x, g_x);
    cudaGetSymbolAddress((void**)&q, g_q);
    cudaGetSymbolAddress((void**)&k, g_k);
    cudaGetSymbolAddress((void**)&v, g_v);
    cudaGetSymbolAddress((void**)&dists, g_dists);
    cudaGetSymbolAddress((void**)&idxb, g_idx);
    cudaGetSymbolAddress((void**)&attout, g_attout);
    cudaGetSymbolAddress((void**)&cnt, g_cnt);
    cudaGetSymbolAddress((void**)&hh, g_hh);   cudaGetSymbolAddress((void**)&hl, g_hl);
    cudaGetSymbolAddress((void**)&th, g_th);   cudaGetSymbolAddress((void**)&tl, g_tl);
    cudaGetSymbolAddress((void**)&aoh, g_aoh); cudaGetSymbolAddress((void**)&aol, g_aol);
    cudaGetSymbolAddress((void**)&Wqh, g_Wqh); cudaGetSymbolAddress((void**)&Wql, g_Wql);
    cudaGetSymbolAddress((void**)&Wkh, g_Wkh); cudaGetSymbolAddress((void**)&Wkl, g_Wkl);
    cudaGetSymbolAddress((void**)&Wvh, g_Wvh); cudaGetSymbolAddress((void**)&Wvl, g_Wvl);
    cudaGetSymbolAddress((void**)&Woh, g_Woh); cudaGetSymbolAddress((void**)&Wol, g_Wol);
    cudaGetSymbolAddress((void**)&W1h, g_W1h); cudaGetSymbolAddress((void**)&W1l, g_W1l);
    cudaGetSymbolAddress((void**)&W2h, g_W2h); cudaGetSymbolAddress((void**)&W2l, g_W2l);

    const int ATTN_SMEM = 4 * 64 * 65 * (int)sizeof(float);
    cudaFuncSetAttribute(bucket_attn_kernel, cudaFuncAttributeMaxDynamicSharedMemorySize, ATTN_SMEM);
    const int DIST_SMEM = (128*65 + 64*64 + 64 + 128) * (int)sizeof(float);
    cudaFuncSetAttribute(dist_kernel, cudaFuncAttributeMaxDynamicSharedMemorySize, DIST_SMEM);

    // weight splits (once per launch)
    const int nE = LL*EE*EE, nF = LL*EE*FF;
    split_kernel<<<nE/1024, 256>>>(Wq, Wqh, Wql, nE);
    split_kernel<<<nE/1024, 256>>>(Wk, Wkh, Wkl, nE);
    split_kernel<<<nE/1024, 256>>>(Wv, Wvh, Wvl, nE);
    split_kernel<<<nE/1024, 256>>>(Wo, Woh, Wol, nE);
    split_kernel<<<nF/1024, 256>>>(W1, W1h, W1l, nF);
    split_kernel<<<nF/1024, 256>>>(W2, W2h, W2l, nF);

    embed_kernel<<<MM, 128>>>(value, depth, pos, sos, tok_emb, depth_emb, pos_emb, x);

    dim3 gE(EE/128, MM/128);     // 4 x 128
    dim3 gF(FF/128, MM/128);     // 16 x 128
    dim3 gD(SS/128, BB*HH);      // 32 x 32

    for (int l = 0; l < LL; l++) {
        size_t oE = (size_t)l*EE*EE, oF = (size_t)l*EE*FF;
        const float* ml = means + (size_t)l*HH*CC*DD;

        ln_kernel<<<MM, 256>>>(x, ln1_s + l*EE, ln1_b + l*EE, hh, hl);
        bf3_gemm<0,0,false><<<gE, 256>>>(hh, hl, Wqh+oE, Wql+oE, nullptr, q, nullptr, nullptr, MM, EE, EE);
        bf3_gemm<0,0,false><<<gE, 256>>>(hh, hl, Wkh+oE, Wkl+oE, nullptr, k, nullptr, nullptr, MM, EE, EE);
        bf3_gemm<0,0,false><<<gE, 256>>>(hh, hl, Wvh+oE, Wvl+oE, nullptr, v, nullptr, nullptr, MM, EE, EE);

        dist_kernel<<<gD, 256, DIST_SMEM>>>(q, ml, dists);
        topk_kernel<<<BB*HH*CC, 256>>>(dists, idxb);

        cudaMemsetAsync(attout, 0, (size_t)MM*EE*sizeof(float));
        cudaMemsetAsync(cnt, 0, (size_t)MM*HH*sizeof(float));
        bucket_attn_kernel<<<BB*HH*CC, 256, ATTN_SMEM>>>(q, k, v, value, idxb, attout, cnt);
        norm_attout_kernel<<<(MM*EE)/256, 256>>>(attout, cnt, aoh, aol);

        bf3_gemm<0,1,false><<<gE, 256>>>(aoh, aol, Woh+oE, Wol+oE, nullptr, x, nullptr, nullptr, MM, EE, EE);

        ln_kernel<<<MM, 256>>>(x, ln2_s + l*EE, ln2_b + l*EE, hh, hl);
        bf3_gemm<1,2,true><<<gF, 256>>>(hh, hl, W1h+oF, W1l+oF, b1 + l*FF, nullptr, th, tl, MM, FF, EE);
        bf3_gemm<0,1,true><<<gE, 256>>>(th, tl, W2h+oF, W2l+oF, b2 + l*EE, x, nullptr, nullptr, MM, EE, FF);
    }

    head_kernel<<<MM/8, 256>>>(x, head_w, out);
}

// round 5
// speedup vs baseline: 2.4302x; 1.0697x over previous
#include <cuda_runtime.h>
#include <cuda_bf16.h>
#include <math.h>
#include <stdint.h>

// ---------------- problem constants ----------------
#define BB 4
#define SS 4096
#define EE 512
#define HH 8
#define LL 4
#define AA 3
#define WIN 64
#define CC 64           // S / WIN clusters
#define DD 64           // E / H
#define MM (BB*SS)      // 16384 rows
#define FF (4*EE)       // 2048 ffn dim
#define QKS (3*EE)      // fused qkv row stride 1536
#define NVOC 17

// ---------------- scratch (device globals; no allocation allowed) ----------------
__device__ float g_x[MM*EE];
__device__ float g_qkv[MM*QKS];
__device__ float g_dists[BB*HH*CC*SS];
__device__ int   g_idx[BB*HH*CC*WIN];
__device__ float g_attout[MM*EE];
__device__ float g_cnt[MM*HH];
// split activations
__device__ __nv_bfloat16 g_hh[MM*EE],  g_hl[MM*EE];
__device__ __nv_bfloat16 g_th[MM*FF],  g_tl[MM*FF];
__device__ __nv_bfloat16 g_aoh[MM*EE], g_aol[MM*EE];
// split weights
__device__ __nv_bfloat16 g_Wqkvh[LL*EE*QKS], g_Wqkvl[LL*EE*QKS];
__device__ __nv_bfloat16 g_Woh[LL*EE*EE], g_Wol[LL*EE*EE];
__device__ __nv_bfloat16 g_W1h[LL*EE*FF], g_W1l[LL*EE*FF];
__device__ __nv_bfloat16 g_W2h[LL*FF*EE], g_W2l[LL*FF*EE];

// ---------------- bf16 split helpers ----------------
__device__ __forceinline__ uint32_t packbf(float x, float y) {
    __nv_bfloat162 t = __floats2bfloat162_rn(x, y);
    return *reinterpret_cast<uint32_t*>(&t);
}
__device__ __forceinline__ void split2(float x, float y, uint32_t& hi, uint32_t& lo) {
    float xh = __bfloat162float(__float2bfloat16(x));
    float yh = __bfloat162float(__float2bfloat16(y));
    hi = packbf(x, y);
    lo = packbf(x - xh, y - yh);
}
__device__ __forceinline__ void split1(float x, __nv_bfloat16& h, __nv_bfloat16& l) {
    h = __float2bfloat16(x);
    l = __float2bfloat16(x - __bfloat162float(h));
}

// ---------------- weight split prep ----------------
__global__ void split_kernel(const float* __restrict__ s, __nv_bfloat16* __restrict__ dh,
                             __nv_bfloat16* __restrict__ dl, int n) {
    int i = (blockIdx.x*256 + threadIdx.x)*4;
    if (i >= n) return;
    float4 v = *(const float4*)(s + i);
    uint32_t hA, lA, hB, lB;
    split2(v.x, v.y, hA, lA);
    split2(v.z, v.w, hB, lB);
    *(uint2*)(dh + i) = make_uint2(hA, hB);
    *(uint2*)(dl + i) = make_uint2(lA, lB);
}

// concat Wq|Wk|Wv into [EE, 1536] per layer, split to bf16 hi/lo
__global__ void split_qkv_kernel(const float* __restrict__ Wq, const float* __restrict__ Wk,
                                 const float* __restrict__ Wv,
                                 __nv_bfloat16* __restrict__ dh, __nv_bfloat16* __restrict__ dl) {
    int gid = blockIdx.x*256 + threadIdx.x;          // over LL*EE*QKS/4
    int i = gid*4;
    if (i >= LL*EE*QKS) return;
    int c = i % QKS;
    int r = (i / QKS) % EE;
    int l = i / (QKS*EE);
    const float* src;
    int cc = c;
    if (c < EE) src = Wq;
    else if (c < 2*EE) { src = Wk; cc = c - EE; }
    else { src = Wv; cc = c - 2*EE; }
    float4 v = *(const float4*)(src + ((size_t)l*EE + r)*EE + cc);
    uint32_t hA, lA, hB, lB;
    split2(v.x, v.y, hA, lA);
    split2(v.z, v.w, hB, lB);
    *(uint2*)(dh + i) = make_uint2(hA, hB);
    *(uint2*)(dl + i) = make_uint2(lA, lB);
}

// ---------------- embedding + shift-right ----------------
__global__ void embed_kernel(const int* __restrict__ value, const int* __restrict__ depth,
                             const int* __restrict__ pos, const float* __restrict__ sos,
                             const float* __restrict__ tok, const float* __restrict__ dep,
                             const float* __restrict__ pemb, float* __restrict__ x) {
    int row = blockIdx.x;
    int t = row & (SS - 1);
    if (t == 0) {
        for (int e = threadIdx.x; e < EE; e += blockDim.x) x[(size_t)row*EE + e] = sos[e];
        return;
    }
    int pr = row - 1;
    int v  = value[pr], dp = depth[pr];
    int p0 = pos[pr*AA+0], p1 = pos[pr*AA+1], p2 = pos[pr*AA+2];
    for (int e = threadIdx.x; e < EE; e += blockDim.x) {
        float s = tok[v*EE+e] + dep[dp*EE+e]
                + pemb[(0*65 + p0)*EE + e]
                + pemb[(1*65 + p1)*EE + e]
                + pemb[(2*65 + p2)*EE + e];
        x[(size_t)row*EE + e] = s;
    }
}

// ---------------- layernorm -> split bf16 output ----------------
__global__ void ln_kernel(const float* __restrict__ x, const float* __restrict__ sc,
                          const float* __restrict__ bi,
                          __nv_bfloat16* __restrict__ oh, __nv_bfloat16* __restrict__ ol) {
    int row = blockIdx.x;
    int tid = threadIdx.x;
    const float* xr = x + (size_t)row*EE;
    float v0 = xr[tid], v1 = xr[tid + 256];
    __shared__ float rs[256], rq[256];
    rs[tid] = v0 + v1;
    rq[tid] = v0*v0 + v1*v1;
    __syncthreads();
    for (int off = 128; off > 0; off >>= 1) {
        if (tid < off) { rs[tid] += rs[tid+off]; rq[tid] += rq[tid+off]; }
        __syncthreads();
    }
    __shared__ float s_m, s_r;
    if (tid == 0) {
        float m = rs[0] * (1.0f/EE);
        float var = rq[0] * (1.0f/EE) - m*m;
        s_m = m; s_r = rsqrtf(var + 1e-5f);
    }
    __syncthreads();
    float m = s_m, r = s_r;
    float y0 = (v0 - m)*r*sc[tid]       + bi[tid];
    float y1 = (v1 - m)*r*sc[tid + 256] + bi[tid + 256];
    __nv_bfloat16 h, l;
    split1(y0, h, l); oh[(size_t)row*EE + tid] = h;       ol[(size_t)row*EE + tid] = l;
    split1(y1, h, l); oh[(size_t)row*EE + tid + 256] = h; ol[(size_t)row*EE + tid + 256] = l;
}

// ---------------- gelu ----------------
__device__ __forceinline__ float gelu_f(float x) {
    float x3 = x*x*x;
    return 0.5f*x*(1.0f + tanhf(0.7978845608028654f*(x + 0.044715f*x3)));
}

__device__ __forceinline__ void mma_bf16(float d[4], const uint32_t a[4], const uint32_t b[2]) {
    asm volatile(
        "mma.sync.aligned.m16n8k16.row.col.f32.bf16.bf16.f32 "
        "{%0,%1,%2,%3}, {%4,%5,%6,%7}, {%8,%9}, {%0,%1,%2,%3};\n"
        : "+f"(d[0]), "+f"(d[1]), "+f"(d[2]), "+f"(d[3])
        : "r"(a[0]), "r"(a[1]), "r"(a[2]), "r"(a[3]), "r"(b[0]), "r"(b[1]));
}

__device__ __forceinline__ void ldsm4(uint32_t f[4], uint32_t smaddr) {
    asm volatile("ldmatrix.sync.aligned.m8n8.x4.shared.b16 {%0,%1,%2,%3}, [%4];"
                 : "=r"(f[0]), "=r"(f[1]), "=r"(f[2]), "=r"(f[3]) : "r"(smaddr));
}

// ---------------- split-bf16 tensor GEMM, pre-split operands, ldmatrix A frags ----------------
// BM=BN=128, BK=16, 256 threads = 8 warps (2x4), warp tile 64x32, m16n8k16.
// OUTMODE: 0=store f32, 1=accum f32, 2=split bf16 store
#define AST 12
#define BST 136
template<int ACT, int OUTMODE, bool HASB>
__global__ void __launch_bounds__(256,2) bf3_gemm(
    const __nv_bfloat16* __restrict__ Ah, const __nv_bfloat16* __restrict__ Al,
    const __nv_bfloat16* __restrict__ Bh, const __nv_bfloat16* __restrict__ Bl,
    const float* __restrict__ bias,
    float* __restrict__ C,
    __nv_bfloat16* __restrict__ Ch, __nv_bfloat16* __restrict__ Cl,
    int M, int N, int K)
{
    __shared__ uint32_t AsH[2][128*AST];
    __shared__ uint32_t AsL[2][128*AST];
    __shared__ uint32_t BsH[2][8*BST];
    __shared__ uint32_t BsL[2][8*BST];
    int tid = threadIdx.x;
    int lane = tid & 31;
    int warp = tid >> 5;
    int wm = (warp >> 2) * 64;
    int wn = (warp & 3) * 32;
    int bm = blockIdx.y * 128, bn = blockIdx.x * 128;

    float acc[4][4][4];
#pragma unroll
    for (int mi = 0; mi < 4; mi++)
#pragma unroll
        for (int ni = 0; ni < 4; ni++)
#pragma unroll
            for (int r = 0; r < 4; r++) acc[mi][ni][r] = 0.0f;

    int a_r = tid >> 1, a_h = (tid & 1) * 8;
    int b_p = tid >> 5, b_cg = (tid & 31) * 4;
    const __nv_bfloat16* Abh = Ah + (size_t)bm * K;
    const __nv_bfloat16* Abl = Al + (size_t)bm * K;
    const __nv_bfloat16* Bbh = Bh + bn;
    const __nv_bfloat16* Bbl = Bl + bn;

    uint4 pAh, pAl;
    uint2 r0h, r1h, r0l, r1l;
    int nk = K / 16;

#define LOAD_AB(K0)                                                       \
    {                                                                     \
        pAh = *(const uint4*)(Abh + (size_t)a_r*K + (K0) + a_h);          \
        pAl = *(const uint4*)(Abl + (size_t)a_r*K + (K0) + a_h);          \
        const __nv_bfloat16* bp = Bbh + (size_t)((K0) + 2*b_p)*N + b_cg;  \
        r0h = *(const uint2*)bp;  r1h = *(const uint2*)(bp + N);          \
        const __nv_bfloat16* bq = Bbl + (size_t)((K0) + 2*b_p)*N + b_cg;  \
        r0l = *(const uint2*)bq;  r1l = *(const uint2*)(bq + N);          \
    }

#define STORE_AB(BUF)                                                     \
    {                                                                     \
        *(uint4*)&AsH[BUF][a_r*AST + (a_h>>1)] = pAh;                     \
        *(uint4*)&AsL[BUF][a_r*AST + (a_h>>1)] = pAl;                     \
        uint32_t q0 = __byte_perm(r0h.x, r1h.x, 0x5410);                  \
        uint32_t q1 = __byte_perm(r0h.x, r1h.x, 0x7632);                  \
        uint32_t q2 = __byte_perm(r0h.y, r1h.y, 0x5410);                  \
        uint32_t q3 = __byte_perm(r0h.y, r1h.y, 0x7632);                  \
        *(uint4*)&BsH[BUF][b_p*BST + b_cg] = make_uint4(q0,q1,q2,q3);     \
        q0 = __byte_perm(r0l.x, r1l.x, 0x5410);                           \
        q1 = __byte_perm(r0l.x, r1l.x, 0x7632);                           \
        q2 = __byte_perm(r0l.y, r1l.y, 0x5410);                           \
        q3 = __byte_perm(r0l.y, r1l.y, 0x7632);                           \
        *(uint4*)&BsL[BUF][b_p*BST + b_cg] = make_uint4(q0,q1,q2,q3);     \
    }

    LOAD_AB(0)
    STORE_AB(0)
    __syncthreads();

    // ldmatrix lane address (A frags): mat0 rows0-7 k0-7, mat1 rows8-15 k0-7,
    // mat2 rows0-7 k8-15, mat3 rows8-15 k8-15
    int l_row = wm + (lane & 7) + ((lane >> 3) & 1) * 8;
    int l_kp  = ((lane >> 4) & 1) * 4;
    uint32_t aoff = (uint32_t)((l_row * AST + l_kp) * 4);
    uint32_t asHbase = (uint32_t)__cvta_generic_to_shared(&AsH[0][0]);
    uint32_t asLbase = (uint32_t)__cvta_generic_to_shared(&AsL[0][0]);

    int bc0 = wn + (lane >> 2);
    int bp0 = lane & 3;

    for (int it = 0; it < nk; it++) {
        int buf = it & 1;
        uint32_t afh[4][4], afl[4][4], bfh[4][2], bfl[4][2];
        uint32_t abufH = asHbase + (uint32_t)buf*(128*AST*4) + aoff;
        uint32_t abufL = asLbase + (uint32_t)buf*(128*AST*4) + aoff;
#pragma unroll
        for (int mi = 0; mi < 4; mi++) {
            ldsm4(afh[mi], abufH + (uint32_t)(mi*16*AST*4));
            ldsm4(afl[mi], abufL + (uint32_t)(mi*16*AST*4));
        }
#pragma unroll
        for (int ni = 0; ni < 4; ni++) {
            int base = bp0*BST + bc0 + ni*8;
            bfh[ni][0] = BsH[buf][base];
            bfh[ni][1] = BsH[buf][base + 4*BST];
            bfl[ni][0] = BsL[buf][base];
            bfl[ni][1] = BsL[buf][base + 4*BST];
        }
        if (it + 1 < nk) {
            LOAD_AB((it + 1) * 16)
            STORE_AB(buf ^ 1)
        }
        __syncthreads();
#pragma unroll
        for (int mi = 0; mi < 4; mi++)
#pragma unroll
            for (int ni = 0; ni < 4; ni++) {
                mma_bf16(acc[mi][ni], afl[mi], bfh[ni]);
                mma_bf16(acc[mi][ni], afh[mi], bfl[ni]);
                mma_bf16(acc[mi][ni], afh[mi], bfh[ni]);
            }
    }

#pragma unroll
    for (int mi = 0; mi < 4; mi++) {
        int r0 = bm + wm + mi*16 + (lane >> 2);
#pragma unroll
        for (int ni = 0; ni < 4; ni++) {
            int c0 = bn + wn + ni*8 + (lane & 3)*2;
            float* a = acc[mi][ni];
#pragma unroll
            for (int hr = 0; hr < 2; hr++) {
                int r = r0 + hr*8;
                float v0 = a[hr*2 + 0], v1 = a[hr*2 + 1];
                if (HASB) { v0 += bias[c0]; v1 += bias[c0+1]; }
                if (ACT == 1) { v0 = gelu_f(v0); v1 = gelu_f(v1); }
                size_t o = (size_t)r*N + c0;
                if (OUTMODE == 0) {
                    float2 t2; t2.x = v0; t2.y = v1;
                    *(float2*)&C[o] = t2;
                } else if (OUTMODE == 1) {
                    float2 old = *(float2*)&C[o];
                    old.x += v0; old.y += v1;
                    *(float2*)&C[o] = old;
                } else {
                    uint32_t hh2, ll2;
                    split2(v0, v1, hh2, ll2);
                    *(uint32_t*)&Ch[o] = hh2;
                    *(uint32_t*)&Cl[o] = ll2;
                }
            }
        }
    }
}

// ---------------- fused qnorm + cluster distances (tiled; q has QKS stride) ----------------
__global__ void dist_kernel(const float* __restrict__ q, const float* __restrict__ means_l,
                            float* __restrict__ dists) {
    extern __shared__ float dsm[];
    float* qs = dsm;             // 128*65
    float* ms = qs + 128*65;     // 64*64
    float* mn = ms + 64*64;      // 64
    float* qn = mn + 64;         // 128
    int tile = blockIdx.x;
    int bh = blockIdx.y;
    int h = bh & 7, b = bh >> 3;
    int n0 = tile * 128;
    int tid = threadIdx.x;
    for (int i = tid; i < 64*64; i += 256) ms[i] = means_l[h*64*64 + i];
    for (int i = tid; i < 128*16; i += 256) {
        int r = i >> 4, c4 = (i & 15) * 4;
        float4 v = *(const float4*)(q + ((size_t)(b*SS + n0 + r))*QKS + h*DD + c4);
        float* dst = qs + r*65 + c4;
        dst[0]=v.x; dst[1]=v.y; dst[2]=v.z; dst[3]=v.w;
    }
    __syncthreads();
    if (tid < 64) {
        float s = 0; const float* mr = ms + tid*64;
#pragma unroll 16
        for (int d = 0; d < 64; d++) s += mr[d]*mr[d];
        mn[tid] = 1.0f/(sqrtf(s) + 1e-8f);
    } else if (tid >= 128) {
        int r = tid - 128;
        float s = 0; const float* qr = qs + r*65;
#pragma unroll 16
        for (int d = 0; d < 64; d++) s += qr[d]*qr[d];
        qn[r] = 1.0f/(sqrtf(s) + 1e-8f);
    }
    __syncthreads();
    int nl = tid & 127;
    int c0 = (tid >> 7) * 32;
    float acc[32];
#pragma unroll
    for (int c = 0; c < 32; c++) acc[c] = 0.0f;
    for (int dc = 0; dc < 64; dc += 16) {
        float qreg[16];
#pragma unroll
        for (int d = 0; d < 16; d++) qreg[d] = qs[nl*65 + dc + d];
#pragma unroll
        for (int c = 0; c < 32; c++) {
            const float* mr = ms + (c0 + c)*64 + dc;
            float s = acc[c];
#pragma unroll
            for (int d = 0; d < 16; d++) s += qreg[d]*mr[d];
            acc[c] = s;
        }
    }
    float qi = qn[nl];
#pragma unroll
    for (int c = 0; c < 32; c++) {
        int cc = c0 + c;
        dists[((size_t)bh*CC + cc)*SS + n0 + nl] = acc[c]*mn[cc]*qi;
    }
}

// ---------------- radix-select top-64 (exact, ties -> smallest index) ----------------
__global__ void topk_kernel(const float* __restrict__ dists, int* __restrict__ idxout) {
    __shared__ uint32_t keys[SS];
    __shared__ int hist[256];
    __shared__ int ties[SS];
    __shared__ int rmin[256];
    __shared__ int s_chosen, s_rem, s_cntgt, s_ntie, s_pick;
    int blk = blockIdx.x, tid = threadIdx.x;
    const float* drow = dists + (size_t)blk*SS;
    for (int n = tid; n < SS; n += 256) {
        uint32_t u = __float_as_uint(drow[n]);
        keys[n] = (u & 0x80000000u) ? ~u : (u | 0x80000000u);
    }
    uint32_t prefix = 0, maskhi = 0;
    int rem = WIN;
    for (int p = 0; p < 4; p++) {
        int shift = 24 - 8*p;
        hist[tid] = 0;
        __syncthreads();
        for (int n = tid; n < SS; n += 256) {
            uint32_t kk = keys[n];
            if ((kk & maskhi) == prefix) atomicAdd(&hist[(kk >> shift) & 255], 1);
        }
        __syncthreads();
        if (tid == 0) {
            int cum = 0, bsel = 255;
            for (; bsel >= 0; bsel--) { cum += hist[bsel]; if (cum >= rem) break; }
            s_chosen = bsel; s_rem = rem - (cum - hist[bsel]);
        }
        __syncthreads();
        prefix |= ((uint32_t)s_chosen) << shift;
        maskhi |= 0xFFu << shift;
        rem = s_rem;
        __syncthreads();
    }
    uint32_t T = prefix;
    if (tid == 0) { s_cntgt = 0; s_ntie = 0; }
    __syncthreads();
    int* orow = idxout + blk*WIN;
    for (int n = tid; n < SS; n += 256) {
        uint32_t kk = keys[n];
        if (kk > T) { int pp = atomicAdd(&s_cntgt, 1); orow[pp] = n; }
        else if (kk == T) { int pp = atomicAdd(&s_ntie, 1); ties[pp] = n; }
    }
    __syncthreads();
    int cntgt = s_cntgt;
    int need = WIN - cntgt;
    int ntie = s_ntie;
    if (need > 0) {
        if (need == ntie) {
            for (int j = tid; j < need; j += 256) orow[cntgt + j] = ties[j];
        } else {
            int last = -1;
            for (int j = 0; j < need; j++) {
                int mymin = 0x7FFFFFFF;
                for (int t2 = tid; t2 < ntie; t2 += 256) {
                    int vv = ties[t2];
                    if (vv > last && vv < mymin) mymin = vv;
                }
                rmin[tid] = mymin;
                __syncthreads();
                for (int off = 128; off; off >>= 1) {
                    if (tid < off) rmin[tid] = min(rmin[tid], rmin[tid+off]);
                    __syncthreads();
                }
                if (tid == 0) { orow[cntgt + j] = rmin[0]; s_pick = rmin[0]; }
                __syncthreads();
                last = s_pick;
            }
        }
    }
}

// ---------------- bucket attention (register-tiled 4x4; q/k/v strided QKS) ----------------
__global__ void bucket_attn_kernel(const float* __restrict__ q, const float* __restrict__ k,
                                   const float* __restrict__ v, const int* __restrict__ value,
                                   const int* __restrict__ idxin, float* __restrict__ attout,
                                   float* __restrict__ cnt) {
    extern __shared__ float sm[];
    float* qb = sm;
    float* kb = qb + 64*65;
    float* vb = kb + 64*65;
    float* sc = vb + 64*65;
    __shared__ int idxs[64];
    __shared__ int kms[64];
    int blk = blockIdx.x;
    int bh = blk / CC; int h = bh % HH; int b = bh / HH;
    int tid = threadIdx.x;
    if (tid < 64) {
        int t = idxin[blk*WIN + tid];
        idxs[tid] = t;
        kms[tid] = (value[b*SS + t] != 0);
    }
    __syncthreads();
    for (int i = tid; i < 64*64; i += 256) {
        int w = i >> 6, d = i & 63;
        size_t base = ((size_t)(b*SS + idxs[w]))*QKS + h*DD + d;
        qb[w*65 + d] = q[base];
        kb[w*65 + d] = k[base];
        vb[w*65 + d] = v[base];
    }
    __syncthreads();
    int tw = (tid >> 4) * 4;           // 4 query rows
    int tx = (tid & 15) * 4;           // 4 key cols
    float a2[4][4];
#pragma unroll
    for (int i = 0; i < 4; i++)
#pragma unroll
        for (int j = 0; j < 4; j++) a2[i][j] = 0.0f;
    for (int kk = 0; kk < 64; kk++) {
        float qv[4], kv[4];
#pragma unroll
        for (int i = 0; i < 4; i++) qv[i] = qb[(tw+i)*65 + kk];
#pragma unroll
        for (int j = 0; j < 4; j++) kv[j] = kb[(tx+j)*65 + kk];
#pragma unroll
        for (int i = 0; i < 4; i++)
#pragma unroll
            for (int j = 0; j < 4; j++) a2[i][j] += qv[i]*kv[j];
    }
#pragma unroll
    for (int i = 0; i < 4; i++)
#pragma unroll
        for (int j = 0; j < 4; j++) {
            bool allowed = (idxs[tw+i] >= idxs[tx+j]) && kms[tx+j];
            sc[(tw+i)*65 + tx+j] = allowed ? a2[i][j]*0.125f : -1e9f;
        }
    __syncthreads();
    if (tid < 64) {
        float mx = -INFINITY;
        for (int xx = 0; xx < 64; xx++) mx = fmaxf(mx, sc[tid*65+xx]);
        float sum = 0.0f;
        for (int xx = 0; xx < 64; xx++) { float e = expf(sc[tid*65+xx]-mx); sc[tid*65+xx] = e; sum += e; }
        float inv = 1.0f/sum;
        for (int xx = 0; xx < 64; xx++) sc[tid*65+xx] *= inv;
    }
    __syncthreads();
    float o2[4][4];
#pragma unroll
    for (int i = 0; i < 4; i++)
#pragma unroll
        for (int j = 0; j < 4; j++) o2[i][j] = 0.0f;
    for (int xx = 0; xx < 64; xx++) {
        float sv[4], vv[4];
#pragma unroll
        for (int i = 0; i < 4; i++) sv[i] = sc[(tw+i)*65 + xx];
#pragma unroll
        for (int j = 0; j < 4; j++) vv[j] = vb[xx*65 + tx+j];
#pragma unroll
        for (int i = 0; i < 4; i++)
#pragma unroll
            for (int j = 0; j < 4; j++) o2[i][j] += sv[i]*vv[j];
    }
#pragma unroll
    for (int i = 0; i < 4; i++)
#pragma unroll
        for (int j = 0; j < 4; j++)
            atomicAdd(&attout[((size_t)(b*SS + idxs[tw+i]))*EE + h*DD + tx+j], o2[i][j]);
    if (tid < 64) atomicAdd(&cnt[(size_t)(b*SS + idxs[tid])*HH + h], 1.0f);
}

// ---------------- scatter-mean normalization -> split bf16 ----------------
__global__ void norm_attout_kernel(const float* __restrict__ attout, const float* __restrict__ cnt,
                                   __nv_bfloat16* __restrict__ oh, __nv_bfloat16* __restrict__ ol) {
    int i = blockIdx.x*256 + threadIdx.x;
    int row = i >> 9;
    int h = (i & 511) >> 6;
    float c = cnt[(size_t)row*HH + h];
    float val = attout[i] / fmaxf(c, 1.0f);
    __nv_bfloat16 hh2, ll2;
    split1(val, hh2, ll2);
    oh[i] = hh2; ol[i] = ll2;
}

// ---------------- head: logits = x @ head_w.T  (N=17), warp per row ----------------
__global__ void head_kernel(const float* __restrict__ x, const float* __restrict__ hw,
                            float* __restrict__ out) {
    int gw = (blockIdx.x*256 + threadIdx.x) >> 5;
    int lane = threadIdx.x & 31;
    if (gw >= MM) return;
    const float* xp = x + (size_t)gw*EE;
    float xr[16];
#pragma unroll
    for (int i = 0; i < 16; i++) xr[i] = xp[lane + i*32];
    for (int o = 0; o < NVOC; o++) {
        const float* w = hw + o*EE;
        float s = 0.0f;
#pragma unroll
        for (int i = 0; i < 16; i++) s += xr[i]*w[lane + i*32];
#pragma unroll
        for (int off = 16; off; off >>= 1) s += __shfl_xor_sync(0xffffffffu, s, off);
        if (lane == 0) out[(size_t)gw*NVOC + o] = s;
    }
}

// ---------------- host orchestration ----------------
extern "C" void kernel_launch(void* const* d_in, const int* in_sizes, int n_in,
                              void* d_out, int out_size) {
    const int*   value     = (const int*)d_in[0];
    const int*   depth     = (const int*)d_in[1];
    const int*   pos       = (const int*)d_in[2];
    const float* sos       = (const float*)d_in[3];
    const float* tok_emb   = (const float*)d_in[4];
    const float* depth_emb = (const float*)d_in[5];
    const float* pos_emb   = (const float*)d_in[6];
    const float* ln1_s     = (const float*)d_in[7];
    const float* ln1_b     = (const float*)d_in[8];
    const float* Wq        = (const float*)d_in[9];
    const float* Wk        = (const float*)d_in[10];
    const float* Wv        = (const float*)d_in[11];
    const float* Wo        = (const float*)d_in[12];
    const float* means     = (const float*)d_in[13];
    const float* ln2_s     = (const float*)d_in[14];
    const float* ln2_b     = (const float*)d_in[15];
    const float* W1        = (const float*)d_in[16];
    const float* b1        = (const float*)d_in[17];
    const float* W2        = (const float*)d_in[18];
    const float* b2        = (const float*)d_in[19];
    const float* head_w    = (const float*)d_in[20];
    float* out = (float*)d_out;

    float *x, *qkv, *dists, *attout, *cnt;
    int* idxb;
    __nv_bfloat16 *hh, *hl, *th, *tl, *aoh, *aol;
    __nv_bfloat16 *Wqkvh, *Wqkvl, *Woh, *Wol, *W1h, *W1l, *W2h, *W2l;
    cudaGetSymbolAddress((void**)&x, g_x);
    cudaGetSymbolAddress((void**)&qkv, g_qkv);
    cudaGetSymbolAddress((void**)&dists, g_dists);
    cudaGetSymbolAddress((void**)&idxb, g_idx);
    cudaGetSymbolAddress((void**)&attout, g_attout);
    cudaGetSymbolAddress((void**)&cnt, g_cnt);
    cudaGetSymbolAddress((void**)&hh, g_hh);   cudaGetSymbolAddress((void**)&hl, g_hl);
    cudaGetSymbolAddress((void**)&th, g_th);   cudaGetSymbolAddress((void**)&tl, g_tl);
    cudaGetSymbolAddress((void**)&aoh, g_aoh); cudaGetSymbolAddress((void**)&aol, g_aol);
    cudaGetSymbolAddress((void**)&Wqkvh, g_Wqkvh); cudaGetSymbolAddress((void**)&Wqkvl, g_Wqkvl);
    cudaGetSymbolAddress((void**)&Woh, g_Woh); cudaGetSymbolAddress((void**)&Wol, g_Wol);
    cudaGetSymbolAddress((void**)&W1h, g_W1h); cudaGetSymbolAddress((void**)&W1l, g_W1l);
    cudaGetSymbolAddress((void**)&W2h, g_W2h); cudaGetSymbolAddress((void**)&W2l, g_W2l);

    const int ATTN_SMEM = 4 * 64 * 65 * (int)sizeof(float);
    cudaFuncSetAttribute(bucket_attn_kernel, cudaFuncAttributeMaxDynamicSharedMemorySize, ATTN_SMEM);
    const int DIST_SMEM = (128*65 + 64*64 + 64 + 128) * (int)sizeof(float);
    cudaFuncSetAttribute(dist_kernel, cudaFuncAttributeMaxDynamicSharedMemorySize, DIST_SMEM);

    // weight splits (once per launch)
    const int nE = LL*EE*EE, nF = LL*EE*FF, nQKV = LL*EE*QKS;
    split_qkv_kernel<<<nQKV/1024, 256>>>(Wq, Wk, Wv, Wqkvh, Wqkvl);
    split_kernel<<<nE/1024, 256>>>(Wo, Woh, Wol, nE);
    split_kernel<<<nF/1024, 256>>>(W1, W1h, W1l, nF);
    split_kernel<<<nF/1024, 256>>>(W2, W2h, W2l, nF);

    embed_kernel<<<MM, 128>>>(value, depth, pos, sos, tok_emb, depth_emb, pos_emb, x);

    dim3 gE(EE/128, MM/128);     // 4 x 128
    dim3 gQ(QKS/128, MM/128);    // 12 x 128
    dim3 gF(FF/128, MM/128);     // 16 x 128
    dim3 gD(SS/128, BB*HH);      // 32 x 32

    for (int l = 0; l < LL; l++) {
        size_t oQ = (size_t)l*EE*QKS, oE = (size_t)l*EE*EE, oF = (size_t)l*EE*FF;
        const float* ml = means + (size_t)l*HH*CC*DD;
        float* q = qkv;
        float* k = qkv + EE;
        float* v = qkv + 2*EE;

        ln_kernel<<<MM, 256>>>(x, ln1_s + l*EE, ln1_b + l*EE, hh, hl);
        bf3_gemm<0,0,false><<<gQ, 256>>>(hh, hl, Wqkvh+oQ, Wqkvl+oQ, nullptr, qkv, nullptr, nullptr, MM, QKS, EE);

        dist_kernel<<<gD, 256, DIST_SMEM>>>(q, ml, dists);
        topk_kernel<<<BB*HH*CC, 256>>>(dists, idxb);

        cudaMemsetAsync(attout, 0, (size_t)MM*EE*sizeof(float));
        cudaMemsetAsync(cnt, 0, (size_t)MM*HH*sizeof(float));
        bucket_attn_kernel<<<BB*HH*CC, 256, ATTN_SMEM>>>(q, k, v, value, idxb, attout, cnt);
        norm_attout_kernel<<<(MM*EE)/256, 256>>>(attout, cnt, aoh, aol);

        bf3_gemm<0,1,false><<<gE, 256>>>(aoh, aol, Woh+oE, Wol+oE, nullptr, x, nullptr, nullptr, MM, EE, EE);

        ln_kernel<<<MM, 256>>>(x, ln2_s + l*EE, ln2_b + l*EE, hh, hl);
        bf3_gemm<1,2,true><<<gF, 256>>>(hh, hl, W1h+oF, W1l+oF, b1 + l*FF, nullptr, th, tl, MM, FF, EE);
        bf3_gemm<0,1,true><<<gE, 256>>>(th, tl, W2h+oF, W2l+oF, b2 + l*EE, x, nullptr, nullptr, MM, EE, FF);
    }

    head_kernel<<<MM/8, 256>>>(x, head_w, out);
}

// round 6
// speedup vs baseline: 2.8844x; 1.1869x over previous
#include <cuda_runtime.h>
#include <cuda_bf16.h>
#include <math.h>
#include <stdint.h>

// ---------------- problem constants ----------------
#define BB 4
#define SS 4096
#define EE 512
#define HH 8
#define LL 4
#define AA 3
#define WIN 64
#define CC 64           // S / WIN clusters
#define DD 64           // E / H
#define MM (BB*SS)      // 16384 rows
#define FF (4*EE)       // 2048 ffn dim
#define QKS (3*EE)      // fused qkv row stride 1536
#define NVOC 17

// ---------------- scratch (device globals; no allocation allowed) ----------------
__device__ float g_x[MM*EE];
__device__ float g_qkv[MM*QKS];
__device__ float g_dists[BB*HH*CC*SS];
__device__ int   g_idx[BB*HH*CC*WIN];
__device__ float g_attout[MM*EE];
__device__ float g_cnt[MM*HH];
// split activations (A operands)
__device__ __nv_bfloat16 g_hh[MM*EE],  g_hl[MM*EE];
__device__ __nv_bfloat16 g_th[MM*FF],  g_tl[MM*FF];
__device__ __nv_bfloat16 g_aoh[MM*EE], g_aol[MM*EE];
// split weights, pair-interleaved: uint32 [K/2][N] per layer (lo half = even k, hi half = odd k)
__device__ uint32_t g_Wqkvh[LL*(EE/2)*QKS], g_Wqkvl[LL*(EE/2)*QKS];
__device__ uint32_t g_Woh[LL*(EE/2)*EE],    g_Wol[LL*(EE/2)*EE];
__device__ uint32_t g_W1h[LL*(EE/2)*FF],    g_W1l[LL*(EE/2)*FF];
__device__ uint32_t g_W2h[LL*(FF/2)*EE],    g_W2l[LL*(FF/2)*EE];

// ---------------- bf16 split helpers ----------------
__device__ __forceinline__ uint32_t packbf(float x, float y) {
    __nv_bfloat162 t = __floats2bfloat162_rn(x, y);
    return *reinterpret_cast<uint32_t*>(&t);
}
__device__ __forceinline__ void split2(float x, float y, uint32_t& hi, uint32_t& lo) {
    float xh = __bfloat162float(__float2bfloat16(x));
    float yh = __bfloat162float(__float2bfloat16(y));
    hi = packbf(x, y);
    lo = packbf(x - xh, y - yh);
}
__device__ __forceinline__ void split1(float x, __nv_bfloat16& h, __nv_bfloat16& l) {
    h = __float2bfloat16(x);
    l = __float2bfloat16(x - __bfloat162float(h));
}

// ---------------- weight split prep (pair-interleaved) ----------------
// W: [LL][K][N] float. Output PI: [LL][K/2][N] uint32 = pack(W[2p][c], W[2p+1][c])
__global__ void split_pi_kernel(const float* __restrict__ W, uint32_t* __restrict__ PIh,
                                uint32_t* __restrict__ PIl, int K, int N, int n4total) {
    int gid = blockIdx.x*256 + threadIdx.x;
    if (gid >= n4total) return;
    int i = gid*4;                         // over LL*(K/2)*N
    int c = i % N;
    int rest = i / N;
    int p = rest % (K/2);
    int l = rest / (K/2);
    const float* w0 = W + ((size_t)l*K + 2*p)*N + c;
    float4 v0 = *(const float4*)w0;
    float4 v1 = *(const float4*)(w0 + N);
    uint32_t h0,l0,h1,l1,h2,l2,h3,l3;
    split2(v0.x, v1.x, h0, l0);
    split2(v0.y, v1.y, h1, l1);
    split2(v0.z, v1.z, h2, l2);
    split2(v0.w, v1.w, h3, l3);
    size_t o = ((size_t)l*(K/2) + p)*N + c;
    *(uint4*)(PIh + o) = make_uint4(h0,h1,h2,h3);
    *(uint4*)(PIl + o) = make_uint4(l0,l1,l2,l3);
}

// concat Wq|Wk|Wv into pair-interleaved [LL][EE/2][1536]
__global__ void split_qkv_pi_kernel(const float* __restrict__ Wq, const float* __restrict__ Wk,
                                    const float* __restrict__ Wv,
                                    uint32_t* __restrict__ PIh, uint32_t* __restrict__ PIl) {
    int gid = blockIdx.x*256 + threadIdx.x;
    int i = gid*4;                         // over LL*(EE/2)*QKS
    if (i >= LL*(EE/2)*QKS) return;
    int c = i % QKS;
    int rest = i / QKS;
    int p = rest % (EE/2);
    int l = rest / (EE/2);
    const float* src; int cc = c;
    if (c < EE) src = Wq;
    else if (c < 2*EE) { src = Wk; cc = c - EE; }
    else { src = Wv; cc = c - 2*EE; }
    const float* w0 = src + ((size_t)l*EE + 2*p)*EE + cc;
    float4 v0 = *(const float4*)w0;
    float4 v1 = *(const float4*)(w0 + EE);
    uint32_t h0,l0,h1,l1,h2,l2,h3,l3;
    split2(v0.x, v1.x, h0, l0);
    split2(v0.y, v1.y, h1, l1);
    split2(v0.z, v1.z, h2, l2);
    split2(v0.w, v1.w, h3, l3);
    size_t o = ((size_t)l*(EE/2) + p)*QKS + c;
    *(uint4*)(PIh + o) = make_uint4(h0,h1,h2,h3);
    *(uint4*)(PIl + o) = make_uint4(l0,l1,l2,l3);
}

// ---------------- embedding + shift-right ----------------
__global__ void embed_kernel(const int* __restrict__ value, const int* __restrict__ depth,
                             const int* __restrict__ pos, const float* __restrict__ sos,
                             const float* __restrict__ tok, const float* __restrict__ dep,
                             const float* __restrict__ pemb, float* __restrict__ x) {
    int row = blockIdx.x;
    int t = row & (SS - 1);
    if (t == 0) {
        for (int e = threadIdx.x; e < EE; e += blockDim.x) x[(size_t)row*EE + e] = sos[e];
        return;
    }
    int pr = row - 1;
    int v  = value[pr], dp = depth[pr];
    int p0 = pos[pr*AA+0], p1 = pos[pr*AA+1], p2 = pos[pr*AA+2];
    for (int e = threadIdx.x; e < EE; e += blockDim.x) {
        float s = tok[v*EE+e] + dep[dp*EE+e]
                + pemb[(0*65 + p0)*EE + e]
                + pemb[(1*65 + p1)*EE + e]
                + pemb[(2*65 + p2)*EE + e];
        x[(size_t)row*EE + e] = s;
    }
}

// ---------------- layernorm -> split bf16 output ----------------
__global__ void ln_kernel(const float* __restrict__ x, const float* __restrict__ sc,
                          const float* __restrict__ bi,
                          __nv_bfloat16* __restrict__ oh, __nv_bfloat16* __restrict__ ol) {
    int row = blockIdx.x;
    int tid = threadIdx.x;
    const float* xr = x + (size_t)row*EE;
    float v0 = xr[tid], v1 = xr[tid + 256];
    __shared__ float rs[256], rq[256];
    rs[tid] = v0 + v1;
    rq[tid] = v0*v0 + v1*v1;
    __syncthreads();
    for (int off = 128; off > 0; off >>= 1) {
        if (tid < off) { rs[tid] += rs[tid+off]; rq[tid] += rq[tid+off]; }
        __syncthreads();
    }
    __shared__ float s_m, s_r;
    if (tid == 0) {
        float m = rs[0] * (1.0f/EE);
        float var = rq[0] * (1.0f/EE) - m*m;
        s_m = m; s_r = rsqrtf(var + 1e-5f);
    }
    __syncthreads();
    float m = s_m, r = s_r;
    float y0 = (v0 - m)*r*sc[tid]       + bi[tid];
    float y1 = (v1 - m)*r*sc[tid + 256] + bi[tid + 256];
    __nv_bfloat16 h, l;
    split1(y0, h, l); oh[(size_t)row*EE + tid] = h;       ol[(size_t)row*EE + tid] = l;
    split1(y1, h, l); oh[(size_t)row*EE + tid + 256] = h; ol[(size_t)row*EE + tid + 256] = l;
}

// ---------------- gelu ----------------
__device__ __forceinline__ float gelu_f(float x) {
    float x3 = x*x*x;
    return 0.5f*x*(1.0f + tanhf(0.7978845608028654f*(x + 0.044715f*x3)));
}

__device__ __forceinline__ void mma_bf16(float d[4], const uint32_t a[4], const uint32_t b[2]) {
    asm volatile(
        "mma.sync.aligned.m16n8k16.row.col.f32.bf16.bf16.f32 "
        "{%0,%1,%2,%3}, {%4,%5,%6,%7}, {%8,%9}, {%0,%1,%2,%3};\n"
        : "+f"(d[0]), "+f"(d[1]), "+f"(d[2]), "+f"(d[3])
        : "r"(a[0]), "r"(a[1]), "r"(a[2]), "r"(a[3]), "r"(b[0]), "r"(b[1]));
}

__device__ __forceinline__ void ldsm4(uint32_t f[4], uint32_t smaddr) {
    asm volatile("ldmatrix.sync.aligned.m8n8.x4.shared.b16 {%0,%1,%2,%3}, [%4];"
                 : "=r"(f[0]), "=r"(f[1]), "=r"(f[2]), "=r"(f[3]) : "r"(smaddr));
}

__device__ __forceinline__ void cpa16(uint32_t dst, const void* src) {
    asm volatile("cp.async.cg.shared.global [%0], [%1], 16;" :: "r"(dst), "l"(src));
}
#define CP_COMMIT() asm volatile("cp.async.commit_group;")
#define CP_WAIT1()  asm volatile("cp.async.wait_group 1;")

// ---------------- split-bf16 tensor GEMM: 3-stage cp.async pipeline ----------------
// BM=BN=128, BK=16, 256 threads = 8 warps (2x4), warp tile 64x32, m16n8k16.
// A: bf16 hi/lo row-major. B: pair-interleaved uint32 [K/2][N].
// OUTMODE: 0=store f32, 1=accum f32, 2=split bf16 store
#define AST 12
#define BST 136
#define STA (128*AST)     // uint32 per A stage (per hi/lo)
#define STB (8*BST)       // uint32 per B stage (per hi/lo)
#define GEMM_SMEM ((3*(STA*2 + STB*2))*4)

template<int ACT, int OUTMODE, bool HASB>
__global__ void __launch_bounds__(256,2) bf3_gemm(
    const __nv_bfloat16* __restrict__ Ah, const __nv_bfloat16* __restrict__ Al,
    const uint32_t* __restrict__ Bh, const uint32_t* __restrict__ Bl,
    const float* __restrict__ bias,
    float* __restrict__ C,
    __nv_bfloat16* __restrict__ Ch, __nv_bfloat16* __restrict__ Cl,
    int M, int N, int K)
{
    extern __shared__ uint32_t gsm[];
    uint32_t* AsH = gsm;
    uint32_t* AsL = AsH + 3*STA;
    uint32_t* BsH = AsL + 3*STA;
    uint32_t* BsL = BsH + 3*STB;

    int tid = threadIdx.x;
    int lane = tid & 31;
    int warp = tid >> 5;
    int wm = (warp >> 2) * 64;
    int wn = (warp & 3) * 32;
    int bm = blockIdx.y * 128, bn = blockIdx.x * 128;

    float acc[4][4][4];
#pragma unroll
    for (int mi = 0; mi < 4; mi++)
#pragma unroll
        for (int ni = 0; ni < 4; ni++)
#pragma unroll
            for (int r = 0; r < 4; r++) acc[mi][ni][r] = 0.0f;

    int a_r = tid >> 1, a_h = (tid & 1) * 8;
    int b_p = tid >> 5, b_cg = (tid & 31) * 4;
    const __nv_bfloat16* Abh = Ah + (size_t)bm*K + (size_t)a_r*K + a_h;
    const __nv_bfloat16* Abl = Al + (size_t)bm*K + (size_t)a_r*K + a_h;
    const uint32_t* Bbh = Bh + (size_t)b_p*N + bn + b_cg;
    const uint32_t* Bbl = Bl + (size_t)b_p*N + bn + b_cg;

    uint32_t awH = (uint32_t)__cvta_generic_to_shared(AsH) + (a_r*AST + (a_h>>1))*4;
    uint32_t awL = (uint32_t)__cvta_generic_to_shared(AsL) + (a_r*AST + (a_h>>1))*4;
    uint32_t bwH = (uint32_t)__cvta_generic_to_shared(BsH) + (b_p*BST + b_cg)*4;
    uint32_t bwL = (uint32_t)__cvta_generic_to_shared(BsL) + (b_p*BST + b_cg)*4;

    int nk = K / 16;

#define ISSUE(S, K0)                                              \
    {                                                             \
        cpa16(awH + (S)*STA*4, Abh + (K0));                       \
        cpa16(awL + (S)*STA*4, Abl + (K0));                       \
        cpa16(bwH + (S)*STB*4, Bbh + (size_t)((K0)>>1)*N);        \
        cpa16(bwL + (S)*STB*4, Bbl + (size_t)((K0)>>1)*N);        \
    }

    ISSUE(0, 0)  CP_COMMIT();
    ISSUE(1, 16) CP_COMMIT();

    // ldmatrix lane address (A frags)
    int l_row = wm + (lane & 7) + ((lane >> 3) & 1) * 8;
    int l_kp  = ((lane >> 4) & 1) * 4;
    uint32_t aoffH = (uint32_t)__cvta_generic_to_shared(AsH) + (l_row*AST + l_kp)*4;
    uint32_t aoffL = (uint32_t)__cvta_generic_to_shared(AsL) + (l_row*AST + l_kp)*4;

    int bc0 = wn + (lane >> 2);
    int bp0 = lane & 3;

    int buf = 0, bufn = 2;
    for (int it = 0; it < nk; it++) {
        CP_WAIT1();
        __syncthreads();
        uint32_t afh[4][4], afl[4][4], bfh[4][2], bfl[4][2];
        uint32_t aH = aoffH + (uint32_t)buf*STA*4;
        uint32_t aL = aoffL + (uint32_t)buf*STA*4;
#pragma unroll
        for (int mi = 0; mi < 4; mi++) {
            ldsm4(afh[mi], aH + (uint32_t)(mi*16*AST*4));
            ldsm4(afl[mi], aL + (uint32_t)(mi*16*AST*4));
        }
        const uint32_t* bsH = BsH + buf*STB;
        const uint32_t* bsL = BsL + buf*STB;
#pragma unroll
        for (int ni = 0; ni < 4; ni++) {
            int base = bp0*BST + bc0 + ni*8;
            bfh[ni][0] = bsH[base];
            bfh[ni][1] = bsH[base + 4*BST];
            bfl[ni][0] = bsL[base];
            bfl[ni][1] = bsL[base + 4*BST];
        }
        if (it + 2 < nk) ISSUE(bufn, (it+2)*16)
        CP_COMMIT();
#pragma unroll
        for (int mi = 0; mi < 4; mi++)
#pragma unroll
            for (int ni = 0; ni < 4; ni++) {
                mma_bf16(acc[mi][ni], afl[mi], bfh[ni]);
                mma_bf16(acc[mi][ni], afh[mi], bfl[ni]);
                mma_bf16(acc[mi][ni], afh[mi], bfh[ni]);
            }
        buf  = (buf  == 2) ? 0 : buf  + 1;
        bufn = (bufn == 2) ? 0 : bufn + 1;
    }

#pragma unroll
    for (int mi = 0; mi < 4; mi++) {
        int r0 = bm + wm + mi*16 + (lane >> 2);
#pragma unroll
        for (int ni = 0; ni < 4; ni++) {
            int c0 = bn + wn + ni*8 + (lane & 3)*2;
            float* a = acc[mi][ni];
#pragma unroll
            for (int hr = 0; hr < 2; hr++) {
                int r = r0 + hr*8;
                float v0 = a[hr*2 + 0], v1 = a[hr*2 + 1];
                if (HASB) { v0 += bias[c0]; v1 += bias[c0+1]; }
                if (ACT == 1) { v0 = gelu_f(v0); v1 = gelu_f(v1); }
                size_t o = (size_t)r*N + c0;
                if (OUTMODE == 0) {
                    float2 t2; t2.x = v0; t2.y = v1;
                    *(float2*)&C[o] = t2;
                } else if (OUTMODE == 1) {
                    float2 old = *(float2*)&C[o];
                    old.x += v0; old.y += v1;
                    *(float2*)&C[o] = old;
                } else {
                    uint32_t hh2, ll2;
                    split2(v0, v1, hh2, ll2);
                    *(uint32_t*)&Ch[o] = hh2;
                    *(uint32_t*)&Cl[o] = ll2;
                }
            }
        }
    }
}

// ---------------- fused qnorm + cluster distances (tiled; q has QKS stride) ----------------
__global__ void dist_kernel(const float* __restrict__ q, const float* __restrict__ means_l,
                            float* __restrict__ dists) {
    extern __shared__ float dsm[];
    float* qs = dsm;             // 128*65
    float* ms = qs + 128*65;     // 64*64
    float* mn = ms + 64*64;      // 64
    float* qn = mn + 64;         // 128
    int tile = blockIdx.x;
    int bh = blockIdx.y;
    int h = bh & 7, b = bh >> 3;
    int n0 = tile * 128;
    int tid = threadIdx.x;
    for (int i = tid; i < 64*64; i += 256) ms[i] = means_l[h*64*64 + i];
    for (int i = tid; i < 128*16; i += 256) {
        int r = i >> 4, c4 = (i & 15) * 4;
        float4 v = *(const float4*)(q + ((size_t)(b*SS + n0 + r))*QKS + h*DD + c4);
        float* dst = qs + r*65 + c4;
        dst[0]=v.x; dst[1]=v.y; dst[2]=v.z; dst[3]=v.w;
    }
    __syncthreads();
    if (tid < 64) {
        float s = 0; const float* mr = ms + tid*64;
#pragma unroll 16
        for (int d = 0; d < 64; d++) s += mr[d]*mr[d];
        mn[tid] = 1.0f/(sqrtf(s) + 1e-8f);
    } else if (tid >= 128) {
        int r = tid - 128;
        float s = 0; const float* qr = qs + r*65;
#pragma unroll 16
        for (int d = 0; d < 64; d++) s += qr[d]*qr[d];
        qn[r] = 1.0f/(sqrtf(s) + 1e-8f);
    }
    __syncthreads();
    int nl = tid & 127;
    int c0 = (tid >> 7) * 32;
    float acc[32];
#pragma unroll
    for (int c = 0; c < 32; c++) acc[c] = 0.0f;
    for (int dc = 0; dc < 64; dc += 16) {
        float qreg[16];
#pragma unroll
        for (int d = 0; d < 16; d++) qreg[d] = qs[nl*65 + dc + d];
#pragma unroll
        for (int c = 0; c < 32; c++) {
            const float* mr = ms + (c0 + c)*64 + dc;
            float s = acc[c];
#pragma unroll
            for (int d = 0; d < 16; d++) s += qreg[d]*mr[d];
            acc[c] = s;
        }
    }
    float qi = qn[nl];
#pragma unroll
    for (int c = 0; c < 32; c++) {
        int cc = c0 + c;
        dists[((size_t)bh*CC + cc)*SS + n0 + nl] = acc[c]*mn[cc]*qi;
    }
}

// ---------------- radix-select top-64 (exact, ties -> smallest index) ----------------
__global__ void topk_kernel(const float* __restrict__ dists, int* __restrict__ idxout) {
    __shared__ uint32_t keys[SS];
    __shared__ int hist[256];
    __shared__ int ties[SS];
    __shared__ int rmin[256];
    __shared__ int s_chosen, s_rem, s_cntgt, s_ntie, s_pick;
    int blk = blockIdx.x, tid = threadIdx.x;
    const float* drow = dists + (size_t)blk*SS;
    for (int n = tid; n < SS; n += 256) {
        uint32_t u = __float_as_uint(drow[n]);
        keys[n] = (u & 0x80000000u) ? ~u : (u | 0x80000000u);
    }
    uint32_t prefix = 0, maskhi = 0;
    int rem = WIN;
    for (int p = 0; p < 4; p++) {
        int shift = 24 - 8*p;
        hist[tid] = 0;
        __syncthreads();
        for (int n = tid; n < SS; n += 256) {
            uint32_t kk = keys[n];
            if ((kk & maskhi) == prefix) atomicAdd(&hist[(kk >> shift) & 255], 1);
        }
        __syncthreads();
        if (tid == 0) {
            int cum = 0, bsel = 255;
            for (; bsel >= 0; bsel--) { cum += hist[bsel]; if (cum >= rem) break; }
            s_chosen = bsel; s_rem = rem - (cum - hist[bsel]);
        }
        __syncthreads();
        prefix |= ((uint32_t)s_chosen) << shift;
        maskhi |= 0xFFu << shift;
        rem = s_rem;
        __syncthreads();
    }
    uint32_t T = prefix;
    if (tid == 0) { s_cntgt = 0; s_ntie = 0; }
    __syncthreads();
    int* orow = idxout + blk*WIN;
    for (int n = tid; n < SS; n += 256) {
        uint32_t kk = keys[n];
        if (kk > T) { int pp = atomicAdd(&s_cntgt, 1); orow[pp] = n; }
        else if (kk == T) { int pp = atomicAdd(&s_ntie, 1); ties[pp] = n; }
    }
    __syncthreads();
    int cntgt = s_cntgt;
    int need = WIN - cntgt;
    int ntie = s_ntie;
    if (need > 0) {
        if (need == ntie) {
            for (int j = tid; j < need; j += 256) orow[cntgt + j] = ties[j];
        } else {
            int last = -1;
            for (int j = 0; j < need; j++) {
                int mymin = 0x7FFFFFFF;
                for (int t2 = tid; t2 < ntie; t2 += 256) {
                    int vv = ties[t2];
                    if (vv > last && vv < mymin) mymin = vv;
                }
                rmin[tid] = mymin;
                __syncthreads();
                for (int off = 128; off; off >>= 1) {
                    if (tid < off) rmin[tid] = min(rmin[tid], rmin[tid+off]);
                    __syncthreads();
                }
                if (tid == 0) { orow[cntgt + j] = rmin[0]; s_pick = rmin[0]; }
                __syncthreads();
                last = s_pick;
            }
        }
    }
}

// ---------------- bucket attention (register-tiled 4x4; q/k/v strided QKS) ----------------
__global__ void bucket_attn_kernel(const float* __restrict__ q, const float* __restrict__ k,
                                   const float* __restrict__ v, const int* __restrict__ value,
                                   const int* __restrict__ idxin, float* __restrict__ attout,
                                   float* __restrict__ cnt) {
    extern __shared__ float sm[];
    float* qb = sm;
    float* kb = qb + 64*65;
    float* vb = kb + 64*65;
    float* sc = vb + 64*65;
    __shared__ int idxs[64];
    __shared__ int kms[64];
    int blk = blockIdx.x;
    int bh = blk / CC; int h = bh % HH; int b = bh / HH;
    int tid = threadIdx.x;
    if (tid < 64) {
        int t = idxin[blk*WIN + tid];
        idxs[tid] = t;
        kms[tid] = (value[b*SS + t] != 0);
    }
    __syncthreads();
    for (int i = tid; i < 64*64; i += 256) {
        int w = i >> 6, d = i & 63;
        size_t base = ((size_t)(b*SS + idxs[w]))*QKS + h*DD + d;
        qb[w*65 + d] = q[base];
        kb[w*65 + d] = k[base];
        vb[w*65 + d] = v[base];
    }
    __syncthreads();
    int tw = (tid >> 4) * 4;
    int tx = (tid & 15) * 4;
    float a2[4][4];
#pragma unroll
    for (int i = 0; i < 4; i++)
#pragma unroll
        for (int j = 0; j < 4; j++) a2[i][j] = 0.0f;
    for (int kk = 0; kk < 64; kk++) {
        float qv[4], kv[4];
#pragma unroll
        for (int i = 0; i < 4; i++) qv[i] = qb[(tw+i)*65 + kk];
#pragma unroll
        for (int j = 0; j < 4; j++) kv[j] = kb[(tx+j)*65 + kk];
#pragma unroll
        for (int i = 0; i < 4; i++)
#pragma unroll
            for (int j = 0; j < 4; j++) a2[i][j] += qv[i]*kv[j];
    }
#pragma unroll
    for (int i = 0; i < 4; i++)
#pragma unroll
        for (int j = 0; j < 4; j++) {
            bool allowed = (idxs[tw+i] >= idxs[tx+j]) && kms[tx+j];
            sc[(tw+i)*65 + tx+j] = allowed ? a2[i][j]*0.125f : -1e9f;
        }
    __syncthreads();
    if (tid < 64) {
        float mx = -INFINITY;
        for (int xx = 0; xx < 64; xx++) mx = fmaxf(mx, sc[tid*65+xx]);
        float sum = 0.0f;
        for (int xx = 0; xx < 64; xx++) { float e = expf(sc[tid*65+xx]-mx); sc[tid*65+xx] = e; sum += e; }
        float inv = 1.0f/sum;
        for (int xx = 0; xx < 64; xx++) sc[tid*65+xx] *= inv;
    }
    __syncthreads();
    float o2[4][4];
#pragma unroll
    for (int i = 0; i < 4; i++)
#pragma unroll
        for (int j = 0; j < 4; j++) o2[i][j] = 0.0f;
    for (int xx = 0; xx < 64; xx++) {
        float sv[4], vv[4];
#pragma unroll
        for (int i = 0; i < 4; i++) sv[i] = sc[(tw+i)*65 + xx];
#pragma unroll
        for (int j = 0; j < 4; j++) vv[j] = vb[xx*65 + tx+j];
#pragma unroll
        for (int i = 0; i < 4; i++)
#pragma unroll
            for (int j = 0; j < 4; j++) o2[i][j] += sv[i]*vv[j];
    }
#pragma unroll
    for (int i = 0; i < 4; i++)
#pragma unroll
        for (int j = 0; j < 4; j++)
            atomicAdd(&attout[((size_t)(b*SS + idxs[tw+i]))*EE + h*DD + tx+j], o2[i][j]);
    if (tid < 64) atomicAdd(&cnt[(size_t)(b*SS + idxs[tid])*HH + h], 1.0f);
}

// ---------------- scatter-mean normalization -> split bf16 ----------------
__global__ void norm_attout_kernel(const float* __restrict__ attout, const float* __restrict__ cnt,
                                   __nv_bfloat16* __restrict__ oh, __nv_bfloat16* __restrict__ ol) {
    int i = blockIdx.x*256 + threadIdx.x;
    int row = i >> 9;
    int h = (i & 511) >> 6;
    float c = cnt[(size_t)row*HH + h];
    float val = attout[i] / fmaxf(c, 1.0f);
    __nv_bfloat16 hh2, ll2;
    split1(val, hh2, ll2);
    oh[i] = hh2; ol[i] = ll2;
}

// ---------------- head: logits = x @ head_w.T  (N=17), warp per row ----------------
__global__ void head_kernel(const float* __restrict__ x, const float* __restrict__ hw,
                            float* __restrict__ out) {
    int gw = (blockIdx.x*256 + threadIdx.x) >> 5;
    int lane = threadIdx.x & 31;
    if (gw >= MM) return;
    const float* xp = x + (size_t)gw*EE;
    float xr[16];
#pragma unroll
    for (int i = 0; i < 16; i++) xr[i] = xp[lane + i*32];
    for (int o = 0; o < NVOC; o++) {
        const float* w = hw + o*EE;
        float s = 0.0f;
#pragma unroll
        for (int i = 0; i < 16; i++) s += xr[i]*w[lane + i*32];
#pragma unroll
        for (int off = 16; off; off >>= 1) s += __shfl_xor_sync(0xffffffffu, s, off);
        if (lane == 0) out[(size_t)gw*NVOC + o] = s;
    }
}

// ---------------- host orchestration ----------------
extern "C" void kernel_launch(void* const* d_in, const int* in_sizes, int n_in,
                              void* d_out, int out_size) {
    const int*   value     = (const int*)d_in[0];
    const int*   depth     = (const int*)d_in[1];
    const int*   pos       = (const int*)d_in[2];
    const float* sos       = (const float*)d_in[3];
    const float* tok_emb   = (const float*)d_in[4];
    const float* depth_emb = (const float*)d_in[5];
    const float* pos_emb   = (const float*)d_in[6];
    const float* ln1_s     = (const float*)d_in[7];
    const float* ln1_b     = (const float*)d_in[8];
    const float* Wq        = (const float*)d_in[9];
    const float* Wk        = (const float*)d_in[10];
    const float* Wv        = (const float*)d_in[11];
    const float* Wo        = (const float*)d_in[12];
    const float* means     = (const float*)d_in[13];
    const float* ln2_s     = (const float*)d_in[14];
    const float* ln2_b     = (const float*)d_in[15];
    const float* W1        = (const float*)d_in[16];
    const float* b1        = (const float*)d_in[17];
    const float* W2        = (const float*)d_in[18];
    const float* b2        = (const float*)d_in[19];
    const float* head_w    = (const float*)d_in[20];
    float* out = (float*)d_out;

    float *x, *qkv, *dists, *attout, *cnt;
    int* idxb;
    __nv_bfloat16 *hh, *hl, *th, *tl, *aoh, *aol;
    uint32_t *Wqkvh, *Wqkvl, *Woh, *Wol, *W1h, *W1l, *W2h, *W2l;
    cudaGetSymbolAddress((void**)&x, g_x);
    cudaGetSymbolAddress((void**)&qkv, g_qkv);
    cudaGetSymbolAddress((void**)&dists, g_dists);
    cudaGetSymbolAddress((void**)&idxb, g_idx);
    cudaGetSymbolAddress((void**)&attout, g_attout);
    cudaGetSymbolAddress((void**)&cnt, g_cnt);
    cudaGetSymbolAddress((void**)&hh, g_hh);   cudaGetSymbolAddress((void**)&hl, g_hl);
    cudaGetSymbolAddress((void**)&th, g_th);   cudaGetSymbolAddress((void**)&tl, g_tl);
    cudaGetSymbolAddress((void**)&aoh, g_aoh); cudaGetSymbolAddress((void**)&aol, g_aol);
    cudaGetSymbolAddress((void**)&Wqkvh, g_Wqkvh); cudaGetSymbolAddress((void**)&Wqkvl, g_Wqkvl);
    cudaGetSymbolAddress((void**)&Woh, g_Woh); cudaGetSymbolAddress((void**)&Wol, g_Wol);
    cudaGetSymbolAddress((void**)&W1h, g_W1h); cudaGetSymbolAddress((void**)&W1l, g_W1l);
    cudaGetSymbolAddress((void**)&W2h, g_W2h); cudaGetSymbolAddress((void**)&W2l, g_W2l);

    const int ATTN_SMEM = 4 * 64 * 65 * (int)sizeof(float);
    cudaFuncSetAttribute(bucket_attn_kernel, cudaFuncAttributeMaxDynamicSharedMemorySize, ATTN_SMEM);
    const int DIST_SMEM = (128*65 + 64*64 + 64 + 128) * (int)sizeof(float);
    cudaFuncSetAttribute(dist_kernel, cudaFuncAttributeMaxDynamicSharedMemorySize, DIST_SMEM);
    cudaFuncSetAttribute(bf3_gemm<0,0,false>, cudaFuncAttributeMaxDynamicSharedMemorySize, GEMM_SMEM);
    cudaFuncSetAttribute(bf3_gemm<0,1,false>, cudaFuncAttributeMaxDynamicSharedMemorySize, GEMM_SMEM);
    cudaFuncSetAttribute(bf3_gemm<1,2,true>,  cudaFuncAttributeMaxDynamicSharedMemorySize, GEMM_SMEM);
    cudaFuncSetAttribute(bf3_gemm<0,1,true>,  cudaFuncAttributeMaxDynamicSharedMemorySize, GEMM_SMEM);

    // weight splits (pair-interleaved, once per launch)
    split_qkv_pi_kernel<<<(LL*(EE/2)*QKS/4 + 255)/256, 256>>>(Wq, Wk, Wv, Wqkvh, Wqkvl);
    split_pi_kernel<<<(LL*(EE/2)*EE/4 + 255)/256, 256>>>(Wo, Woh, Wol, EE, EE, LL*(EE/2)*EE/4);
    split_pi_kernel<<<(LL*(EE/2)*FF/4 + 255)/256, 256>>>(W1, W1h, W1l, EE, FF, LL*(EE/2)*FF/4);
    split_pi_kernel<<<(LL*(FF/2)*EE/4 + 255)/256, 256>>>(W2, W2h, W2l, FF, EE, LL*(FF/2)*EE/4);

    embed_kernel<<<MM, 128>>>(value, depth, pos, sos, tok_emb, depth_emb, pos_emb, x);

    dim3 gE(EE/128, MM/128);     // 4 x 128
    dim3 gQ(QKS/128, MM/128);    // 12 x 128
    dim3 gF(FF/128, MM/128);     // 16 x 128
    dim3 gD(SS/128, BB*HH);      // 32 x 32

    for (int l = 0; l < LL; l++) {
        size_t oQ = (size_t)l*(EE/2)*QKS;
        size_t oE = (size_t)l*(EE/2)*EE;
        size_t oF1 = (size_t)l*(EE/2)*FF;
        size_t oF2 = (size_t)l*(FF/2)*EE;
        const float* ml = means + (size_t)l*HH*CC*DD;
        float* q = qkv;
        float* k = qkv + EE;
        float* v = qkv + 2*EE;

        ln_kernel<<<MM, 256>>>(x, ln1_s + l*EE, ln1_b + l*EE, hh, hl);
        bf3_gemm<0,0,false><<<gQ, 256, GEMM_SMEM>>>(hh, hl, Wqkvh+oQ, Wqkvl+oQ, nullptr, qkv, nullptr, nullptr, MM, QKS, EE);

        dist_kernel<<<gD, 256, DIST_SMEM>>>(q, ml, dists);
        topk_kernel<<<BB*HH*CC, 256>>>(dists, idxb);

        cudaMemsetAsync(attout, 0, (size_t)MM*EE*sizeof(float));
        cudaMemsetAsync(cnt, 0, (size_t)MM*HH*sizeof(float));
        bucket_attn_kernel<<<BB*HH*CC, 256, ATTN_SMEM>>>(q, k, v, value, idxb, attout, cnt);
        norm_attout_kernel<<<(MM*EE)/256, 256>>>(attout, cnt, aoh, aol);

        bf3_gemm<0,1,false><<<gE, 256, GEMM_SMEM>>>(aoh, aol, Woh+oE, Wol+oE, nullptr, x, nullptr, nullptr, MM, EE, EE);

        ln_kernel<<<MM, 256>>>(x, ln2_s + l*EE, ln2_b + l*EE, hh, hl);
        bf3_gemm<1,2,true><<<gF, 256, GEMM_SMEM>>>(hh, hl, W1h+oF1, W1l+oF1, b1 + l*FF, nullptr, th, tl, MM, FF, EE);
        bf3_gemm<0,1,true><<<gE, 256, GEMM_SMEM>>>(th, tl, W2h+oF2, W2l+oF2, b2 + l*EE, x, nullptr, nullptr, MM, EE, FF);
    }

    head_kernel<<<MM/8, 256>>>(x, head_w, out);
}

// round 8
// speedup vs baseline: 2.9093x; 1.0086x over previous
#include <cuda_runtime.h>
#include <cuda_bf16.h>
#include <math.h>
#include <stdint.h>

// ---------------- problem constants ----------------
#define BB 4
#define SS 4096
#define EE 512
#define HH 8
#define LL 4
#define AA 3
#define WIN 64
#define CC 64           // S / WIN clusters
#define DD 64           // E / H
#define MM (BB*SS)      // 16384 rows
#define FF (4*EE)       // 2048 ffn dim
#define QKS (3*EE)      // fused qkv row stride 1536
#define NVOC 17

// ---------------- scratch (device globals; no allocation allowed) ----------------
__device__ float g_x[MM*EE];
__device__ float g_qkv[MM*QKS];
__device__ float g_dists[BB*HH*CC*SS];
__device__ int   g_idx[BB*HH*CC*WIN];
__device__ float g_attout[MM*EE];
__device__ float g_cnt[MM*HH];
// split activations (A operands)
__device__ __nv_bfloat16 g_hh[MM*EE],  g_hl[MM*EE];
__device__ __nv_bfloat16 g_th[MM*FF],  g_tl[MM*FF];
__device__ __nv_bfloat16 g_aoh[MM*EE], g_aol[MM*EE];
// split weights, pair-interleaved: uint32 [K/2][N] per layer
__device__ uint32_t g_Wqkvh[LL*(EE/2)*QKS], g_Wqkvl[LL*(EE/2)*QKS];
__device__ uint32_t g_Woh[LL*(EE/2)*EE],    g_Wol[LL*(EE/2)*EE];
__device__ uint32_t g_W1h[LL*(EE/2)*FF],    g_W1l[LL*(EE/2)*FF];
__device__ uint32_t g_W2h[LL*(FF/2)*EE],    g_W2l[LL*(FF/2)*EE];

// ---------------- bf16 split helpers ----------------
__device__ __forceinline__ uint32_t packbf(float x, float y) {
    __nv_bfloat162 t = __floats2bfloat162_rn(x, y);
    return *reinterpret_cast<uint32_t*>(&t);
}
__device__ __forceinline__ void split2(float x, float y, uint32_t& hi, uint32_t& lo) {
    float xh = __bfloat162float(__float2bfloat16(x));
    float yh = __bfloat162float(__float2bfloat16(y));
    hi = packbf(x, y);
    lo = packbf(x - xh, y - yh);
}
__device__ __forceinline__ void split1(float x, __nv_bfloat16& h, __nv_bfloat16& l) {
    h = __float2bfloat16(x);
    l = __float2bfloat16(x - __bfloat162float(h));
}

// ---------------- weight split prep (pair-interleaved) ----------------
__global__ void split_pi_kernel(const float* __restrict__ W, uint32_t* __restrict__ PIh,
                                uint32_t* __restrict__ PIl, int K, int N, int n4total) {
    int gid = blockIdx.x*256 + threadIdx.x;
    if (gid >= n4total) return;
    int i = gid*4;
    int c = i % N;
    int rest = i / N;
    int p = rest % (K/2);
    int l = rest / (K/2);
    const float* w0 = W + ((size_t)l*K + 2*p)*N + c;
    float4 v0 = *(const float4*)w0;
    float4 v1 = *(const float4*)(w0 + N);
    uint32_t h0,l0,h1,l1,h2,l2,h3,l3;
    split2(v0.x, v1.x, h0, l0);
    split2(v0.y, v1.y, h1, l1);
    split2(v0.z, v1.z, h2, l2);
    split2(v0.w, v1.w, h3, l3);
    size_t o = ((size_t)l*(K/2) + p)*N + c;
    *(uint4*)(PIh + o) = make_uint4(h0,h1,h2,h3);
    *(uint4*)(PIl + o) = make_uint4(l0,l1,l2,l3);
}

__global__ void split_qkv_pi_kernel(const float* __restrict__ Wq, const float* __restrict__ Wk,
                                    const float* __restrict__ Wv,
                                    uint32_t* __restrict__ PIh, uint32_t* __restrict__ PIl) {
    int gid = blockIdx.x*256 + threadIdx.x;
    int i = gid*4;
    if (i >= LL*(EE/2)*QKS) return;
    int c = i % QKS;
    int rest = i / QKS;
    int p = rest % (EE/2);
    int l = rest / (EE/2);
    const float* src; int cc = c;
    if (c < EE) src = Wq;
    else if (c < 2*EE) { src = Wk; cc = c - EE; }
    else { src = Wv; cc = c - 2*EE; }
    const float* w0 = src + ((size_t)l*EE + 2*p)*EE + cc;
    float4 v0 = *(const float4*)w0;
    float4 v1 = *(const float4*)(w0 + EE);
    uint32_t h0,l0,h1,l1,h2,l2,h3,l3;
    split2(v0.x, v1.x, h0, l0);
    split2(v0.y, v1.y, h1, l1);
    split2(v0.z, v1.z, h2, l2);
    split2(v0.w, v1.w, h3, l3);
    size_t o = ((size_t)l*(EE/2) + p)*QKS + c;
    *(uint4*)(PIh + o) = make_uint4(h0,h1,h2,h3);
    *(uint4*)(PIl + o) = make_uint4(l0,l1,l2,l3);
}

// ---------------- embedding + shift-right ----------------
__global__ void embed_kernel(const int* __restrict__ value, const int* __restrict__ depth,
                             const int* __restrict__ pos, const float* __restrict__ sos,
                             const float* __restrict__ tok, const float* __restrict__ dep,
                             const float* __restrict__ pemb, float* __restrict__ x) {
    int row = blockIdx.x;
    int t = row & (SS - 1);
    if (t == 0) {
        for (int e = threadIdx.x; e < EE; e += blockDim.x) x[(size_t)row*EE + e] = sos[e];
        return;
    }
    int pr = row - 1;
    int v  = value[pr], dp = depth[pr];
    int p0 = pos[pr*AA+0], p1 = pos[pr*AA+1], p2 = pos[pr*AA+2];
    for (int e = threadIdx.x; e < EE; e += blockDim.x) {
        float s = tok[v*EE+e] + dep[dp*EE+e]
                + pemb[(0*65 + p0)*EE + e]
                + pemb[(1*65 + p1)*EE + e]
                + pemb[(2*65 + p2)*EE + e];
        x[(size_t)row*EE + e] = s;
    }
}

// ---------------- layernorm: warp per row, no smem ----------------
__global__ void ln_kernel(const float* __restrict__ x, const float* __restrict__ sc,
                          const float* __restrict__ bi,
                          __nv_bfloat16* __restrict__ oh, __nv_bfloat16* __restrict__ ol) {
    int warp = threadIdx.x >> 5, lane = threadIdx.x & 31;
    int row = blockIdx.x*8 + warp;
    const float4* xr = (const float4*)(x + (size_t)row*EE);
    float4 v[4];
    float s = 0.0f, q2 = 0.0f;
#pragma unroll
    for (int i = 0; i < 4; i++) {
        v[i] = xr[lane + 32*i];
        s  += v[i].x + v[i].y + v[i].z + v[i].w;
        q2 += v[i].x*v[i].x + v[i].y*v[i].y + v[i].z*v[i].z + v[i].w*v[i].w;
    }
#pragma unroll
    for (int o = 16; o; o >>= 1) {
        s  += __shfl_xor_sync(0xffffffffu, s, o);
        q2 += __shfl_xor_sync(0xffffffffu, q2, o);
    }
    float m = s * (1.0f/EE);
    float r = rsqrtf(q2 * (1.0f/EE) - m*m + 1e-5f);
#pragma unroll
    for (int i = 0; i < 4; i++) {
        int c4 = (lane + 32*i) * 4;
        float y0 = (v[i].x - m)*r*sc[c4+0] + bi[c4+0];
        float y1 = (v[i].y - m)*r*sc[c4+1] + bi[c4+1];
        float y2 = (v[i].z - m)*r*sc[c4+2] + bi[c4+2];
        float y3 = (v[i].w - m)*r*sc[c4+3] + bi[c4+3];
        uint32_t hA, lA, hB, lB;
        split2(y0, y1, hA, lA);
        split2(y2, y3, hB, lB);
        *(uint2*)(oh + (size_t)row*EE + c4) = make_uint2(hA, hB);
        *(uint2*)(ol + (size_t)row*EE + c4) = make_uint2(lA, lB);
    }
}

// ---------------- gelu ----------------
__device__ __forceinline__ float gelu_f(float x) {
    float x3 = x*x*x;
    return 0.5f*x*(1.0f + tanhf(0.7978845608028654f*(x + 0.044715f*x3)));
}

__device__ __forceinline__ void mma_bf16(float d[4], const uint32_t a[4], const uint32_t b[2]) {
    asm volatile(
        "mma.sync.aligned.m16n8k16.row.col.f32.bf16.bf16.f32 "
        "{%0,%1,%2,%3}, {%4,%5,%6,%7}, {%8,%9}, {%0,%1,%2,%3};\n"
        : "+f"(d[0]), "+f"(d[1]), "+f"(d[2]), "+f"(d[3])
        : "r"(a[0]), "r"(a[1]), "r"(a[2]), "r"(a[3]), "r"(b[0]), "r"(b[1]));
}

__device__ __forceinline__ void ldsm4(uint32_t f[4], uint32_t smaddr) {
    asm volatile("ldmatrix.sync.aligned.m8n8.x4.shared.b16 {%0,%1,%2,%3}, [%4];"
                 : "=r"(f[0]), "=r"(f[1]), "=r"(f[2]), "=r"(f[3]) : "r"(smaddr));
}

__device__ __forceinline__ void cpa16(uint32_t dst, const void* src) {
    asm volatile("cp.async.cg.shared.global [%0], [%1], 16;" :: "r"(dst), "l"(src));
}
#define CP_COMMIT() asm volatile("cp.async.commit_group;")
#define CP_WAIT2()  asm volatile("cp.async.wait_group 2;")

// ---------------- split-bf16 tensor GEMM: 4-stage cp.async pipeline ----------------
// BM=BN=128, BK=16, 256 threads = 8 warps (2x4), warp tile 64x32, m16n8k16.
// A: bf16 hi/lo row-major. B: pair-interleaved uint32 [K/2][N].
// OUTMODE: 0=store f32, 1=accum f32, 2=split bf16 store
#define AST 12
#define BST 136
#define STA (128*AST)     // uint32 per A stage (per hi/lo)
#define STB (8*BST)       // uint32 per B stage (per hi/lo)
#define NSTG 4
#define GEMM_SMEM ((NSTG*(STA*2 + STB*2))*4)

template<int ACT, int OUTMODE, bool HASB>
__global__ void __launch_bounds__(256,2) bf3_gemm(
    const __nv_bfloat16* __restrict__ Ah, const __nv_bfloat16* __restrict__ Al,
    const uint32_t* __restrict__ Bh, const uint32_t* __restrict__ Bl,
    const float* __restrict__ bias,
    float* __restrict__ C,
    __nv_bfloat16* __restrict__ Ch, __nv_bfloat16* __restrict__ Cl,
    int M, int N, int K)
{
    extern __shared__ uint32_t gsm[];
    uint32_t* AsH = gsm;
    uint32_t* AsL = AsH + NSTG*STA;
    uint32_t* BsH = AsL + NSTG*STA;
    uint32_t* BsL = BsH + NSTG*STB;

    int tid = threadIdx.x;
    int lane = tid & 31;
    int warp = tid >> 5;
    int wm = (warp >> 2) * 64;
    int wn = (warp & 3) * 32;
    int bm = blockIdx.y * 128, bn = blockIdx.x * 128;

    float acc[4][4][4];
#pragma unroll
    for (int mi = 0; mi < 4; mi++)
#pragma unroll
        for (int ni = 0; ni < 4; ni++)
#pragma unroll
            for (int r = 0; r < 4; r++) acc[mi][ni][r] = 0.0f;

    int a_r = tid >> 1, a_h = (tid & 1) * 8;
    int b_p = tid >> 5, b_cg = (tid & 31) * 4;
    const __nv_bfloat16* Abh = Ah + (size_t)bm*K + (size_t)a_r*K + a_h;
    const __nv_bfloat16* Abl = Al + (size_t)bm*K + (size_t)a_r*K + a_h;
    const uint32_t* Bbh = Bh + (size_t)b_p*N + bn + b_cg;
    const uint32_t* Bbl = Bl + (size_t)b_p*N + bn + b_cg;

    uint32_t awH = (uint32_t)__cvta_generic_to_shared(AsH) + (a_r*AST + (a_h>>1))*4;
    uint32_t awL = (uint32_t)__cvta_generic_to_shared(AsL) + (a_r*AST + (a_h>>1))*4;
    uint32_t bwH = (uint32_t)__cvta_generic_to_shared(BsH) + (b_p*BST + b_cg)*4;
    uint32_t bwL = (uint32_t)__cvta_generic_to_shared(BsL) + (b_p*BST + b_cg)*4;

    int nk = K / 16;

#define ISSUE(S, K0)                                              \
    {                                                             \
        cpa16(awH + (S)*STA*4, Abh + (K0));                       \
        cpa16(awL + (S)*STA*4, Abl + (K0));                       \
        cpa16(bwH + (S)*STB*4, Bbh + (size_t)((K0)>>1)*N);        \
        cpa16(bwL + (S)*STB*4, Bbl + (size_t)((K0)>>1)*N);        \
    }

    ISSUE(0, 0)  CP_COMMIT();
    ISSUE(1, 16) CP_COMMIT();
    ISSUE(2, 32) CP_COMMIT();

    // ldmatrix lane address (A frags)
    int l_row = wm + (lane & 7) + ((lane >> 3) & 1) * 8;
    int l_kp  = ((lane >> 4) & 1) * 4;
    uint32_t aoffH = (uint32_t)__cvta_generic_to_shared(AsH) + (l_row*AST + l_kp)*4;
    uint32_t aoffL = (uint32_t)__cvta_generic_to_shared(AsL) + (l_row*AST + l_kp)*4;

    int bc0 = wn + (lane >> 2);
    int bp0 = lane & 3;

    for (int it = 0; it < nk; it++) {
        int buf = it & (NSTG-1);
        CP_WAIT2();
        __syncthreads();
        uint32_t afh[4][4], afl[4][4], bfh[4][2], bfl[4][2];
        uint32_t aH = aoffH + (uint32_t)buf*STA*4;
        uint32_t aL = aoffL + (uint32_t)buf*STA*4;
#pragma unroll
        for (int mi = 0; mi < 4; mi++) {
            ldsm4(afh[mi], aH + (uint32_t)(mi*16*AST*4));
            ldsm4(afl[mi], aL + (uint32_t)(mi*16*AST*4));
        }
        const uint32_t* bsH = BsH + buf*STB;
        const uint32_t* bsL = BsL + buf*STB;
#pragma unroll
        for (int ni = 0; ni < 4; ni++) {
            int base = bp0*BST + bc0 + ni*8;
            bfh[ni][0] = bsH[base];
            bfh[ni][1] = bsH[base + 4*BST];
            bfl[ni][0] = bsL[base];
            bfl[ni][1] = bsL[base + 4*BST];
        }
        if (it + 3 < nk) ISSUE((it+3) & (NSTG-1), (it+3)*16)
        CP_COMMIT();
#pragma unroll
        for (int mi = 0; mi < 4; mi++)
#pragma unroll
            for (int ni = 0; ni < 4; ni++) {
                mma_bf16(acc[mi][ni], afl[mi], bfh[ni]);
                mma_bf16(acc[mi][ni], afh[mi], bfl[ni]);
                mma_bf16(acc[mi][ni], afh[mi], bfh[ni]);
            }
    }

#pragma unroll
    for (int mi = 0; mi < 4; mi++) {
        int r0 = bm + wm + mi*16 + (lane >> 2);
#pragma unroll
        for (int ni = 0; ni < 4; ni++) {
            int c0 = bn + wn + ni*8 + (lane & 3)*2;
            float* a = acc[mi][ni];
#pragma unroll
            for (int hr = 0; hr < 2; hr++) {
                int r = r0 + hr*8;
                float v0 = a[hr*2 + 0], v1 = a[hr*2 + 1];
                if (HASB) { v0 += bias[c0]; v1 += bias[c0+1]; }
                if (ACT == 1) { v0 = gelu_f(v0); v1 = gelu_f(v1); }
                size_t o = (size_t)r*N + c0;
                if (OUTMODE == 0) {
                    float2 t2; t2.x = v0; t2.y = v1;
                    *(float2*)&C[o] = t2;
                } else if (OUTMODE == 1) {
                    float2 old = *(float2*)&C[o];
                    old.x += v0; old.y += v1;
                    *(float2*)&C[o] = old;
                } else {
                    uint32_t hh2, ll2;
                    split2(v0, v1, hh2, ll2);
                    *(uint32_t*)&Ch[o] = hh2;
                    *(uint32_t*)&Cl[o] = ll2;
                }
            }
        }
    }
}

// ---------------- fused qnorm + cluster distances (tiled; q has QKS stride) ----------------
__global__ void dist_kernel(const float* __restrict__ q, const float* __restrict__ means_l,
                            float* __restrict__ dists) {
    extern __shared__ float dsm[];
    float* qs = dsm;             // 128*65
    float* ms = qs + 128*65;     // 64*64
    float* mn = ms + 64*64;      // 64
    float* qn = mn + 64;         // 128
    int tile = blockIdx.x;
    int bh = blockIdx.y;
    int h = bh & 7, b = bh >> 3;
    int n0 = tile * 128;
    int tid = threadIdx.x;
    for (int i = tid; i < 64*64; i += 256) ms[i] = means_l[h*64*64 + i];
    for (int i = tid; i < 128*16; i += 256) {
        int r = i >> 4, c4 = (i & 15) * 4;
        float4 v = *(const float4*)(q + ((size_t)(b*SS + n0 + r))*QKS + h*DD + c4);
        float* dst = qs + r*65 + c4;
        dst[0]=v.x; dst[1]=v.y; dst[2]=v.z; dst[3]=v.w;
    }
    __syncthreads();
    if (tid < 64) {
        float s = 0; const float* mr = ms + tid*64;
#pragma unroll 16
        for (int d = 0; d < 64; d++) s += mr[d]*mr[d];
        mn[tid] = 1.0f/(sqrtf(s) + 1e-8f);
    } else if (tid >= 128) {
        int r = tid - 128;
        float s = 0; const float* qr = qs + r*65;
#pragma unroll 16
        for (int d = 0; d < 64; d++) s += qr[d]*qr[d];
        qn[r] = 1.0f/(sqrtf(s) + 1e-8f);
    }
    __syncthreads();
    int nl = tid & 127;
    int c0 = (tid >> 7) * 32;
    float acc[32];
#pragma unroll
    for (int c = 0; c < 32; c++) acc[c] = 0.0f;
    for (int dc = 0; dc < 64; dc += 16) {
        float qreg[16];
#pragma unroll
        for (int d = 0; d < 16; d++) qreg[d] = qs[nl*65 + dc + d];
#pragma unroll
        for (int c = 0; c < 32; c++) {
            const float* mr = ms + (c0 + c)*64 + dc;
            float s = acc[c];
#pragma unroll
            for (int d = 0; d < 16; d++) s += qreg[d]*mr[d];
            acc[c] = s;
        }
    }
    float qi = qn[nl];
#pragma unroll
    for (int c = 0; c < 32; c++) {
        int cc = c0 + c;
        dists[((size_t)bh*CC + cc)*SS + n0 + nl] = acc[c]*mn[cc]*qi;
    }
}

// ---------------- radix-select top-64 (exact, ties -> smallest index) ----------------
__global__ void topk_kernel(const float* __restrict__ dists, int* __restrict__ idxout) {
    __shared__ uint32_t keys[SS];
    __shared__ int hist[256];
    __shared__ int ties[SS];
    __shared__ int rmin[256];
    __shared__ int s_chosen, s_rem, s_cntgt, s_ntie, s_pick;
    int blk = blockIdx.x, tid = threadIdx.x;
    const float* drow = dists + (size_t)blk*SS;
    for (int n = tid; n < SS; n += 256) {
        uint32_t u = __float_as_uint(drow[n]);
        keys[n] = (u & 0x80000000u) ? ~u : (u | 0x80000000u);
    }
    uint32_t prefix = 0, maskhi = 0;
    int rem = WIN;
    for (int p = 0; p < 4; p++) {
        int shift = 24 - 8*p;
        hist[tid] = 0;
        __syncthreads();
        for (int n = tid; n < SS; n += 256) {
            uint32_t kk = keys[n];
            if ((kk & maskhi) == prefix) atomicAdd(&hist[(kk >> shift) & 255], 1);
        }
        __syncthreads();
        if (tid == 0) {
            int cum = 0, bsel = 255;
            for (; bsel >= 0; bsel--) { cum += hist[bsel]; if (cum >= rem) break; }
            s_chosen = bsel; s_rem = rem - (cum - hist[bsel]);
        }
        __syncthreads();
        prefix |= ((uint32_t)s_chosen) << shift;
        maskhi |= 0xFFu << shift;
        rem = s_rem;
        __syncthreads();
    }
    uint32_t T = prefix;
    if (tid == 0) { s_cntgt = 0; s_ntie = 0; }
    __syncthreads();
    int* orow = idxout + blk*WIN;
    for (int n = tid; n < SS; n += 256) {
        uint32_t kk = keys[n];
        if (kk > T) { int pp = atomicAdd(&s_cntgt, 1); orow[pp] = n; }
        else if (kk == T) { int pp = atomicAdd(&s_ntie, 1); ties[pp] = n; }
    }
    __syncthreads();
    int cntgt = s_cntgt;
    int need = WIN - cntgt;
    int ntie = s_ntie;
    if (need > 0) {
        if (need == ntie) {
            for (int j = tid; j < need; j += 256) orow[cntgt + j] = ties[j];
        } else {
            int last = -1;
            for (int j = 0; j < need; j++) {
                int mymin = 0x7FFFFFFF;
                for (int t2 = tid; t2 < ntie; t2 += 256) {
                    int vv = ties[t2];
                    if (vv > last && vv < mymin) mymin = vv;
                }
                rmin[tid] = mymin;
                __syncthreads();
                for (int off = 128; off; off >>= 1) {
                    if (tid < off) rmin[tid] = min(rmin[tid], rmin[tid+off]);
                    __syncthreads();
                }
                if (tid == 0) { orow[cntgt + j] = rmin[0]; s_pick = rmin[0]; }
                __syncthreads();
                last = s_pick;
            }
        }
    }
}

// ---------------- bucket attention (register-tiled 4x4; q/k/v strided QKS) ----------------
__global__ void bucket_attn_kernel(const float* __restrict__ q, const float* __restrict__ k,
                                   const float* __restrict__ v, const int* __restrict__ value,
                                   const int* __restrict__ idxin, float* __restrict__ attout,
                                   float* __restrict__ cnt) {
    extern __shared__ float sm[];
    float* qb = sm;
    float* kb = qb + 64*65;
    float* vb = kb + 64*65;
    float* sc = vb + 64*65;
    __shared__ int idxs[64];
    __shared__ int kms[64];
    int blk = blockIdx.x;
    int bh = blk / CC; int h = bh % HH; int b = bh / HH;
    int tid = threadIdx.x;
    if (tid < 64) {
        int t = idxin[blk*WIN + tid];
        idxs[tid] = t;
        kms[tid] = (value[b*SS + t] != 0);
    }
    __syncthreads();
    for (int i = tid; i < 64*64; i += 256) {
        int w = i >> 6, d = i & 63;
        size_t base = ((size_t)(b*SS + idxs[w]))*QKS + h*DD + d;
        qb[w*65 + d] = q[base];
        kb[w*65 + d] = k[base];
        vb[w*65 + d] = v[base];
    }
    __syncthreads();
    int tw = (tid >> 4) * 4;
    int tx = (tid & 15) * 4;
    float a2[4][4];
#pragma unroll
    for (int i = 0; i < 4; i++)
#pragma unroll
        for (int j = 0; j < 4; j++) a2[i][j] = 0.0f;
    for (int kk = 0; kk < 64; kk++) {
        float qv[4], kv[4];
#pragma unroll
        for (int i = 0; i < 4; i++) qv[i] = qb[(tw+i)*65 + kk];
#pragma unroll
        for (int j = 0; j < 4; j++) kv[j] = kb[(tx+j)*65 + kk];
#pragma unroll
        for (int i = 0; i < 4; i++)
#pragma unroll
            for (int j = 0; j < 4; j++) a2[i][j] += qv[i]*kv[j];
    }
#pragma unroll
    for (int i = 0; i < 4; i++)
#pragma unroll
        for (int j = 0; j < 4; j++) {
            bool allowed = (idxs[tw+i] >= idxs[tx+j]) && kms[tx+j];
            sc[(tw+i)*65 + tx+j] = allowed ? a2[i][j]*0.125f : -1e9f;
        }
    __syncthreads();
    if (tid < 64) {
        float mx = -INFINITY;
        for (int xx = 0; xx < 64; xx++) mx = fmaxf(mx, sc[tid*65+xx]);
        float sum = 0.0f;
        for (int xx = 0; xx < 64; xx++) { float e = expf(sc[tid*65+xx]-mx); sc[tid*65+xx] = e; sum += e; }
        float inv = 1.0f/sum;
        for (int xx = 0; xx < 64; xx++) sc[tid*65+xx] *= inv;
    }
    __syncthreads();
    float o2[4][4];
#pragma unroll
    for (int i = 0; i < 4; i++)
#pragma unroll
        for (int j = 0; j < 4; j++) o2[i][j] = 0.0f;
    for (int xx = 0; xx < 64; xx++) {
        float sv[4], vv[4];
#pragma unroll
        for (int i = 0; i < 4; i++) sv[i] = sc[(tw+i)*65 + xx];
#pragma unroll
        for (int j = 0; j < 4; j++) vv[j] = vb[xx*65 + tx+j];
#pragma unroll
        for (int i = 0; i < 4; i++)
#pragma unroll
            for (int j = 0; j < 4; j++) o2[i][j] += sv[i]*vv[j];
    }
#pragma unroll
    for (int i = 0; i < 4; i++)
#pragma unroll
        for (int j = 0; j < 4; j++)
            atomicAdd(&attout[((size_t)(b*SS + idxs[tw+i]))*EE + h*DD + tx+j], o2[i][j]);
    if (tid < 64) atomicAdd(&cnt[(size_t)(b*SS + idxs[tid])*HH + h], 1.0f);
}

// ---------------- scatter-mean normalization -> split bf16 ----------------
__global__ void norm_attout_kernel(const float* __restrict__ attout, const float* __restrict__ cnt,
                                   __nv_bfloat16* __restrict__ oh, __nv_bfloat16* __restrict__ ol) {
    int i = blockIdx.x*256 + threadIdx.x;
    int row = i >> 9;
    int h = (i & 511) >> 6;
    float c = cnt[(size_t)row*HH + h];
    float val = attout[i] / fmaxf(c, 1.0f);
    __nv_bfloat16 hh2, ll2;
    split1(val, hh2, ll2);
    oh[i] = hh2; ol[i] = ll2;
}

// ---------------- head: logits = x @ head_w.T  (N=17), warp per row ----------------
__global__ void head_kernel(const float* __restrict__ x, const float* __restrict__ hw,
                            float* __restrict__ out) {
    int gw = (blockIdx.x*256 + threadIdx.x) >> 5;
    int lane = threadIdx.x & 31;
    if (gw >= MM) return;
    const float* xp = x + (size_t)gw*EE;
    float xr[16];
#pragma unroll
    for (int i = 0; i < 16; i++) xr[i] = xp[lane + i*32];
    for (int o = 0; o < NVOC; o++) {
        const float* w = hw + o*EE;
        float s = 0.0f;
#pragma unroll
        for (int i = 0; i < 16; i++) s += xr[i]*w[lane + i*32];
#pragma unroll
        for (int off = 16; off; off >>= 1) s += __shfl_xor_sync(0xffffffffu, s, off);
        if (lane == 0) out[(size_t)gw*NVOC + o] = s;
    }
}

// ---------------- host orchestration ----------------
extern "C" void kernel_launch(void* const* d_in, const int* in_sizes, int n_in,
                              void* d_out, int out_size) {
    const int*   value     = (const int*)d_in[0];
    const int*   depth     = (const int*)d_in[1];
    const int*   pos       = (const int*)d_in[2];
    const float* sos       = (const float*)d_in[3];
    const float* tok_emb   = (const float*)d_in[4];
    const float* depth_emb = (const float*)d_in[5];
    const float* pos_emb   = (const float*)d_in[6];
    const float* ln1_s     = (const float*)d_in[7];
    const float* ln1_b     = (const float*)d_in[8];
    const float* Wq        = (const float*)d_in[9];
    const float* Wk        = (const float*)d_in[10];
    const float* Wv        = (const float*)d_in[11];
    const float* Wo        = (const float*)d_in[12];
    const float* means     = (const float*)d_in[13];
    const float* ln2_s     = (const float*)d_in[14];
    const float* ln2_b     = (const float*)d_in[15];
    const float* W1        = (const float*)d_in[16];
    const float* b1        = (const float*)d_in[17];
    const float* W2        = (const float*)d_in[18];
    const float* b2        = (const float*)d_in[19];
    const float* head_w    = (const float*)d_in[20];
    float* out = (float*)d_out;

    float *x, *qkv, *dists, *attout, *cnt;
    int* idxb;
    __nv_bfloat16 *hh, *hl, *th, *tl, *aoh, *aol;
    uint32_t *Wqkvh, *Wqkvl, *Woh, *Wol, *W1h, *W1l, *W2h, *W2l;
    cudaGetSymbolAddress((void**)&x, g_x);
    cudaGetSymbolAddress((void**)&qkv, g_qkv);
    cudaGetSymbolAddress((void**)&dists, g_dists);
    cudaGetSymbolAddress((void**)&idxb, g_idx);
    cudaGetSymbolAddress((void**)&attout, g_attout);
    cudaGetSymbolAddress((void**)&cnt, g_cnt);
    cudaGetSymbolAddress((void**)&hh, g_hh);   cudaGetSymbolAddress((void**)&hl, g_hl);
    cudaGetSymbolAddress((void**)&th, g_th);   cudaGetSymbolAddress((void**)&tl, g_tl);
    cudaGetSymbolAddress((void**)&aoh, g_aoh); cudaGetSymbolAddress((void**)&aol, g_aol);
    cudaGetSymbolAddress((void**)&Wqkvh, g_Wqkvh); cudaGetSymbolAddress((void**)&Wqkvl, g_Wqkvl);
    cudaGetSymbolAddress((void**)&Woh, g_Woh); cudaGetSymbolAddress((void**)&Wol, g_Wol);
    cudaGetSymbolAddress((void**)&W1h, g_W1h); cudaGetSymbolAddress((void**)&W1l, g_W1l);
    cudaGetSymbolAddress((void**)&W2h, g_W2h); cudaGetSymbolAddress((void**)&W2l, g_W2l);

    const int ATTN_SMEM = 4 * 64 * 65 * (int)sizeof(float);
    cudaFuncSetAttribute(bucket_attn_kernel, cudaFuncAttributeMaxDynamicSharedMemorySize, ATTN_SMEM);
    const int DIST_SMEM = (128*65 + 64*64 + 64 + 128) * (int)sizeof(float);
    cudaFuncSetAttribute(dist_kernel, cudaFuncAttributeMaxDynamicSharedMemorySize, DIST_SMEM);
    cudaFuncSetAttribute(bf3_gemm<0,0,false>, cudaFuncAttributeMaxDynamicSharedMemorySize, GEMM_SMEM);
    cudaFuncSetAttribute(bf3_gemm<0,1,false>, cudaFuncAttributeMaxDynamicSharedMemorySize, GEMM_SMEM);
    cudaFuncSetAttribute(bf3_gemm<1,2,true>,  cudaFuncAttributeMaxDynamicSharedMemorySize, GEMM_SMEM);
    cudaFuncSetAttribute(bf3_gemm<0,1,true>,  cudaFuncAttributeMaxDynamicSharedMemorySize, GEMM_SMEM);

    // weight splits (pair-interleaved, once per launch)
    split_qkv_pi_kernel<<<(LL*(EE/2)*QKS/4 + 255)/256, 256>>>(Wq, Wk, Wv, Wqkvh, Wqkvl);
    split_pi_kernel<<<(LL*(EE/2)*EE/4 + 255)/256, 256>>>(Wo, Woh, Wol, EE, EE, LL*(EE/2)*EE/4);
    split_pi_kernel<<<(LL*(EE/2)*FF/4 + 255)/256, 256>>>(W1, W1h, W1l, EE, FF, LL*(EE/2)*FF/4);
    split_pi_kernel<<<(LL*(FF/2)*EE/4 + 255)/256, 256>>>(W2, W2h, W2l, FF, EE, LL*(FF/2)*EE/4);

    embed_kernel<<<MM, 128>>>(value, depth, pos, sos, tok_emb, depth_emb, pos_emb, x);

    dim3 gE(EE/128, MM/128);     // 4 x 128
    dim3 gQ(QKS/128, MM/128);    // 12 x 128
    dim3 gF(FF/128, MM/128);     // 16 x 128
    dim3 gD(SS/128, BB*HH);      // 32 x 32

    for (int l = 0; l < LL; l++) {
        size_t oQ = (size_t)l*(EE/2)*QKS;
        size_t oE = (size_t)l*(EE/2)*EE;
        size_t oF1 = (size_t)l*(EE/2)*FF;
        size_t oF2 = (size_t)l*(FF/2)*EE;
        const float* ml = means + (size_t)l*HH*CC*DD;
        float* q = qkv;
        float* k = qkv + EE;
        float* v = qkv + 2*EE;

        ln_kernel<<<MM/8, 256>>>(x, ln1_s + l*EE, ln1_b + l*EE, hh, hl);
        bf3_gemm<0,0,false><<<gQ, 256, GEMM_SMEM>>>(hh, hl, Wqkvh+oQ, Wqkvl+oQ, nullptr, qkv, nullptr, nullptr, MM, QKS, EE);

        dist_kernel<<<gD, 256, DIST_SMEM>>>(q, ml, dists);
        topk_kernel<<<BB*HH*CC, 256>>>(dists, idxb);

        cudaMemsetAsync(attout, 0, (size_t)MM*EE*sizeof(float));
        cudaMemsetAsync(cnt, 0, (size_t)MM*HH*sizeof(float));
        bucket_attn_kernel<<<BB*HH*CC, 256, ATTN_SMEM>>>(q, k, v, value, idxb, attout, cnt);
        norm_attout_kernel<<<(MM*EE)/256, 256>>>(attout, cnt, aoh, aol);

        bf3_gemm<0,1,false><<<gE, 256, GEMM_SMEM>>>(aoh, aol, Woh+oE, Wol+oE, nullptr, x, nullptr, nullptr, MM, EE, EE);

        ln_kernel<<<MM/8, 256>>>(x, ln2_s + l*EE, ln2_b + l*EE, hh, hl);
        bf3_gemm<1,2,true><<<gF, 256, GEMM_SMEM>>>(hh, hl, W1h+oF1, W1l+oF1, b1 + l*FF, nullptr, th, tl, MM, FF, EE);
        bf3_gemm<0,1,true><<<gE, 256, GEMM_SMEM>>>(th, tl, W2h+oF2, W2l+oF2, b2 + l*EE, x, nullptr, nullptr, MM, EE, FF);
    }

    head_kernel<<<MM/8, 256>>>(x, head_w, out);
}

// round 9
// speedup vs baseline: 2.9289x; 1.0067x over previous
#include <cuda_runtime.h>
#include <cuda_bf16.h>
#include <math.h>
#include <stdint.h>

// ---------------- problem constants ----------------
#define BB 4
#define SS 4096
#define EE 512
#define HH 8
#define LL 4
#define AA 3
#define WIN 64
#define CC 64           // S / WIN clusters
#define DD 64           // E / H
#define MM (BB*SS)      // 16384 rows
#define FF (4*EE)       // 2048 ffn dim
#define QKS (3*EE)      // fused qkv row stride 1536
#define NVOC 17

// ---------------- scratch (device globals; no allocation allowed) ----------------
__device__ float g_x[MM*EE];
__device__ float g_qkv[MM*QKS];
__device__ float g_dists[BB*HH*CC*SS];
__device__ int   g_idx[BB*HH*CC*WIN];
__device__ float g_attout[MM*EE];
__device__ float g_cnt[MM*HH];
// split activations (A operands)
__device__ __nv_bfloat16 g_hh[MM*EE],  g_hl[MM*EE];
__device__ __nv_bfloat16 g_th[MM*FF],  g_tl[MM*FF];
__device__ __nv_bfloat16 g_aoh[MM*EE], g_aol[MM*EE];
// split weights, pair-interleaved: uint32 [K/2][N] per layer
__device__ uint32_t g_Wqkvh[LL*(EE/2)*QKS], g_Wqkvl[LL*(EE/2)*QKS];
__device__ uint32_t g_Woh[LL*(EE/2)*EE],    g_Wol[LL*(EE/2)*EE];
__device__ uint32_t g_W1h[LL*(EE/2)*FF],    g_W1l[LL*(EE/2)*FF];
__device__ uint32_t g_W2h[LL*(FF/2)*EE],    g_W2l[LL*(FF/2)*EE];

// ---------------- bf16 split helpers ----------------
__device__ __forceinline__ uint32_t packbf(float x, float y) {
    __nv_bfloat162 t = __floats2bfloat162_rn(x, y);
    return *reinterpret_cast<uint32_t*>(&t);
}
__device__ __forceinline__ void split2(float x, float y, uint32_t& hi, uint32_t& lo) {
    float xh = __bfloat162float(__float2bfloat16(x));
    float yh = __bfloat162float(__float2bfloat16(y));
    hi = packbf(x, y);
    lo = packbf(x - xh, y - yh);
}
__device__ __forceinline__ void split1(float x, __nv_bfloat16& h, __nv_bfloat16& l) {
    h = __float2bfloat16(x);
    l = __float2bfloat16(x - __bfloat162float(h));
}

// ---------------- weight split prep (pair-interleaved) ----------------
__global__ void split_pi_kernel(const float* __restrict__ W, uint32_t* __restrict__ PIh,
                                uint32_t* __restrict__ PIl, int K, int N, int n4total) {
    int gid = blockIdx.x*256 + threadIdx.x;
    if (gid >= n4total) return;
    int i = gid*4;
    int c = i % N;
    int rest = i / N;
    int p = rest % (K/2);
    int l = rest / (K/2);
    const float* w0 = W + ((size_t)l*K + 2*p)*N + c;
    float4 v0 = *(const float4*)w0;
    float4 v1 = *(const float4*)(w0 + N);
    uint32_t h0,l0,h1,l1,h2,l2,h3,l3;
    split2(v0.x, v1.x, h0, l0);
    split2(v0.y, v1.y, h1, l1);
    split2(v0.z, v1.z, h2, l2);
    split2(v0.w, v1.w, h3, l3);
    size_t o = ((size_t)l*(K/2) + p)*N + c;
    *(uint4*)(PIh + o) = make_uint4(h0,h1,h2,h3);
    *(uint4*)(PIl + o) = make_uint4(l0,l1,l2,l3);
}

__global__ void split_qkv_pi_kernel(const float* __restrict__ Wq, const float* __restrict__ Wk,
                                    const float* __restrict__ Wv,
                                    uint32_t* __restrict__ PIh, uint32_t* __restrict__ PIl) {
    int gid = blockIdx.x*256 + threadIdx.x;
    int i = gid*4;
    if (i >= LL*(EE/2)*QKS) return;
    int c = i % QKS;
    int rest = i / QKS;
    int p = rest % (EE/2);
    int l = rest / (EE/2);
    const float* src; int cc = c;
    if (c < EE) src = Wq;
    else if (c < 2*EE) { src = Wk; cc = c - EE; }
    else { src = Wv; cc = c - 2*EE; }
    const float* w0 = src + ((size_t)l*EE + 2*p)*EE + cc;
    float4 v0 = *(const float4*)w0;
    float4 v1 = *(const float4*)(w0 + EE);
    uint32_t h0,l0,h1,l1,h2,l2,h3,l3;
    split2(v0.x, v1.x, h0, l0);
    split2(v0.y, v1.y, h1, l1);
    split2(v0.z, v1.z, h2, l2);
    split2(v0.w, v1.w, h3, l3);
    size_t o = ((size_t)l*(EE/2) + p)*QKS + c;
    *(uint4*)(PIh + o) = make_uint4(h0,h1,h2,h3);
    *(uint4*)(PIl + o) = make_uint4(l0,l1,l2,l3);
}

// ---------------- embedding + shift-right ----------------
__global__ void embed_kernel(const int* __restrict__ value, const int* __restrict__ depth,
                             const int* __restrict__ pos, const float* __restrict__ sos,
                             const float* __restrict__ tok, const float* __restrict__ dep,
                             const float* __restrict__ pemb, float* __restrict__ x) {
    int row = blockIdx.x;
    int t = row & (SS - 1);
    if (t == 0) {
        for (int e = threadIdx.x; e < EE; e += blockDim.x) x[(size_t)row*EE + e] = sos[e];
        return;
    }
    int pr = row - 1;
    int v  = value[pr], dp = depth[pr];
    int p0 = pos[pr*AA+0], p1 = pos[pr*AA+1], p2 = pos[pr*AA+2];
    for (int e = threadIdx.x; e < EE; e += blockDim.x) {
        float s = tok[v*EE+e] + dep[dp*EE+e]
                + pemb[(0*65 + p0)*EE + e]
                + pemb[(1*65 + p1)*EE + e]
                + pemb[(2*65 + p2)*EE + e];
        x[(size_t)row*EE + e] = s;
    }
}

// ---------------- layernorm: warp per row, no smem ----------------
__global__ void ln_kernel(const float* __restrict__ x, const float* __restrict__ sc,
                          const float* __restrict__ bi,
                          __nv_bfloat16* __restrict__ oh, __nv_bfloat16* __restrict__ ol) {
    int warp = threadIdx.x >> 5, lane = threadIdx.x & 31;
    int row = blockIdx.x*8 + warp;
    const float4* xr = (const float4*)(x + (size_t)row*EE);
    float4 v[4];
    float s = 0.0f, q2 = 0.0f;
#pragma unroll
    for (int i = 0; i < 4; i++) {
        v[i] = xr[lane + 32*i];
        s  += v[i].x + v[i].y + v[i].z + v[i].w;
        q2 += v[i].x*v[i].x + v[i].y*v[i].y + v[i].z*v[i].z + v[i].w*v[i].w;
    }
#pragma unroll
    for (int o = 16; o; o >>= 1) {
        s  += __shfl_xor_sync(0xffffffffu, s, o);
        q2 += __shfl_xor_sync(0xffffffffu, q2, o);
    }
    float m = s * (1.0f/EE);
    float r = rsqrtf(q2 * (1.0f/EE) - m*m + 1e-5f);
#pragma unroll
    for (int i = 0; i < 4; i++) {
        int c4 = (lane + 32*i) * 4;
        float y0 = (v[i].x - m)*r*sc[c4+0] + bi[c4+0];
        float y1 = (v[i].y - m)*r*sc[c4+1] + bi[c4+1];
        float y2 = (v[i].z - m)*r*sc[c4+2] + bi[c4+2];
        float y3 = (v[i].w - m)*r*sc[c4+3] + bi[c4+3];
        uint32_t hA, lA, hB, lB;
        split2(y0, y1, hA, lA);
        split2(y2, y3, hB, lB);
        *(uint2*)(oh + (size_t)row*EE + c4) = make_uint2(hA, hB);
        *(uint2*)(ol + (size_t)row*EE + c4) = make_uint2(lA, lB);
    }
}

// ---------------- gelu ----------------
__device__ __forceinline__ float gelu_f(float x) {
    float x3 = x*x*x;
    return 0.5f*x*(1.0f + tanhf(0.7978845608028654f*(x + 0.044715f*x3)));
}

__device__ __forceinline__ void mma_bf16(float d[4], const uint32_t a[4], const uint32_t b[2]) {
    asm volatile(
        "mma.sync.aligned.m16n8k16.row.col.f32.bf16.bf16.f32 "
        "{%0,%1,%2,%3}, {%4,%5,%6,%7}, {%8,%9}, {%0,%1,%2,%3};\n"
        : "+f"(d[0]), "+f"(d[1]), "+f"(d[2]), "+f"(d[3])
        : "r"(a[0]), "r"(a[1]), "r"(a[2]), "r"(a[3]), "r"(b[0]), "r"(b[1]));
}

__device__ __forceinline__ void ldsm4(uint32_t f[4], uint32_t smaddr) {
    asm volatile("ldmatrix.sync.aligned.m8n8.x4.shared.b16 {%0,%1,%2,%3}, [%4];"
                 : "=r"(f[0]), "=r"(f[1]), "=r"(f[2]), "=r"(f[3]) : "r"(smaddr));
}

__device__ __forceinline__ void cpa16(uint32_t dst, const void* src) {
    asm volatile("cp.async.cg.shared.global [%0], [%1], 16;" :: "r"(dst), "l"(src));
}
#define CP_COMMIT() asm volatile("cp.async.commit_group;")
#define CP_WAIT2()  asm volatile("cp.async.wait_group 2;")

// ---------------- split-bf16 tensor GEMM: 4-stage cp.async pipeline ----------------
#define AST 12
#define BST 136
#define STA (128*AST)
#define STB (8*BST)
#define NSTG 4
#define GEMM_SMEM ((NSTG*(STA*2 + STB*2))*4)

template<int ACT, int OUTMODE, bool HASB>
__global__ void __launch_bounds__(256,2) bf3_gemm(
    const __nv_bfloat16* __restrict__ Ah, const __nv_bfloat16* __restrict__ Al,
    const uint32_t* __restrict__ Bh, const uint32_t* __restrict__ Bl,
    const float* __restrict__ bias,
    float* __restrict__ C,
    __nv_bfloat16* __restrict__ Ch, __nv_bfloat16* __restrict__ Cl,
    int M, int N, int K)
{
    extern __shared__ uint32_t gsm[];
    uint32_t* AsH = gsm;
    uint32_t* AsL = AsH + NSTG*STA;
    uint32_t* BsH = AsL + NSTG*STA;
    uint32_t* BsL = BsH + NSTG*STB;

    int tid = threadIdx.x;
    int lane = tid & 31;
    int warp = tid >> 5;
    int wm = (warp >> 2) * 64;
    int wn = (warp & 3) * 32;
    int bm = blockIdx.y * 128, bn = blockIdx.x * 128;

    float acc[4][4][4];
#pragma unroll
    for (int mi = 0; mi < 4; mi++)
#pragma unroll
        for (int ni = 0; ni < 4; ni++)
#pragma unroll
            for (int r = 0; r < 4; r++) acc[mi][ni][r] = 0.0f;

    int a_r = tid >> 1, a_h = (tid & 1) * 8;
    int b_p = tid >> 5, b_cg = (tid & 31) * 4;
    const __nv_bfloat16* Abh = Ah + (size_t)bm*K + (size_t)a_r*K + a_h;
    const __nv_bfloat16* Abl = Al + (size_t)bm*K + (size_t)a_r*K + a_h;
    const uint32_t* Bbh = Bh + (size_t)b_p*N + bn + b_cg;
    const uint32_t* Bbl = Bl + (size_t)b_p*N + bn + b_cg;

    uint32_t awH = (uint32_t)__cvta_generic_to_shared(AsH) + (a_r*AST + (a_h>>1))*4;
    uint32_t awL = (uint32_t)__cvta_generic_to_shared(AsL) + (a_r*AST + (a_h>>1))*4;
    uint32_t bwH = (uint32_t)__cvta_generic_to_shared(BsH) + (b_p*BST + b_cg)*4;
    uint32_t bwL = (uint32_t)__cvta_generic_to_shared(BsL) + (b_p*BST + b_cg)*4;

    int nk = K / 16;

#define ISSUE(S, K0)                                              \
    {                                                             \
        cpa16(awH + (S)*STA*4, Abh + (K0));                       \
        cpa16(awL + (S)*STA*4, Abl + (K0));                       \
        cpa16(bwH + (S)*STB*4, Bbh + (size_t)((K0)>>1)*N);        \
        cpa16(bwL + (S)*STB*4, Bbl + (size_t)((K0)>>1)*N);        \
    }

    ISSUE(0, 0)  CP_COMMIT();
    ISSUE(1, 16) CP_COMMIT();
    ISSUE(2, 32) CP_COMMIT();

    int l_row = wm + (lane & 7) + ((lane >> 3) & 1) * 8;
    int l_kp  = ((lane >> 4) & 1) * 4;
    uint32_t aoffH = (uint32_t)__cvta_generic_to_shared(AsH) + (l_row*AST + l_kp)*4;
    uint32_t aoffL = (uint32_t)__cvta_generic_to_shared(AsL) + (l_row*AST + l_kp)*4;

    int bc0 = wn + (lane >> 2);
    int bp0 = lane & 3;

    for (int it = 0; it < nk; it++) {
        int buf = it & (NSTG-1);
        CP_WAIT2();
        __syncthreads();
        uint32_t afh[4][4], afl[4][4], bfh[4][2], bfl[4][2];
        uint32_t aH = aoffH + (uint32_t)buf*STA*4;
        uint32_t aL = aoffL + (uint32_t)buf*STA*4;
#pragma unroll
        for (int mi = 0; mi < 4; mi++) {
            ldsm4(afh[mi], aH + (uint32_t)(mi*16*AST*4));
            ldsm4(afl[mi], aL + (uint32_t)(mi*16*AST*4));
        }
        const uint32_t* bsH = BsH + buf*STB;
        const uint32_t* bsL = BsL + buf*STB;
#pragma unroll
        for (int ni = 0; ni < 4; ni++) {
            int base = bp0*BST + bc0 + ni*8;
            bfh[ni][0] = bsH[base];
            bfh[ni][1] = bsH[base + 4*BST];
            bfl[ni][0] = bsL[base];
            bfl[ni][1] = bsL[base + 4*BST];
        }
        if (it + 3 < nk) ISSUE((it+3) & (NSTG-1), (it+3)*16)
        CP_COMMIT();
#pragma unroll
        for (int mi = 0; mi < 4; mi++)
#pragma unroll
            for (int ni = 0; ni < 4; ni++) {
                mma_bf16(acc[mi][ni], afl[mi], bfh[ni]);
                mma_bf16(acc[mi][ni], afh[mi], bfl[ni]);
                mma_bf16(acc[mi][ni], afh[mi], bfh[ni]);
            }
    }

#pragma unroll
    for (int mi = 0; mi < 4; mi++) {
        int r0 = bm + wm + mi*16 + (lane >> 2);
#pragma unroll
        for (int ni = 0; ni < 4; ni++) {
            int c0 = bn + wn + ni*8 + (lane & 3)*2;
            float* a = acc[mi][ni];
#pragma unroll
            for (int hr = 0; hr < 2; hr++) {
                int r = r0 + hr*8;
                float v0 = a[hr*2 + 0], v1 = a[hr*2 + 1];
                if (HASB) { v0 += bias[c0]; v1 += bias[c0+1]; }
                if (ACT == 1) { v0 = gelu_f(v0); v1 = gelu_f(v1); }
                size_t o = (size_t)r*N + c0;
                if (OUTMODE == 0) {
                    float2 t2; t2.x = v0; t2.y = v1;
                    *(float2*)&C[o] = t2;
                } else if (OUTMODE == 1) {
                    float2 old = *(float2*)&C[o];
                    old.x += v0; old.y += v1;
                    *(float2*)&C[o] = old;
                } else {
                    uint32_t hh2, ll2;
                    split2(v0, v1, hh2, ll2);
                    *(uint32_t*)&Ch[o] = hh2;
                    *(uint32_t*)&Cl[o] = ll2;
                }
            }
        }
    }
}

// ---------------- fused qnorm + cluster distances (tiled; q has QKS stride) ----------------
__global__ void dist_kernel(const float* __restrict__ q, const float* __restrict__ means_l,
                            float* __restrict__ dists) {
    extern __shared__ float dsm[];
    float* qs = dsm;
    float* ms = qs + 128*65;
    float* mn = ms + 64*64;
    float* qn = mn + 64;
    int tile = blockIdx.x;
    int bh = blockIdx.y;
    int h = bh & 7, b = bh >> 3;
    int n0 = tile * 128;
    int tid = threadIdx.x;
    for (int i = tid; i < 64*64; i += 256) ms[i] = means_l[h*64*64 + i];
    for (int i = tid; i < 128*16; i += 256) {
        int r = i >> 4, c4 = (i & 15) * 4;
        float4 v = *(const float4*)(q + ((size_t)(b*SS + n0 + r))*QKS + h*DD + c4);
        float* dst = qs + r*65 + c4;
        dst[0]=v.x; dst[1]=v.y; dst[2]=v.z; dst[3]=v.w;
    }
    __syncthreads();
    if (tid < 64) {
        float s = 0; const float* mr = ms + tid*64;
#pragma unroll 16
        for (int d = 0; d < 64; d++) s += mr[d]*mr[d];
        mn[tid] = 1.0f/(sqrtf(s) + 1e-8f);
    } else if (tid >= 128) {
        int r = tid - 128;
        float s = 0; const float* qr = qs + r*65;
#pragma unroll 16
        for (int d = 0; d < 64; d++) s += qr[d]*qr[d];
        qn[r] = 1.0f/(sqrtf(s) + 1e-8f);
    }
    __syncthreads();
    int nl = tid & 127;
    int c0 = (tid >> 7) * 32;
    float acc[32];
#pragma unroll
    for (int c = 0; c < 32; c++) acc[c] = 0.0f;
    for (int dc = 0; dc < 64; dc += 16) {
        float qreg[16];
#pragma unroll
        for (int d = 0; d < 16; d++) qreg[d] = qs[nl*65 + dc + d];
#pragma unroll
        for (int c = 0; c < 32; c++) {
            const float* mr = ms + (c0 + c)*64 + dc;
            float s = acc[c];
#pragma unroll
            for (int d = 0; d < 16; d++) s += qreg[d]*mr[d];
            acc[c] = s;
        }
    }
    float qi = qn[nl];
#pragma unroll
    for (int c = 0; c < 32; c++) {
        int cc = c0 + c;
        dists[((size_t)bh*CC + cc)*SS + n0 + nl] = acc[c]*mn[cc]*qi;
    }
}

// ---------------- radix-select top-64 (exact, ties -> smallest index) ----------------
__global__ void topk_kernel(const float* __restrict__ dists, int* __restrict__ idxout) {
    __shared__ uint32_t keys[SS];
    __shared__ int hist[256];
    __shared__ int ties[SS];
    __shared__ int rmin[256];
    __shared__ int s_chosen, s_rem, s_cntgt, s_ntie, s_pick;
    int blk = blockIdx.x, tid = threadIdx.x;
    const float* drow = dists + (size_t)blk*SS;
    for (int n = tid; n < SS; n += 256) {
        uint32_t u = __float_as_uint(drow[n]);
        keys[n] = (u & 0x80000000u) ? ~u : (u | 0x80000000u);
    }
    uint32_t prefix = 0, maskhi = 0;
    int rem = WIN;
    for (int p = 0; p < 4; p++) {
        int shift = 24 - 8*p;
        hist[tid] = 0;
        __syncthreads();
        for (int n = tid; n < SS; n += 256) {
            uint32_t kk = keys[n];
            if ((kk & maskhi) == prefix) atomicAdd(&hist[(kk >> shift) & 255], 1);
        }
        __syncthreads();
        if (tid == 0) {
            int cum = 0, bsel = 255;
            for (; bsel >= 0; bsel--) { cum += hist[bsel]; if (cum >= rem) break; }
            s_chosen = bsel; s_rem = rem - (cum - hist[bsel]);
        }
        __syncthreads();
        prefix |= ((uint32_t)s_chosen) << shift;
        maskhi |= 0xFFu << shift;
        rem = s_rem;
        __syncthreads();
    }
    uint32_t T = prefix;
    if (tid == 0) { s_cntgt = 0; s_ntie = 0; }
    __syncthreads();
    int* orow = idxout + blk*WIN;
    for (int n = tid; n < SS; n += 256) {
        uint32_t kk = keys[n];
        if (kk > T) { int pp = atomicAdd(&s_cntgt, 1); orow[pp] = n; }
        else if (kk == T) { int pp = atomicAdd(&s_ntie, 1); ties[pp] = n; }
    }
    __syncthreads();
    int cntgt = s_cntgt;
    int need = WIN - cntgt;
    int ntie = s_ntie;
    if (need > 0) {
        if (need == ntie) {
            for (int j = tid; j < need; j += 256) orow[cntgt + j] = ties[j];
        } else {
            int last = -1;
            for (int j = 0; j < need; j++) {
                int mymin = 0x7FFFFFFF;
                for (int t2 = tid; t2 < ntie; t2 += 256) {
                    int vv = ties[t2];
                    if (vv > last && vv < mymin) mymin = vv;
                }
                rmin[tid] = mymin;
                __syncthreads();
                for (int off = 128; off; off >>= 1) {
                    if (tid < off) rmin[tid] = min(rmin[tid], rmin[tid+off]);
                    __syncthreads();
                }
                if (tid == 0) { orow[cntgt + j] = rmin[0]; s_pick = rmin[0]; }
                __syncthreads();
                last = s_pick;
            }
        }
    }
}

// ---------------- bucket attention (register-tiled 4x4; parallel softmax) ----------------
__global__ void bucket_attn_kernel(const float* __restrict__ q, const float* __restrict__ k,
                                   const float* __restrict__ v, const int* __restrict__ value,
                                   const int* __restrict__ idxin, float* __restrict__ attout,
                                   float* __restrict__ cnt) {
    extern __shared__ float sm[];
    float* qb = sm;
    float* kb = qb + 64*65;
    float* vb = kb + 64*65;
    float* sc = vb + 64*65;
    __shared__ int idxs[64];
    __shared__ int kms[64];
    int blk = blockIdx.x;
    int bh = blk / CC; int h = bh % HH; int b = bh / HH;
    int tid = threadIdx.x;
    if (tid < 64) {
        int t = idxin[blk*WIN + tid];
        idxs[tid] = t;
        kms[tid] = (value[b*SS + t] != 0);
    }
    __syncthreads();
    for (int i = tid; i < 64*64; i += 256) {
        int w = i >> 6, d = i & 63;
        size_t base = ((size_t)(b*SS + idxs[w]))*QKS + h*DD + d;
        qb[w*65 + d] = q[base];
        kb[w*65 + d] = k[base];
        vb[w*65 + d] = v[base];
    }
    __syncthreads();
    int tw = (tid >> 4) * 4;
    int tx = (tid & 15) * 4;
    float a2[4][4];
#pragma unroll
    for (int i = 0; i < 4; i++)
#pragma unroll
        for (int j = 0; j < 4; j++) a2[i][j] = 0.0f;
    for (int kk = 0; kk < 64; kk++) {
        float qv[4], kv[4];
#pragma unroll
        for (int i = 0; i < 4; i++) qv[i] = qb[(tw+i)*65 + kk];
#pragma unroll
        for (int j = 0; j < 4; j++) kv[j] = kb[(tx+j)*65 + kk];
#pragma unroll
        for (int i = 0; i < 4; i++)
#pragma unroll
            for (int j = 0; j < 4; j++) a2[i][j] += qv[i]*kv[j];
    }
#pragma unroll
    for (int i = 0; i < 4; i++)
#pragma unroll
        for (int j = 0; j < 4; j++) {
            bool allowed = (idxs[tw+i] >= idxs[tx+j]) && kms[tx+j];
            sc[(tw+i)*65 + tx+j] = allowed ? a2[i][j]*0.125f : -1e9f;
        }
    __syncthreads();
    // parallel softmax: 4 threads per row (row = tid>>2, cols (tid&3)*16 .. +16)
    {
        int row = tid >> 2;
        int c0 = (tid & 3) * 16;
        float* sr = sc + row*65 + c0;
        float mx = -INFINITY;
#pragma unroll
        for (int j = 0; j < 16; j++) mx = fmaxf(mx, sr[j]);
        mx = fmaxf(mx, __shfl_xor_sync(0xffffffffu, mx, 1));
        mx = fmaxf(mx, __shfl_xor_sync(0xffffffffu, mx, 2));
        float e[16];
        float sum = 0.0f;
#pragma unroll
        for (int j = 0; j < 16; j++) { e[j] = __expf(sr[j] - mx); sum += e[j]; }
        sum += __shfl_xor_sync(0xffffffffu, sum, 1);
        sum += __shfl_xor_sync(0xffffffffu, sum, 2);
        float inv = 1.0f / sum;
#pragma unroll
        for (int j = 0; j < 16; j++) sr[j] = e[j] * inv;
    }
    __syncthreads();
    float o2[4][4];
#pragma unroll
    for (int i = 0; i < 4; i++)
#pragma unroll
        for (int j = 0; j < 4; j++) o2[i][j] = 0.0f;
    for (int xx = 0; xx < 64; xx++) {
        float sv[4], vv[4];
#pragma unroll
        for (int i = 0; i < 4; i++) sv[i] = sc[(tw+i)*65 + xx];
#pragma unroll
        for (int j = 0; j < 4; j++) vv[j] = vb[xx*65 + tx+j];
#pragma unroll
        for (int i = 0; i < 4; i++)
#pragma unroll
            for (int j = 0; j < 4; j++) o2[i][j] += sv[i]*vv[j];
    }
#pragma unroll
    for (int i = 0; i < 4; i++)
#pragma unroll
        for (int j = 0; j < 4; j++)
            atomicAdd(&attout[((size_t)(b*SS + idxs[tw+i]))*EE + h*DD + tx+j], o2[i][j]);
    if (tid < 64) atomicAdd(&cnt[(size_t)(b*SS + idxs[tid])*HH + h], 1.0f);
}

// ---------------- scatter-mean normalization -> split bf16; zeroes attout/cnt in place ----------------
__global__ void norm_attout_kernel(float* __restrict__ attout, float* __restrict__ cnt,
                                   __nv_bfloat16* __restrict__ oh, __nv_bfloat16* __restrict__ ol) {
    int i = blockIdx.x*256 + threadIdx.x;
    int row = i >> 9;
    int h = (i & 511) >> 6;
    float c = cnt[(size_t)row*HH + h];
    float val = attout[i] / fmaxf(c, 1.0f);
    __nv_bfloat16 hh2, ll2;
    split1(val, hh2, ll2);
    oh[i] = hh2; ol[i] = ll2;
    attout[i] = 0.0f;                 // re-zero for next layer (same thread, safe)
    __syncthreads();                  // all cnt reads in this block complete
    if ((i & 63) == 0) cnt[(size_t)row*HH + h] = 0.0f;
}

// ---------------- head: logits = x @ head_w.T  (N=17), warp per row ----------------
__global__ void head_kernel(const float* __restrict__ x, const float* __restrict__ hw,
                            float* __restrict__ out) {
    int gw = (blockIdx.x*256 + threadIdx.x) >> 5;
    int lane = threadIdx.x & 31;
    if (gw >= MM) return;
    const float* xp = x + (size_t)gw*EE;
    float xr[16];
#pragma unroll
    for (int i = 0; i < 16; i++) xr[i] = xp[lane + i*32];
    for (int o = 0; o < NVOC; o++) {
        const float* w = hw + o*EE;
        float s = 0.0f;
#pragma unroll
        for (int i = 0; i < 16; i++) s += xr[i]*w[lane + i*32];
#pragma unroll
        for (int off = 16; off; off >>= 1) s += __shfl_xor_sync(0xffffffffu, s, off);
        if (lane == 0) out[(size_t)gw*NVOC + o] = s;
    }
}

// ---------------- host orchestration ----------------
extern "C" void kernel_launch(void* const* d_in, const int* in_sizes, int n_in,
                              void* d_out, int out_size) {
    const int*   value     = (const int*)d_in[0];
    const int*   depth     = (const int*)d_in[1];
    const int*   pos       = (const int*)d_in[2];
    const float* sos       = (const float*)d_in[3];
    const float* tok_emb   = (const float*)d_in[4];
    const float* depth_emb = (const float*)d_in[5];
    const float* pos_emb   = (const float*)d_in[6];
    const float* ln1_s     = (const float*)d_in[7];
    const float* ln1_b     = (const float*)d_in[8];
    const float* Wq        = (const float*)d_in[9];
    const float* Wk        = (const float*)d_in[10];
    const float* Wv        = (const float*)d_in[11];
    const float* Wo        = (const float*)d_in[12];
    const float* means     = (const float*)d_in[13];
    const float* ln2_s     = (const float*)d_in[14];
    const float* ln2_b     = (const float*)d_in[15];
    const float* W1        = (const float*)d_in[16];
    const float* b1        = (const float*)d_in[17];
    const float* W2        = (const float*)d_in[18];
    const float* b2        = (const float*)d_in[19];
    const float* head_w    = (const float*)d_in[20];
    float* out = (float*)d_out;

    float *x, *qkv, *dists, *attout, *cnt;
    int* idxb;
    __nv_bfloat16 *hh, *hl, *th, *tl, *aoh, *aol;
    uint32_t *Wqkvh, *Wqkvl, *Woh, *Wol, *W1h, *W1l, *W2h, *W2l;
    cudaGetSymbolAddress((void**)&x, g_x);
    cudaGetSymbolAddress((void**)&qkv, g_qkv);
    cudaGetSymbolAddress((void**)&dists, g_dists);
    cudaGetSymbolAddress((void**)&idxb, g_idx);
    cudaGetSymbolAddress((void**)&attout, g_attout);
    cudaGetSymbolAddress((void**)&cnt, g_cnt);
    cudaGetSymbolAddress((void**)&hh, g_hh);   cudaGetSymbolAddress((void**)&hl, g_hl);
    cudaGetSymbolAddress((void**)&th, g_th);   cudaGetSymbolAddress((void**)&tl, g_tl);
    cudaGetSymbolAddress((void**)&aoh, g_aoh); cudaGetSymbolAddress((void**)&aol, g_aol);
    cudaGetSymbolAddress((void**)&Wqkvh, g_Wqkvh); cudaGetSymbolAddress((void**)&Wqkvl, g_Wqkvl);
    cudaGetSymbolAddress((void**)&Woh, g_Woh); cudaGetSymbolAddress((void**)&Wol, g_Wol);
    cudaGetSymbolAddress((void**)&W1h, g_W1h); cudaGetSymbolAddress((void**)&W1l, g_W1l);
    cudaGetSymbolAddress((void**)&W2h, g_W2h); cudaGetSymbolAddress((void**)&W2l, g_W2l);

    const int ATTN_SMEM = 4 * 64 * 65 * (int)sizeof(float);
    cudaFuncSetAttribute(bucket_attn_kernel, cudaFuncAttributeMaxDynamicSharedMemorySize, ATTN_SMEM);
    const int DIST_SMEM = (128*65 + 64*64 + 64 + 128) * (int)sizeof(float);
    cudaFuncSetAttribute(dist_kernel, cudaFuncAttributeMaxDynamicSharedMemorySize, DIST_SMEM);
    cudaFuncSetAttribute(bf3_gemm<0,0,false>, cudaFuncAttributeMaxDynamicSharedMemorySize, GEMM_SMEM);
    cudaFuncSetAttribute(bf3_gemm<0,1,false>, cudaFuncAttributeMaxDynamicSharedMemorySize, GEMM_SMEM);
    cudaFuncSetAttribute(bf3_gemm<1,2,true>,  cudaFuncAttributeMaxDynamicSharedMemorySize, GEMM_SMEM);
    cudaFuncSetAttribute(bf3_gemm<0,1,true>,  cudaFuncAttributeMaxDynamicSharedMemorySize, GEMM_SMEM);

    // weight splits (pair-interleaved, once per launch)
    split_qkv_pi_kernel<<<(LL*(EE/2)*QKS/4 + 255)/256, 256>>>(Wq, Wk, Wv, Wqkvh, Wqkvl);
    split_pi_kernel<<<(LL*(EE/2)*EE/4 + 255)/256, 256>>>(Wo, Woh, Wol, EE, EE, LL*(EE/2)*EE/4);
    split_pi_kernel<<<(LL*(EE/2)*FF/4 + 255)/256, 256>>>(W1, W1h, W1l, EE, FF, LL*(EE/2)*FF/4);
    split_pi_kernel<<<(LL*(FF/2)*EE/4 + 255)/256, 256>>>(W2, W2h, W2l, FF, EE, LL*(FF/2)*EE/4);

    embed_kernel<<<MM, 128>>>(value, depth, pos, sos, tok_emb, depth_emb, pos_emb, x);

    // initial zero of scatter buffers (per replay; subsequent layers re-zeroed by norm_attout)
    cudaMemsetAsync(attout, 0, (size_t)MM*EE*sizeof(float));
    cudaMemsetAsync(cnt, 0, (size_t)MM*HH*sizeof(float));

    dim3 gE(EE/128, MM/128);     // 4 x 128
    dim3 gQ(QKS/128, MM/128);    // 12 x 128
    dim3 gF(FF/128, MM/128);     // 16 x 128
    dim3 gD(SS/128, BB*HH);      // 32 x 32

    for (int l = 0; l < LL; l++) {
        size_t oQ = (size_t)l*(EE/2)*QKS;
        size_t oE = (size_t)l*(EE/2)*EE;
        size_t oF1 = (size_t)l*(EE/2)*FF;
        size_t oF2 = (size_t)l*(FF/2)*EE;
        const float* ml = means + (size_t)l*HH*CC*DD;
        float* q = qkv;
        float* k = qkv + EE;
        float* v = qkv + 2*EE;

        ln_kernel<<<MM/8, 256>>>(x, ln1_s + l*EE, ln1_b + l*EE, hh, hl);
        bf3_gemm<0,0,false><<<gQ, 256, GEMM_SMEM>>>(hh, hl, Wqkvh+oQ, Wqkvl+oQ, nullptr, qkv, nullptr, nullptr, MM, QKS, EE);

        dist_kernel<<<gD, 256, DIST_SMEM>>>(q, ml, dists);
        topk_kernel<<<BB*HH*CC, 256>>>(dists, idxb);

        bucket_attn_kernel<<<BB*HH*CC, 256, ATTN_SMEM>>>(q, k, v, value, idxb, attout, cnt);
        norm_attout_kernel<<<(MM*EE)/256, 256>>>(attout, cnt, aoh, aol);

        bf3_gemm<0,1,false><<<gE, 256, GEMM_SMEM>>>(aoh, aol, Woh+oE, Wol+oE, nullptr, x, nullptr, nullptr, MM, EE, EE);

        ln_kernel<<<MM/8, 256>>>(x, ln2_s + l*EE, ln2_b + l*EE, hh, hl);
        bf3_gemm<1,2,true><<<gF, 256, GEMM_SMEM>>>(hh, hl, W1h+oF1, W1l+oF1, b1 + l*FF, nullptr, th, tl, MM, FF, EE);
        bf3_gemm<0,1,true><<<gE, 256, GEMM_SMEM>>>(th, tl, W2h+oF2, W2l+oF2, b2 + l*EE, x, nullptr, nullptr, MM, EE, FF);
    }

    head_kernel<<<MM/8, 256>>>(x, head_w, out);
}